// round 2
// baseline (speedup 1.0000x reference)
#include <cuda_runtime.h>
#include <cstdint>

// ---------------------------------------------------------------------------
// HebbianMap2d: y_out = relu(conv(x,w)); new_w = w + eta*(r^T Xu - tril(r^T r) W)/N
// with r = lfb(winner(relu(s))) * relu(s).
//
// Shapes: x[32,3,64,64], w[256,3,5,5] -> y_out[32,256,60,60], new_w[256,75]
// ---------------------------------------------------------------------------

#define B_    32
#define C_    3
#define H_    64
#define W_    64
#define HO_   60
#define WO_   60
#define HW_   3600          // 60*60
#define O_    256
#define D_    75            // 3*5*5
#define NTOT  115200        // 32*3600
#define YOUT  29491200      // 32*256*3600
#define ZB    120           // split-K chunks
#define KCHUNK 960          // NTOT / ZB (multiple of 32)

// ------------------------- scratch (device globals) ------------------------
__device__ float g_K[O_ * O_];                       // 256 KB  SOM lateral kernel
__device__ float g_xunf[(size_t)D_ * NTOT];          // 34.6 MB [d][n]
__device__ float g_rT[(size_t)O_ * NTOT];            // 118 MB  [o][n]
__device__ float g_ymax[NTOT];
__device__ float g_rrP[(size_t)ZB * O_ * O_];        // 31.5 MB split-K partials
__device__ float g_rxP[(size_t)ZB * O_ * D_];        // 9.2 MB
__device__ float g_rr[O_ * O_];
__device__ float g_rx[O_ * D_];

// ------------------------- K table ------------------------------------------
// lfb[i,j] for winner (wi,wj): a = wi-i+7, b = wj-j+7 must be in [0,16);
// value exp(-max(|wi-i|,|wj-j|)^2 / (2*7^2)).
__global__ void k_buildK() {
    int t = blockIdx.x * 256 + threadIdx.x;          // 65536 total
    int w = t >> 8, o = t & 255;
    int wi = w >> 4, wj = w & 15, i = o >> 4, j = o & 15;
    int a = wi - i + 7, b = wj - j + 7;
    float v = 0.f;
    if (a >= 0 && a < 16 && b >= 0 && b < 16) {
        int da = abs(a - 7), db = abs(b - 7);
        int m = da > db ? da : db;
        v = expf(-(float)(m * m) / 98.0f);
    }
    g_K[t] = v;
}

// ------------------------- im2col -------------------------------------------
__global__ void k_xunf(const float* __restrict__ x) {
    int t = blockIdx.x * 256 + threadIdx.x;          // D_*NTOT = 8,640,000 exactly
    int d = t / NTOT;
    int n = t - d * NTOT;
    int b = n / HW_;
    int hw = n - b * HW_;
    int i = hw / WO_;
    int j = hw - i * WO_;
    int c = d / 25;
    int rr = d - c * 25;
    int ki = rr / 5;
    int kj = rr - ki * 5;
    g_xunf[t] = x[((b * C_ + c) * H_ + i + ki) * W_ + j + kj];
}

// ------------------------- conv as GEMM: S = W[256,75] @ Xu[75,N] -----------
// block tile 64(o) x 128(n), BK = 25 (3 chunks)
__global__ void k_conv(const float* __restrict__ Wt, float* __restrict__ out) {
    __shared__ float Ws[25][65];
    __shared__ float Xs[25][132];
    int tx = threadIdx.x & 15, ty = threadIdx.x >> 4;
    int oT = blockIdx.y * 64, nT = blockIdx.x * 128;

    float acc[4][8];
#pragma unroll
    for (int i = 0; i < 4; i++)
#pragma unroll
        for (int j = 0; j < 8; j++) acc[i][j] = 0.f;

    for (int k0 = 0; k0 < 75; k0 += 25) {
        for (int idx = threadIdx.x; idx < 25 * 64; idx += 256) {
            int k = idx >> 6, o = idx & 63;
            Ws[k][o] = Wt[(oT + o) * D_ + k0 + k];
        }
        for (int idx = threadIdx.x; idx < 25 * 128; idx += 256) {
            int k = idx >> 7, n = idx & 127;
            Xs[k][n] = g_xunf[(size_t)(k0 + k) * NTOT + nT + n];
        }
        __syncthreads();
#pragma unroll
        for (int k = 0; k < 25; k++) {
            float a[4], bb[8];
#pragma unroll
            for (int i = 0; i < 4; i++) a[i] = Ws[k][ty + 16 * i];
#pragma unroll
            for (int j = 0; j < 8; j++) bb[j] = Xs[k][tx + 16 * j];
#pragma unroll
            for (int i = 0; i < 4; i++)
#pragma unroll
                for (int j = 0; j < 8; j++) acc[i][j] += a[i] * bb[j];
        }
        __syncthreads();
    }
#pragma unroll
    for (int i = 0; i < 4; i++) {
        int o = oT + ty + 16 * i;
#pragma unroll
        for (int j = 0; j < 8; j++) {
            int n = nT + tx + 16 * j;
            int b = n / HW_;
            int hw = n - b * HW_;
            out[((size_t)b * O_ + o) * HW_ + hw] = fmaxf(acc[i][j], 0.f);
        }
    }
}

// ------------------------- row max over o ------------------------------------
__global__ void k_ymax(const float* __restrict__ y) {
    int n = blockIdx.x * 256 + threadIdx.x;          // 115200 exactly
    int b = n / HW_;
    int hw = n - b * HW_;
    const float* p = y + (size_t)b * O_ * HW_ + hw;
    float m = 0.f;                                   // y >= 0 (relu)
#pragma unroll 8
    for (int o = 0; o < O_; o++) m = fmaxf(m, p[o * HW_]);
    g_ymax[n] = m;
}

// ------------------------- winner -> lfb -> r, write r^T --------------------
// block: 256 threads handle 32 n-rows x 256 o. smem transpose for coalesced
// rT writes. If ymax == 0, whole row r = 0 (y = 0 everywhere).
__global__ void k_lfbr(const float* __restrict__ y) {
    __shared__ float ys[32][257];
    __shared__ float ymx[32];
    __shared__ int cnt[32];
    __shared__ int widx[32][8];
    int t = threadIdx.x;
    int lane = t & 31, wrp = t >> 5;
    int n0 = blockIdx.x * 32;

    {   // load: warp wrp loads o = wrp, wrp+8, ..., lanes cover n
        int n = n0 + lane;
        int b = n / HW_;
        int hw = n - b * HW_;
        const float* p = y + (size_t)b * O_ * HW_ + hw;
        for (int o = wrp; o < O_; o += 8) ys[lane][o] = p[o * HW_];
    }
    if (t < 32) { ymx[t] = g_ymax[n0 + t]; cnt[t] = 0; }
    __syncthreads();

    // winner detection: thread t owns channel o = t
#pragma unroll 4
    for (int nn = 0; nn < 32; nn++) {
        float ym = ymx[nn];
        if (ym > 0.f && ys[nn][t] == ym) {
            int pos = atomicAdd(&cnt[nn], 1);
            if (pos < 8) widx[nn][pos] = t;
        }
    }
    __syncthreads();

    // r = clip(lfb,-1,1) * y, in place
#pragma unroll 4
    for (int nn = 0; nn < 32; nn++) {
        int c = cnt[nn]; if (c > 8) c = 8;
        float lfb = 0.f;
        for (int k2 = 0; k2 < c; k2++) lfb += g_K[widx[nn][k2] * O_ + t];
        lfb = fminf(fmaxf(lfb, -1.f), 1.f);
        ys[nn][t] = lfb * ys[nn][t];
    }
    __syncthreads();

    // coalesced rT writes: warp wrp owns o in [32*wrp, 32*wrp+32)
    for (int o = wrp * 32; o < wrp * 32 + 32; o++)
        g_rT[(size_t)o * NTOT + n0 + lane] = ys[lane][o];
}

// ------------------------- NT GEMM, 128x128 tile, BK=32, split-K ------------
// C_partial[z] = A[128-tile, :] * B[128-tile, :]^T over K-chunk z.
// RR: A=B=g_rT (256x256 out). !RR: A=g_rT, B=g_xunf (256x75 out).
template <bool RR>
__global__ void __launch_bounds__(256) k_gemm_nt() {
    __shared__ float As[32][129];
    __shared__ float Bs[32][129];
    const float* A = g_rT;
    const float* Bm = RR ? g_rT : g_xunf;
    const int N2  = RR ? O_ : D_;
    const int ldc = RR ? O_ : D_;
    float* Cp = RR ? (g_rrP + (size_t)blockIdx.z * (O_ * O_))
                   : (g_rxP + (size_t)blockIdx.z * (O_ * D_));

    int tx = threadIdx.x & 15, ty = threadIdx.x >> 4;
    int mT = blockIdx.y * 128, nT = blockIdx.x * 128;
    size_t k0 = (size_t)blockIdx.z * KCHUNK;

    float acc[8][8];
#pragma unroll
    for (int i = 0; i < 8; i++)
#pragma unroll
        for (int j = 0; j < 8; j++) acc[i][j] = 0.f;

    for (int kk = 0; kk < KCHUNK; kk += 32) {
        size_t kb = k0 + kk;
        for (int idx = threadIdx.x; idx < 128 * 32; idx += 256) {
            int m = idx >> 5, k = idx & 31;
            As[k][m] = A[(size_t)(mT + m) * NTOT + kb + k];
        }
        for (int idx = threadIdx.x; idx < 128 * 32; idx += 256) {
            int n = idx >> 5, k = idx & 31;
            Bs[k][n] = (nT + n < N2) ? Bm[(size_t)(nT + n) * NTOT + kb + k] : 0.f;
        }
        __syncthreads();
#pragma unroll
        for (int k = 0; k < 32; k++) {
            float a[8], b[8];
#pragma unroll
            for (int i = 0; i < 8; i++) a[i] = As[k][ty + 16 * i];
#pragma unroll
            for (int j = 0; j < 8; j++) b[j] = Bs[k][tx + 16 * j];
#pragma unroll
            for (int i = 0; i < 8; i++)
#pragma unroll
                for (int j = 0; j < 8; j++) acc[i][j] += a[i] * b[j];
        }
        __syncthreads();
    }
#pragma unroll
    for (int i = 0; i < 8; i++) {
        int m = mT + ty + 16 * i;
#pragma unroll
        for (int j = 0; j < 8; j++) {
            int n = nT + tx + 16 * j;
            if (n < N2) Cp[(size_t)m * ldc + n] = acc[i][j];
        }
    }
}

// ------------------------- deterministic split-K reduce ---------------------
__global__ void k_reduce() {
    int t = blockIdx.x * 256 + threadIdx.x;          // 65536 + 19200 = 84736
    if (t < O_ * O_) {
        float s = 0.f;
        for (int z = 0; z < ZB; z++) s += g_rrP[(size_t)z * (O_ * O_) + t];
        g_rr[t] = s;
    } else if (t < O_ * O_ + O_ * D_) {
        int e = t - O_ * O_;
        float s = 0.f;
        for (int z = 0; z < ZB; z++) s += g_rxP[(size_t)z * (O_ * D_) + e];
        g_rx[e] = s;
    }
}

// ------------------------- weight update ------------------------------------
// new_w[o,d] = w[o,d] + 0.01 * (rx[o,d] - sum_{o2<=o} rr[o,o2]*w[o2,d]) / N
__global__ void k_update(const float* __restrict__ Wt, float* __restrict__ out) {
    int t = blockIdx.x * 256 + threadIdx.x;
    if (t >= O_ * D_) return;
    int o = t / D_;
    int d = t - o * D_;
    float s = 0.f;
    for (int o2 = 0; o2 <= o; o2++)
        s += g_rr[o * O_ + o2] * Wt[o2 * D_ + d];
    out[YOUT + t] = Wt[t] + 0.01f * ((g_rx[t] - s) * (1.0f / 115200.0f));
}

// ---------------------------------------------------------------------------
extern "C" void kernel_launch(void* const* d_in, const int* in_sizes, int n_in,
                              void* d_out, int out_size) {
    const float* x  = (const float*)d_in[0];
    const float* wt = (const float*)d_in[1];
    float* out = (float*)d_out;

    k_buildK<<<256, 256>>>();
    k_xunf<<<33750, 256>>>(x);
    k_conv<<<dim3(900, 4), 256>>>(wt, out);
    k_ymax<<<450, 256>>>(out);
    k_lfbr<<<3600, 256>>>(out);
    k_gemm_nt<true ><<<dim3(2, 2, ZB), 256>>>();
    k_gemm_nt<false><<<dim3(1, 2, ZB), 256>>>();
    k_reduce<<<332, 256>>>();
    k_update<<<75, 256>>>(wt, out);
}

// round 3
// speedup vs baseline: 2.7888x; 2.7888x over previous
#include <cuda_runtime.h>
#include <cuda_bf16.h>
#include <cstdint>

// ---------------------------------------------------------------------------
// HebbianMap2d: y_out = relu(conv(x,w)); new_w = w + eta*(r^T Xu - tril(r^T r) W)/N
// with r = lfb(winner(relu(s))) * relu(s).
// Shapes: x[32,3,64,64], w[256,3,5,5] -> y_out[32,256,60,60], new_w[256,75]
// ---------------------------------------------------------------------------

#define B_    32
#define C_    3
#define H_    64
#define W_    64
#define HO_   60
#define WO_   60
#define HW_   3600          // 60*60
#define O_    256
#define D_    75            // 3*5*5
#define NTOT  115200        // 32*3600
#define YOUT  29491200      // 32*256*3600
#define ZB    150           // split-K chunks
#define KCHUNK 768          // NTOT / ZB (multiple of 64)

// ------------------------- scratch (device globals) ------------------------
__device__ __align__(16) float g_K[O_ * O_];                 // SOM lateral kernel
__device__ __align__(16) float g_xunf[(size_t)D_ * NTOT];    // 34.6 MB fp32 [d][n]
__device__ __align__(16) __nv_bfloat16 g_xunfh[(size_t)D_ * NTOT]; // 17.3 MB bf16
__device__ __align__(16) __nv_bfloat16 g_rTh[(size_t)O_ * NTOT];   // 59 MB bf16 [o][n]
__device__ __align__(16) float g_rrP[(size_t)ZB * O_ * O_];  // split-K partials
__device__ __align__(16) float g_rxP[(size_t)ZB * O_ * D_];
__device__ __align__(16) float g_rr[O_ * O_];
__device__ __align__(16) float g_rx[O_ * D_];

// ------------------------- K table ------------------------------------------
__global__ void k_buildK() {
    int t = blockIdx.x * 256 + threadIdx.x;          // 65536 total
    int w = t >> 8, o = t & 255;
    int wi = w >> 4, wj = w & 15, i = o >> 4, j = o & 15;
    int a = wi - i + 7, b = wj - j + 7;
    float v = 0.f;
    if (a >= 0 && a < 16 && b >= 0 && b < 16) {
        int da = abs(a - 7), db = abs(b - 7);
        int m = da > db ? da : db;
        v = expf(-(float)(m * m) / 98.0f);
    }
    g_K[t] = v;
}

// ------------------------- im2col (fp32 + bf16 copies) ----------------------
__global__ void k_xunf(const float* __restrict__ x) {
    int t = blockIdx.x * 256 + threadIdx.x;          // D_*NTOT = 8,640,000 exactly
    int d = t / NTOT;
    int n = t - d * NTOT;
    int b = n / HW_;
    int hw = n - b * HW_;
    int i = hw / WO_;
    int j = hw - i * WO_;
    int c = d / 25;
    int rr = d - c * 25;
    int ki = rr / 5;
    int kj = rr - ki * 5;
    float v = x[((b * C_ + c) * H_ + i + ki) * W_ + j + kj];
    g_xunf[t] = v;
    g_xunfh[t] = __float2bfloat16(v);
}

// ------------------------- conv as GEMM: S = W[256,75] @ Xu[75,N] -----------
__global__ void k_conv(const float* __restrict__ Wt, float* __restrict__ out) {
    __shared__ float Ws[25][65];
    __shared__ float Xs[25][132];
    int tx = threadIdx.x & 15, ty = threadIdx.x >> 4;
    int oT = blockIdx.y * 64, nT = blockIdx.x * 128;

    float acc[4][8];
#pragma unroll
    for (int i = 0; i < 4; i++)
#pragma unroll
        for (int j = 0; j < 8; j++) acc[i][j] = 0.f;

    for (int k0 = 0; k0 < 75; k0 += 25) {
        for (int idx = threadIdx.x; idx < 25 * 64; idx += 256) {
            int k = idx >> 6, o = idx & 63;
            Ws[k][o] = Wt[(oT + o) * D_ + k0 + k];
        }
        for (int idx = threadIdx.x; idx < 25 * 128; idx += 256) {
            int k = idx >> 7, n = idx & 127;
            Xs[k][n] = g_xunf[(size_t)(k0 + k) * NTOT + nT + n];
        }
        __syncthreads();
#pragma unroll
        for (int k = 0; k < 25; k++) {
            float a[4], bb[8];
#pragma unroll
            for (int i = 0; i < 4; i++) a[i] = Ws[k][ty + 16 * i];
#pragma unroll
            for (int j = 0; j < 8; j++) bb[j] = Xs[k][tx + 16 * j];
#pragma unroll
            for (int i = 0; i < 4; i++)
#pragma unroll
                for (int j = 0; j < 8; j++) acc[i][j] += a[i] * bb[j];
        }
        __syncthreads();
    }
#pragma unroll
    for (int i = 0; i < 4; i++) {
        int o = oT + ty + 16 * i;
#pragma unroll
        for (int j = 0; j < 8; j++) {
            int n = nT + tx + 16 * j;
            int b = n / HW_;
            int hw = n - b * HW_;
            out[((size_t)b * O_ + o) * HW_ + hw] = fmaxf(acc[i][j], 0.f);
        }
    }
}

// ------------------------- winner -> lfb -> r, write r^T (bf16) -------------
// ymax computed in-block (fused). If ymax == 0, row r = 0.
__global__ void k_lfbr(const float* __restrict__ y) {
    __shared__ float ys[32][257];
    __shared__ float ymx[32];
    __shared__ int cnt[32];
    __shared__ int widx[32][8];
    int t = threadIdx.x;
    int lane = t & 31, wrp = t >> 5;
    int n0 = blockIdx.x * 32;

    {   // load: warp wrp loads o = wrp, wrp+8, ..., lanes cover n
        int n = n0 + lane;
        int b = n / HW_;
        int hw = n - b * HW_;
        const float* p = y + (size_t)b * O_ * HW_ + hw;
        for (int o = wrp; o < O_; o += 8) ys[lane][o] = p[o * HW_];
    }
    if (t < 32) cnt[t] = 0;
    __syncthreads();

    // fused ymax: warp wrp reduces rows wrp*4 .. wrp*4+3
#pragma unroll
    for (int q = 0; q < 4; q++) {
        int nn = wrp * 4 + q;
        float m = 0.f;                               // y >= 0 (relu)
#pragma unroll
        for (int o = lane; o < O_; o += 32) m = fmaxf(m, ys[nn][o]);
#pragma unroll
        for (int s = 16; s; s >>= 1) m = fmaxf(m, __shfl_xor_sync(0xffffffffu, m, s));
        if (lane == 0) ymx[nn] = m;
    }
    __syncthreads();

    // winner detection: thread t owns channel o = t
#pragma unroll 4
    for (int nn = 0; nn < 32; nn++) {
        float ym = ymx[nn];
        if (ym > 0.f && ys[nn][t] == ym) {
            int pos = atomicAdd(&cnt[nn], 1);
            if (pos < 8) widx[nn][pos] = t;
        }
    }
    __syncthreads();

    // r = clip(lfb,-1,1) * y, in place
#pragma unroll 4
    for (int nn = 0; nn < 32; nn++) {
        int c = cnt[nn]; if (c > 8) c = 8;
        float lfb = 0.f;
        for (int k2 = 0; k2 < c; k2++) lfb += g_K[widx[nn][k2] * O_ + t];
        lfb = fminf(fmaxf(lfb, -1.f), 1.f);
        ys[nn][t] = lfb * ys[nn][t];
    }
    __syncthreads();

    // coalesced rT writes (bf16): warp wrp owns o in [32*wrp, 32*wrp+32)
    for (int o = wrp * 32; o < wrp * 32 + 32; o++)
        g_rTh[(size_t)o * NTOT + n0 + lane] = __float2bfloat16(ys[lane][o]);
}

// ------------------------- bf16 tensor-core NT GEMM, split-K ----------------
// C_partial[z] += A[128,KCHUNK] * B[128,KCHUNK]^T.  A = rT (bf16).
// RR: B = rT  (256x256 out, strictly-upper tile skipped).
// !RR: B = xunf bf16 padded with zero rows (256x75 out).
// smem: 128 rows x 128B (64 bf16), SW128 XOR swizzle -> conflict-free ldmatrix.
__device__ __forceinline__ uint32_t sw_off(int row, int kch) {
    return (uint32_t)(row * 128 + ((kch ^ (row & 7)) << 4));
}

template <bool RR>
__global__ void __launch_bounds__(256) k_mma() {
    __shared__ __align__(16) uint8_t As[128 * 128];
    __shared__ __align__(16) uint8_t Bs[128 * 128];

    int mT = blockIdx.y * 128, nT = blockIdx.x * 128;
    if (RR && mT < nT) return;                       // tril: skip upper tile

    const __nv_bfloat16* A = g_rTh;
    const __nv_bfloat16* Bm = RR ? g_rTh : g_xunfh;
    float* Cp = RR ? (g_rrP + (size_t)blockIdx.z * (O_ * O_))
                   : (g_rxP + (size_t)blockIdx.z * (O_ * D_));
    const int ldc = RR ? O_ : D_;

    int tid = threadIdx.x;
    int lane = tid & 31, wid = tid >> 5;
    int wm = wid >> 2, wn = wid & 3;                 // warp tile 64(m) x 32(n)
    size_t k0 = (size_t)blockIdx.z * KCHUNK;

    uint32_t sA = (uint32_t)__cvta_generic_to_shared(As);
    uint32_t sB = (uint32_t)__cvta_generic_to_shared(Bs);

    float c[4][4][4];
#pragma unroll
    for (int i = 0; i < 4; i++)
#pragma unroll
        for (int j = 0; j < 4; j++)
#pragma unroll
            for (int q = 0; q < 4; q++) c[i][j][q] = 0.f;

    // precompute ldmatrix lane addresses (row/kch pattern fixed per lane)
    int lt = lane >> 3, lr = lane & 7;               // tile idx, row-in-tile
    int arow = ((lt & 1) << 3) + lr;                 // row offset within 16
    int akch = lt >> 1;                              // k-chunk offset (0/1)

    for (int kk = 0; kk < KCHUNK; kk += 64) {
        // ---- global -> smem (swizzled), 4 uint4 per thread per tile ----
#pragma unroll
        for (int i = 0; i < 4; i++) {
            int idx = tid + i * 256;
            int row = idx >> 3, ch = idx & 7;
            uint4 v = *(const uint4*)(A + (size_t)(mT + row) * NTOT + k0 + kk + ch * 8);
            *(uint4*)(As + row * 128 + ((ch ^ (row & 7)) << 4)) = v;
        }
#pragma unroll
        for (int i = 0; i < 4; i++) {
            int idx = tid + i * 256;
            int row = idx >> 3, ch = idx & 7;
            int grow = nT + row;
            uint4 v = make_uint4(0u, 0u, 0u, 0u);
            if (RR || grow < D_)
                v = *(const uint4*)(Bm + (size_t)grow * NTOT + k0 + kk + ch * 8);
            *(uint4*)(Bs + row * 128 + ((ch ^ (row & 7)) << 4)) = v;
        }
        __syncthreads();

#pragma unroll
        for (int ks = 0; ks < 4; ks++) {
            int kb = ks * 16;                        // bf16 index within 64
            int kchb = kb >> 3;
            // A fragments: 4 m-atoms (16 rows each)
            uint32_t af[4][4];
#pragma unroll
            for (int mi = 0; mi < 4; mi++) {
                int row = wm * 64 + mi * 16 + arow;
                uint32_t addr = sA + sw_off(row, kchb + akch);
                asm volatile("ldmatrix.sync.aligned.m8n8.x4.shared.b16 {%0,%1,%2,%3}, [%4];"
                             : "=r"(af[mi][0]), "=r"(af[mi][1]), "=r"(af[mi][2]), "=r"(af[mi][3])
                             : "r"(addr));
            }
            // B fragments: 2 groups cover 4 n-atoms (8 cols each)
            uint32_t bf[2][4];
#pragma unroll
            for (int bj = 0; bj < 2; bj++) {
                int row = wn * 32 + bj * 16 + arow;
                uint32_t addr = sB + sw_off(row, kchb + akch);
                asm volatile("ldmatrix.sync.aligned.m8n8.x4.shared.b16 {%0,%1,%2,%3}, [%4];"
                             : "=r"(bf[bj][0]), "=r"(bf[bj][1]), "=r"(bf[bj][2]), "=r"(bf[bj][3])
                             : "r"(addr));
            }
#pragma unroll
            for (int mi = 0; mi < 4; mi++)
#pragma unroll
                for (int nj = 0; nj < 4; nj++) {
                    int g = nj >> 1, od = nj & 1;
                    asm volatile(
                        "mma.sync.aligned.m16n8k16.row.col.f32.bf16.bf16.f32 "
                        "{%0,%1,%2,%3}, {%4,%5,%6,%7}, {%8,%9}, {%0,%1,%2,%3};"
                        : "+f"(c[mi][nj][0]), "+f"(c[mi][nj][1]),
                          "+f"(c[mi][nj][2]), "+f"(c[mi][nj][3])
                        : "r"(af[mi][0]), "r"(af[mi][1]), "r"(af[mi][2]), "r"(af[mi][3]),
                          "r"(bf[g][od]), "r"(bf[g][od + 2]));
                }
        }
        __syncthreads();
    }

    // ---- epilogue: write fp32 partials ----
#pragma unroll
    for (int mi = 0; mi < 4; mi++) {
        int row0 = mT + wm * 64 + mi * 16 + (lane >> 2);
#pragma unroll
        for (int nj = 0; nj < 4; nj++) {
            int col0 = nT + wn * 32 + nj * 8 + 2 * (lane & 3);
#pragma unroll
            for (int h = 0; h < 2; h++) {            // h: +0 / +8 row
                int r = row0 + h * 8;
                float v0 = c[mi][nj][h * 2 + 0], v1 = c[mi][nj][h * 2 + 1];
                if (RR) {
                    Cp[(size_t)r * ldc + col0] = v0;
                    Cp[(size_t)r * ldc + col0 + 1] = v1;
                } else {
                    if (col0 < D_)     Cp[(size_t)r * ldc + col0] = v0;
                    if (col0 + 1 < D_) Cp[(size_t)r * ldc + col0 + 1] = v1;
                }
            }
        }
    }
}

// ------------------------- deterministic split-K reduce ---------------------
__global__ void k_reduce() {
    int t = blockIdx.x * 256 + threadIdx.x;          // 65536 + 19200 = 84736
    if (t < O_ * O_) {
        float s = 0.f;
        for (int z = 0; z < ZB; z++) s += g_rrP[(size_t)z * (O_ * O_) + t];
        g_rr[t] = s;
    } else if (t < O_ * O_ + O_ * D_) {
        int e = t - O_ * O_;
        float s = 0.f;
        for (int z = 0; z < ZB; z++) s += g_rxP[(size_t)z * (O_ * D_) + e];
        g_rx[e] = s;
    }
}

// ------------------------- weight update ------------------------------------
__global__ void k_update(const float* __restrict__ Wt, float* __restrict__ out) {
    int t = blockIdx.x * 256 + threadIdx.x;
    if (t >= O_ * D_) return;
    int o = t / D_;
    int d = t - o * D_;
    float s = 0.f;
    for (int o2 = 0; o2 <= o; o2++)
        s += g_rr[o * O_ + o2] * Wt[o2 * D_ + d];
    out[YOUT + t] = Wt[t] + 0.01f * ((g_rx[t] - s) * (1.0f / 115200.0f));
}

// ---------------------------------------------------------------------------
extern "C" void kernel_launch(void* const* d_in, const int* in_sizes, int n_in,
                              void* d_out, int out_size) {
    const float* x  = (const float*)d_in[0];
    const float* wt = (const float*)d_in[1];
    float* out = (float*)d_out;

    k_buildK<<<256, 256>>>();
    k_xunf<<<33750, 256>>>(x);
    k_conv<<<dim3(900, 4), 256>>>(wt, out);
    k_lfbr<<<3600, 256>>>(out);
    k_mma<true ><<<dim3(2, 2, ZB), 256>>>();
    k_mma<false><<<dim3(1, 2, ZB), 256>>>();
    k_reduce<<<332, 256>>>();
    k_update<<<75, 256>>>(wt, out);
}

// round 5
// speedup vs baseline: 2.9091x; 1.0431x over previous
#include <cuda_runtime.h>
#include <cuda_bf16.h>
#include <cstdint>

// ---------------------------------------------------------------------------
// HebbianMap2d: y_out = relu(conv(x,w)); new_w = w + eta*(r^T Xu - tril(r^T r) W)/N
// with r = lfb(winner(relu(s))) * relu(s).
// Shapes: x[32,3,64,64], w[256,3,5,5] -> y_out[32,256,60,60], new_w[256,75]
// ---------------------------------------------------------------------------

#define B_    32
#define C_    3
#define H_    64
#define W_    64
#define HO_   60
#define WO_   60
#define HW_   3600          // 60*60
#define O_    256
#define D_    75            // 3*5*5
#define DP    80            // D padded to multiple of 16
#define NTOT  115200        // 32*3600
#define YOUT  29491200      // 32*256*3600
#define ZB    150           // split-K chunks
#define KCHUNK 768          // NTOT / ZB (multiple of 64)

// ------------------------- scratch (device globals) ------------------------
__device__ __align__(16) float g_K[O_ * O_];                 // SOM lateral kernel
__device__ __align__(16) __nv_bfloat16 g_Whi[O_ * DP];       // W split-bf16 hi
__device__ __align__(16) __nv_bfloat16 g_Wlo[O_ * DP];       // W split-bf16 lo
__device__ __align__(16) __nv_bfloat16 g_xch[(size_t)NTOT * DP]; // im2col [n][80] hi
__device__ __align__(16) __nv_bfloat16 g_xcl[(size_t)NTOT * DP]; // im2col [n][80] lo
__device__ __align__(16) __nv_bfloat16 g_xunfh[(size_t)D_ * NTOT]; // [d][n] bf16 (rx GEMM)
__device__ __align__(16) __nv_bfloat16 g_rTh[(size_t)O_ * NTOT];   // r^T bf16 [o][n]
__device__ __align__(16) float g_rrP[(size_t)ZB * O_ * O_];  // split-K partials
__device__ __align__(16) float g_rxP[(size_t)ZB * O_ * D_];
__device__ __align__(16) float g_rr[O_ * O_];
__device__ __align__(16) float g_rx[O_ * D_];

// ------------------------- K table ------------------------------------------
__global__ void k_buildK() {
    int t = blockIdx.x * 256 + threadIdx.x;          // 65536 total
    int w = t >> 8, o = t & 255;
    int wi = w >> 4, wj = w & 15, i = o >> 4, j = o & 15;
    int a = wi - i + 7, b = wj - j + 7;
    float v = 0.f;
    if (a >= 0 && a < 16 && b >= 0 && b < 16) {
        int da = abs(a - 7), db = abs(b - 7);
        int m = da > db ? da : db;
        v = expf(-(float)(m * m) / 98.0f);
    }
    g_K[t] = v;
}

// ------------------------- W split-bf16 prep --------------------------------
__global__ void k_wprep(const float* __restrict__ Wt) {
    int t = blockIdx.x * 256 + threadIdx.x;          // 20480 exactly
    if (t >= O_ * DP) return;
    int o = t / DP, d = t - o * DP;
    float v = (d < D_) ? Wt[o * D_ + d] : 0.f;
    __nv_bfloat16 hi = __float2bfloat16(v);
    g_Whi[t] = hi;
    g_Wlo[t] = __float2bfloat16(v - __bfloat162float(hi));
}

// ------------------------- im2col [d][n] bf16 (for rx GEMM) -----------------
__global__ void k_xunf_dn(const float* __restrict__ x) {
    int t = blockIdx.x * 256 + threadIdx.x;          // D_*NTOT = 8,640,000 exactly
    int d = t / NTOT;
    int n = t - d * NTOT;
    int b = n / HW_;
    int hw = n - b * HW_;
    int i = hw / WO_;
    int j = hw - i * WO_;
    int c = d / 25;
    int rr = d - c * 25;
    int ki = rr / 5;
    int kj = rr - ki * 5;
    g_xunfh[t] = __float2bfloat16(x[((b * C_ + c) * H_ + i + ki) * W_ + j + kj]);
}

// ------------------------- im2col [n][80] hi/lo (for conv MMA) --------------
__global__ void k_xunf_nk(const float* __restrict__ x) {
    int t = blockIdx.x * 256 + threadIdx.x;          // NTOT*DP = 9,216,000 exactly
    int n = t / DP;
    int d = t - n * DP;
    float v = 0.f;
    if (d < D_) {
        int b = n / HW_;
        int hw = n - b * HW_;
        int i = hw / WO_;
        int j = hw - i * WO_;
        int c = d / 25;
        int rr = d - c * 25;
        int ki = rr / 5;
        int kj = rr - ki * 5;
        v = x[((b * C_ + c) * H_ + i + ki) * W_ + j + kj];
    }
    __nv_bfloat16 hi = __float2bfloat16(v);
    g_xch[t] = hi;
    g_xcl[t] = __float2bfloat16(v - __bfloat162float(hi));
}

// ------------------------- fused conv + winner + lfb + r --------------------
// Block: 256 threads = 8 warps (wm 0..3 over 64 o each, wn 0..1 over 32 n each)
// Tile: 256(o) x 64(n). Split-bf16 3-pass MMA; epilogue computes per-n max over
// all 256 channels, winners, lfb, r; writes y_out (fp32) and r^T (bf16).
#define LDSM(r0,r1,r2,r3,addr) \
    asm volatile("ldmatrix.sync.aligned.m8n8.x4.shared.b16 {%0,%1,%2,%3}, [%4];" \
                 : "=r"(r0), "=r"(r1), "=r"(r2), "=r"(r3) : "r"(addr))
#define MMA16816(c0,c1,c2,c3,a0,a1,a2,a3,b0,b1) \
    asm volatile("mma.sync.aligned.m16n8k16.row.col.f32.bf16.bf16.f32 " \
                 "{%0,%1,%2,%3}, {%4,%5,%6,%7}, {%8,%9}, {%0,%1,%2,%3};" \
                 : "+f"(c0), "+f"(c1), "+f"(c2), "+f"(c3) \
                 : "r"(a0), "r"(a1), "r"(a2), "r"(a3), "r"(b0), "r"(b1))

__global__ void __launch_bounds__(256) k_convfused(float* __restrict__ out) {
    // rows of 24 bf16 (48B): ldmatrix bank-conflict-free (12r mod 32 distinct)
    __shared__ __align__(16) __nv_bfloat16 sW[512 * 24];   // rows 0-255 hi, 256-511 lo
    __shared__ __align__(16) __nv_bfloat16 sX[128 * 24];   // rows 0-63 hi, 64-127 lo
    __shared__ float pmax[4][64];
    __shared__ float ymx[64];
    __shared__ int cnt[64];
    __shared__ int widx[64][8];

    int tid = threadIdx.x, lane = tid & 31, wid = tid >> 5;
    int wm = wid >> 1, wn = wid & 1;
    int nT = blockIdx.x * 64;

    uint32_t sWb = (uint32_t)__cvta_generic_to_shared(sW);
    uint32_t sXb = (uint32_t)__cvta_generic_to_shared(sX);

    int lt = lane >> 3, lr = lane & 7;
    int arow = ((lt & 1) << 3) + lr;
    int akch = lt >> 1;

    float c[4][4][4];
#pragma unroll
    for (int i = 0; i < 4; i++)
#pragma unroll
        for (int j = 0; j < 4; j++)
#pragma unroll
            for (int q = 0; q < 4; q++) c[i][j][q] = 0.f;

    for (int s = 0; s < 5; s++) {
        // load W chunk: 1024 uint4, 4 per thread
#pragma unroll
        for (int i = 0; i < 4; i++) {
            int idx = tid + i * 256;
            int piece = idx & 1, hl = (idx >> 1) & 1, row = idx >> 2;
            const __nv_bfloat16* src = hl ? g_Wlo : g_Whi;
            uint4 v = *(const uint4*)(src + row * DP + s * 16 + piece * 8);
            *(uint4*)(sW + (hl * 256 + row) * 24 + piece * 8) = v;
        }
        // load X chunk: 256 uint4, 1 per thread
        {
            int piece = tid & 1, hl = (tid >> 1) & 1, row = tid >> 2;
            const __nv_bfloat16* src = hl ? g_xcl : g_xch;
            uint4 v = *(const uint4*)(src + (size_t)(nT + row) * DP + s * 16 + piece * 8);
            *(uint4*)(sX + (hl * 64 + row) * 24 + piece * 8) = v;
        }
        __syncthreads();

        uint32_t ah[4][4], al[4][4], bh[2][4], bl[2][4];
#pragma unroll
        for (int mi = 0; mi < 4; mi++) {
            int row = wm * 64 + mi * 16 + arow;
            LDSM(ah[mi][0], ah[mi][1], ah[mi][2], ah[mi][3], sWb + row * 48 + akch * 16);
            LDSM(al[mi][0], al[mi][1], al[mi][2], al[mi][3], sWb + (256 + row) * 48 + akch * 16);
        }
#pragma unroll
        for (int bj = 0; bj < 2; bj++) {
            int row = wn * 32 + bj * 16 + arow;
            LDSM(bh[bj][0], bh[bj][1], bh[bj][2], bh[bj][3], sXb + row * 48 + akch * 16);
            LDSM(bl[bj][0], bl[bj][1], bl[bj][2], bl[bj][3], sXb + (64 + row) * 48 + akch * 16);
        }
#pragma unroll
        for (int mi = 0; mi < 4; mi++)
#pragma unroll
            for (int nj = 0; nj < 4; nj++) {
                int g = nj >> 1, od = nj & 1;
                MMA16816(c[mi][nj][0], c[mi][nj][1], c[mi][nj][2], c[mi][nj][3],
                         ah[mi][0], ah[mi][1], ah[mi][2], ah[mi][3],
                         bh[g][od], bh[g][od + 2]);
                MMA16816(c[mi][nj][0], c[mi][nj][1], c[mi][nj][2], c[mi][nj][3],
                         ah[mi][0], ah[mi][1], ah[mi][2], ah[mi][3],
                         bl[g][od], bl[g][od + 2]);
                MMA16816(c[mi][nj][0], c[mi][nj][1], c[mi][nj][2], c[mi][nj][3],
                         al[mi][0], al[mi][1], al[mi][2], al[mi][3],
                         bh[g][od], bh[g][od + 2]);
            }
        __syncthreads();
    }

    // ---------------- epilogue ----------------
    int lq = lane >> 2, ln = lane & 3;

    // n bases for this thread's 8 columns
    int nbase[4][2];
#pragma unroll
    for (int nj = 0; nj < 4; nj++)
#pragma unroll
        for (int q = 0; q < 2; q++) {
            int n = nT + wn * 32 + nj * 8 + 2 * ln + q;
            int b = n / HW_;
            int hw = n - b * HW_;
            nbase[nj][q] = b * (O_ * HW_) + hw;
        }

    // relu + y_out store + per-thread column max
    float tmax[4][2];
#pragma unroll
    for (int nj = 0; nj < 4; nj++)
#pragma unroll
        for (int q = 0; q < 2; q++) tmax[nj][q] = 0.f;

#pragma unroll
    for (int mi = 0; mi < 4; mi++)
#pragma unroll
        for (int h = 0; h < 2; h++) {
            int o = wm * 64 + mi * 16 + lq + 8 * h;
            size_t ob = (size_t)o * HW_;
#pragma unroll
            for (int nj = 0; nj < 4; nj++)
#pragma unroll
                for (int q = 0; q < 2; q++) {
                    float y = fmaxf(c[mi][nj][h * 2 + q], 0.f);
                    c[mi][nj][h * 2 + q] = y;
                    out[ob + nbase[nj][q]] = y;
                    tmax[nj][q] = fmaxf(tmax[nj][q], y);
                }
        }

    // warp-level max across lane>>2, then cross-warp via smem
#pragma unroll
    for (int nj = 0; nj < 4; nj++)
#pragma unroll
        for (int q = 0; q < 2; q++) {
            float m = tmax[nj][q];
            m = fmaxf(m, __shfl_xor_sync(0xffffffffu, m, 4));
            m = fmaxf(m, __shfl_xor_sync(0xffffffffu, m, 8));
            m = fmaxf(m, __shfl_xor_sync(0xffffffffu, m, 16));
            if (lq == 0) pmax[wm][wn * 32 + nj * 8 + 2 * ln + q] = m;
        }
    __syncthreads();
    if (tid < 64) {
        float m = fmaxf(fmaxf(pmax[0][tid], pmax[1][tid]),
                        fmaxf(pmax[2][tid], pmax[3][tid]));
        ymx[tid] = m;
        cnt[tid] = 0;
    }
    __syncthreads();

    // winner detection
#pragma unroll
    for (int mi = 0; mi < 4; mi++)
#pragma unroll
        for (int h = 0; h < 2; h++) {
            int o = wm * 64 + mi * 16 + lq + 8 * h;
#pragma unroll
            for (int nj = 0; nj < 4; nj++)
#pragma unroll
                for (int q = 0; q < 2; q++) {
                    int nn = wn * 32 + nj * 8 + 2 * ln + q;
                    float ym = ymx[nn];
                    if (ym > 0.f && c[mi][nj][h * 2 + q] == ym) {
                        int pos = atomicAdd(&cnt[nn], 1);
                        if (pos < 8) widx[nn][pos] = o;
                    }
                }
        }
    __syncthreads();

    // r = clip(lfb,-1,1) * y, store r^T bf16 (paired stores along n)
#pragma unroll
    for (int nj = 0; nj < 4; nj++) {
        int nn0 = wn * 32 + nj * 8 + 2 * ln;
        int c0 = min(cnt[nn0], 8), c1 = min(cnt[nn0 + 1], 8);
#pragma unroll
        for (int mi = 0; mi < 4; mi++)
#pragma unroll
            for (int h = 0; h < 2; h++) {
                int o = wm * 64 + mi * 16 + lq + 8 * h;
                float lfb0 = 0.f, lfb1 = 0.f;
                for (int j = 0; j < c0; j++) lfb0 += g_K[widx[nn0][j] * O_ + o];
                for (int j = 0; j < c1; j++) lfb1 += g_K[widx[nn0 + 1][j] * O_ + o];
                lfb0 = fminf(fmaxf(lfb0, -1.f), 1.f);
                lfb1 = fminf(fmaxf(lfb1, -1.f), 1.f);
                __nv_bfloat162 p;
                p.x = __float2bfloat16(lfb0 * c[mi][nj][h * 2 + 0]);
                p.y = __float2bfloat16(lfb1 * c[mi][nj][h * 2 + 1]);
                *(__nv_bfloat162*)(g_rTh + (size_t)o * NTOT + nT + nn0) = p;
            }
    }
}

// ------------------------- bf16 tensor-core NT GEMM, split-K ----------------
__device__ __forceinline__ uint32_t sw_off(int row, int kch) {
    return (uint32_t)(row * 128 + ((kch ^ (row & 7)) << 4));
}

template <bool RR>
__global__ void __launch_bounds__(256) k_mma() {
    __shared__ __align__(16) uint8_t As[128 * 128];
    __shared__ __align__(16) uint8_t Bs[128 * 128];

    int mT = blockIdx.y * 128, nT = blockIdx.x * 128;
    if (RR && mT < nT) return;                       // tril: skip upper tile

    const __nv_bfloat16* A = g_rTh;
    const __nv_bfloat16* Bm = RR ? g_rTh : g_xunfh;
    float* Cp = RR ? (g_rrP + (size_t)blockIdx.z * (O_ * O_))
                   : (g_rxP + (size_t)blockIdx.z * (O_ * D_));
    const int ldc = RR ? O_ : D_;

    int tid = threadIdx.x;
    int lane = tid & 31, wid = tid >> 5;
    int wm = wid >> 2, wn = wid & 3;                 // warp tile 64(m) x 32(n)
    size_t k0 = (size_t)blockIdx.z * KCHUNK;

    uint32_t sA = (uint32_t)__cvta_generic_to_shared(As);
    uint32_t sB = (uint32_t)__cvta_generic_to_shared(Bs);

    float c[4][4][4];
#pragma unroll
    for (int i = 0; i < 4; i++)
#pragma unroll
        for (int j = 0; j < 4; j++)
#pragma unroll
            for (int q = 0; q < 4; q++) c[i][j][q] = 0.f;

    int lt = lane >> 3, lr = lane & 7;
    int arow = ((lt & 1) << 3) + lr;
    int akch = lt >> 1;

    for (int kk = 0; kk < KCHUNK; kk += 64) {
#pragma unroll
        for (int i = 0; i < 4; i++) {
            int idx = tid + i * 256;
            int row = idx >> 3, ch = idx & 7;
            uint4 v = *(const uint4*)(A + (size_t)(mT + row) * NTOT + k0 + kk + ch * 8);
            *(uint4*)(As + row * 128 + ((ch ^ (row & 7)) << 4)) = v;
        }
#pragma unroll
        for (int i = 0; i < 4; i++) {
            int idx = tid + i * 256;
            int row = idx >> 3, ch = idx & 7;
            int grow = nT + row;
            uint4 v = make_uint4(0u, 0u, 0u, 0u);
            if (RR || grow < D_)
                v = *(const uint4*)(Bm + (size_t)grow * NTOT + k0 + kk + ch * 8);
            *(uint4*)(Bs + row * 128 + ((ch ^ (row & 7)) << 4)) = v;
        }
        __syncthreads();

#pragma unroll
        for (int ks = 0; ks < 4; ks++) {
            int kchb = ks * 2;
            uint32_t af[4][4];
#pragma unroll
            for (int mi = 0; mi < 4; mi++) {
                int row = wm * 64 + mi * 16 + arow;
                LDSM(af[mi][0], af[mi][1], af[mi][2], af[mi][3],
                     sA + sw_off(row, kchb + akch));
            }
            uint32_t bf[2][4];
#pragma unroll
            for (int bj = 0; bj < 2; bj++) {
                int row = wn * 32 + bj * 16 + arow;
                LDSM(bf[bj][0], bf[bj][1], bf[bj][2], bf[bj][3],
                     sB + sw_off(row, kchb + akch));
            }
#pragma unroll
            for (int mi = 0; mi < 4; mi++)
#pragma unroll
                for (int nj = 0; nj < 4; nj++) {
                    int g = nj >> 1, od = nj & 1;
                    MMA16816(c[mi][nj][0], c[mi][nj][1], c[mi][nj][2], c[mi][nj][3],
                             af[mi][0], af[mi][1], af[mi][2], af[mi][3],
                             bf[g][od], bf[g][od + 2]);
                }
        }
        __syncthreads();
    }

#pragma unroll
    for (int mi = 0; mi < 4; mi++) {
        int row0 = mT + wm * 64 + mi * 16 + (lane >> 2);
#pragma unroll
        for (int nj = 0; nj < 4; nj++) {
            int col0 = nT + wn * 32 + nj * 8 + 2 * (lane & 3);
#pragma unroll
            for (int h = 0; h < 2; h++) {
                int r = row0 + h * 8;
                float v0 = c[mi][nj][h * 2 + 0], v1 = c[mi][nj][h * 2 + 1];
                if (RR) {
                    Cp[(size_t)r * ldc + col0] = v0;
                    Cp[(size_t)r * ldc + col0 + 1] = v1;
                } else {
                    if (col0 < D_)     Cp[(size_t)r * ldc + col0] = v0;
                    if (col0 + 1 < D_) Cp[(size_t)r * ldc + col0 + 1] = v1;
                }
            }
        }
    }
}

// ------------------------- deterministic split-K reduce ---------------------
__global__ void k_reduce() {
    int t = blockIdx.x * 256 + threadIdx.x;          // 65536 + 19200 = 84736
    if (t < O_ * O_) {
        float s = 0.f;
        for (int z = 0; z < ZB; z++) s += g_rrP[(size_t)z * (O_ * O_) + t];
        g_rr[t] = s;
    } else if (t < O_ * O_ + O_ * D_) {
        int e = t - O_ * O_;
        float s = 0.f;
        for (int z = 0; z < ZB; z++) s += g_rxP[(size_t)z * (O_ * D_) + e];
        g_rx[e] = s;
    }
}

// ------------------------- weight update ------------------------------------
__global__ void k_update(const float* __restrict__ Wt, float* __restrict__ out) {
    int t = blockIdx.x * 256 + threadIdx.x;
    if (t >= O_ * D_) return;
    int o = t / D_;
    int d = t - o * D_;
    float s = 0.f;
    for (int o2 = 0; o2 <= o; o2++)
        s += g_rr[o * O_ + o2] * Wt[o2 * D_ + d];
    out[YOUT + t] = Wt[t] + 0.01f * ((g_rx[t] - s) * (1.0f / 115200.0f));
}

// ---------------------------------------------------------------------------
extern "C" void kernel_launch(void* const* d_in, const int* in_sizes, int n_in,
                              void* d_out, int out_size) {
    const float* x  = (const float*)d_in[0];
    const float* wt = (const float*)d_in[1];
    float* out = (float*)d_out;

    k_buildK<<<256, 256>>>();
    k_wprep<<<80, 256>>>(wt);
    k_xunf_dn<<<33750, 256>>>(x);
    k_xunf_nk<<<36000, 256>>>(x);
    k_convfused<<<1800, 256>>>(out);
    k_mma<true ><<<dim3(2, 2, ZB), 256>>>();
    k_mma<false><<<dim3(1, 2, ZB), 256>>>();
    k_reduce<<<332, 256>>>();
    k_update<<<75, 256>>>(wt, out);
}

// round 6
// speedup vs baseline: 2.9804x; 1.0245x over previous
#include <cuda_runtime.h>
#include <cuda_bf16.h>
#include <cstdint>

// ---------------------------------------------------------------------------
// HebbianMap2d: y_out = relu(conv(x,w)); new_w = w + eta*(r^T Xu - tril(r^T r) W)/N
// with r = lfb(winner(relu(s))) * relu(s).
// Shapes: x[32,3,64,64], w[256,3,5,5] -> y_out[32,256,60,60], new_w[256,75]
// ---------------------------------------------------------------------------

#define B_    32
#define C_    3
#define H_    64
#define W_    64
#define HO_   60
#define WO_   60
#define HW_   3600          // 60*60
#define O_    256
#define D_    75            // 3*5*5
#define DP    80            // D padded to multiple of 16
#define NTOT  115200        // 32*3600
#define YOUT  29491200      // 32*256*3600
#define ZB    150           // split-K chunks
#define KCHUNK 768          // NTOT / ZB (multiple of 64)

// ------------------------- scratch (device globals) ------------------------
__device__ __align__(16) float g_K[O_ * O_];                 // SOM lateral kernel
__device__ __align__(16) __nv_bfloat16 g_Whi[O_ * DP];       // W split-bf16 hi
__device__ __align__(16) __nv_bfloat16 g_Wlo[O_ * DP];       // W split-bf16 lo
__device__ __align__(16) __nv_bfloat16 g_xch[(size_t)NTOT * DP]; // im2col [n][80] hi
__device__ __align__(16) __nv_bfloat16 g_xcl[(size_t)NTOT * DP]; // im2col [n][80] lo
__device__ __align__(16) __nv_bfloat16 g_xunfh[(size_t)D_ * NTOT]; // [d][n] bf16 (rx GEMM)
__device__ __align__(16) __nv_bfloat16 g_rTh[(size_t)O_ * NTOT];   // r^T bf16 [o][n]
__device__ __align__(16) float g_rrP[(size_t)ZB * O_ * O_];  // split-K partials
__device__ __align__(16) float g_rxP[(size_t)ZB * O_ * D_];
__device__ __align__(16) float g_rr[O_ * O_];
__device__ __align__(16) float g_rx[O_ * D_];

// ------------------------- K table + W split prep (merged) ------------------
__global__ void k_init(const float* __restrict__ Wt) {
    int t = blockIdx.x * 256 + threadIdx.x;          // 65536 total
    {   // K table
        int w = t >> 8, o = t & 255;
        int wi = w >> 4, wj = w & 15, i = o >> 4, j = o & 15;
        int a = wi - i + 7, b = wj - j + 7;
        float v = 0.f;
        if (a >= 0 && a < 16 && b >= 0 && b < 16) {
            int da = abs(a - 7), db = abs(b - 7);
            int m = da > db ? da : db;
            v = expf(-(float)(m * m) / 98.0f);
        }
        g_K[t] = v;
    }
    if (t < O_ * DP) {                               // W split-bf16
        int o = t / DP, d = t - o * DP;
        float v = (d < D_) ? Wt[o * D_ + d] : 0.f;
        __nv_bfloat16 hi = __float2bfloat16(v);
        g_Whi[t] = hi;
        g_Wlo[t] = __float2bfloat16(v - __bfloat162float(hi));
    }
}

// ------------------------- im2col [d][n] bf16 (for rx GEMM) -----------------
__global__ void k_xunf_dn(const float* __restrict__ x) {
    int t = blockIdx.x * 256 + threadIdx.x;          // D_*NTOT = 8,640,000 exactly
    int d = t / NTOT;
    int n = t - d * NTOT;
    int b = n / HW_;
    int hw = n - b * HW_;
    int i = hw / WO_;
    int j = hw - i * WO_;
    int c = d / 25;
    int rr = d - c * 25;
    int ki = rr / 5;
    int kj = rr - ki * 5;
    g_xunfh[t] = __float2bfloat16(x[((b * C_ + c) * H_ + i + ki) * W_ + j + kj]);
}

// ------------------------- im2col [n][80] hi/lo (for conv MMA) --------------
__global__ void k_xunf_nk(const float* __restrict__ x) {
    int t = blockIdx.x * 256 + threadIdx.x;          // NTOT*DP = 9,216,000 exactly
    int n = t / DP;
    int d = t - n * DP;
    float v = 0.f;
    if (d < D_) {
        int b = n / HW_;
        int hw = n - b * HW_;
        int i = hw / WO_;
        int j = hw - i * WO_;
        int c = d / 25;
        int rr = d - c * 25;
        int ki = rr / 5;
        int kj = rr - ki * 5;
        v = x[((b * C_ + c) * H_ + i + ki) * W_ + j + kj];
    }
    __nv_bfloat16 hi = __float2bfloat16(v);
    g_xch[t] = hi;
    g_xcl[t] = __float2bfloat16(v - __bfloat162float(hi));
}

// ------------------------- fused conv + winner + lfb + r --------------------
#define LDSM(r0,r1,r2,r3,addr) \
    asm volatile("ldmatrix.sync.aligned.m8n8.x4.shared.b16 {%0,%1,%2,%3}, [%4];" \
                 : "=r"(r0), "=r"(r1), "=r"(r2), "=r"(r3) : "r"(addr))
#define MMA16816(c0,c1,c2,c3,a0,a1,a2,a3,b0,b1) \
    asm volatile("mma.sync.aligned.m16n8k16.row.col.f32.bf16.bf16.f32 " \
                 "{%0,%1,%2,%3}, {%4,%5,%6,%7}, {%8,%9}, {%0,%1,%2,%3};" \
                 : "+f"(c0), "+f"(c1), "+f"(c2), "+f"(c3) \
                 : "r"(a0), "r"(a1), "r"(a2), "r"(a3), "r"(b0), "r"(b1))

// union buffer: mainloop (sW 24KB + sX 6KB) / ybuf 33.8KB / rbuf 33.8KB
#define SMEM_U_BYTES 33792

__global__ void __launch_bounds__(256) k_convfused(float* __restrict__ out) {
    __shared__ __align__(16) uint8_t smem_u[SMEM_U_BYTES];
    __shared__ float pmax[4][64];
    __shared__ float ymx[64];
    __shared__ int   nbase64[64];
    __shared__ int   cnt[64];
    __shared__ int   widx[64][8];

    __nv_bfloat16* sW = (__nv_bfloat16*)smem_u;                 // 512 rows x 24
    __nv_bfloat16* sX = (__nv_bfloat16*)(smem_u + 24576);       // 128 rows x 24
    float*         ybuf = (float*)smem_u;                       // 128 rows x 66
    __nv_bfloat16* rbuf = (__nv_bfloat16*)smem_u;               // 256 rows x 66

    int tid = threadIdx.x, lane = tid & 31, wid = tid >> 5;
    int wm = wid >> 1, wn = wid & 1;
    int nT = blockIdx.x * 64;

    uint32_t sWb = (uint32_t)__cvta_generic_to_shared(sW);
    uint32_t sXb = (uint32_t)__cvta_generic_to_shared(sX);

    int lt = lane >> 3, lr = lane & 7;
    int arow = ((lt & 1) << 3) + lr;
    int akch = lt >> 1;

    float c[4][4][4];
#pragma unroll
    for (int i = 0; i < 4; i++)
#pragma unroll
        for (int j = 0; j < 4; j++)
#pragma unroll
            for (int q = 0; q < 4; q++) c[i][j][q] = 0.f;

    // per-thread fixed load indices
    int wpiece = tid & 1, whl = (tid >> 1) & 1;      // for W: idx = tid + i*256
    int xpiece = tid & 1, xhl = (tid >> 1) & 1, xrow = tid >> 2;

    uint4 wreg[4];
    uint4 xreg;

    // ---- prologue: load stage 0 ----
#pragma unroll
    for (int i = 0; i < 4; i++) {
        int idx = tid + i * 256;
        int row = idx >> 2;
        const __nv_bfloat16* src = ((idx >> 1) & 1) ? g_Wlo : g_Whi;
        wreg[i] = *(const uint4*)(src + row * DP + (idx & 1) * 8);
    }
    {
        const __nv_bfloat16* src = xhl ? g_xcl : g_xch;
        xreg = *(const uint4*)(src + (size_t)(nT + xrow) * DP + xpiece * 8);
    }
#pragma unroll
    for (int i = 0; i < 4; i++) {
        int idx = tid + i * 256;
        int row = idx >> 2;
        *(uint4*)(sW + (((idx >> 1) & 1) * 256 + row) * 24 + (idx & 1) * 8) = wreg[i];
    }
    *(uint4*)(sX + (xhl * 64 + xrow) * 24 + xpiece * 8) = xreg;
    __syncthreads();

    for (int s = 0; s < 5; s++) {
        // prefetch next stage into regs (latency overlapped with MMAs)
        if (s < 4) {
#pragma unroll
            for (int i = 0; i < 4; i++) {
                int idx = tid + i * 256;
                int row = idx >> 2;
                const __nv_bfloat16* src = ((idx >> 1) & 1) ? g_Wlo : g_Whi;
                wreg[i] = *(const uint4*)(src + row * DP + (s + 1) * 16 + (idx & 1) * 8);
            }
            const __nv_bfloat16* src = xhl ? g_xcl : g_xch;
            xreg = *(const uint4*)(src + (size_t)(nT + xrow) * DP + (s + 1) * 16 + xpiece * 8);
        }

        uint32_t ah[4][4], al[4][4], bh[2][4], bl[2][4];
#pragma unroll
        for (int mi = 0; mi < 4; mi++) {
            int row = wm * 64 + mi * 16 + arow;
            LDSM(ah[mi][0], ah[mi][1], ah[mi][2], ah[mi][3], sWb + row * 48 + akch * 16);
            LDSM(al[mi][0], al[mi][1], al[mi][2], al[mi][3], sWb + (256 + row) * 48 + akch * 16);
        }
#pragma unroll
        for (int bj = 0; bj < 2; bj++) {
            int row = wn * 32 + bj * 16 + arow;
            LDSM(bh[bj][0], bh[bj][1], bh[bj][2], bh[bj][3], sXb + row * 48 + akch * 16);
            LDSM(bl[bj][0], bl[bj][1], bl[bj][2], bl[bj][3], sXb + (64 + row) * 48 + akch * 16);
        }
#pragma unroll
        for (int mi = 0; mi < 4; mi++)
#pragma unroll
            for (int nj = 0; nj < 4; nj++) {
                int g = nj >> 1, od = nj & 1;
                MMA16816(c[mi][nj][0], c[mi][nj][1], c[mi][nj][2], c[mi][nj][3],
                         ah[mi][0], ah[mi][1], ah[mi][2], ah[mi][3],
                         bh[g][od], bh[g][od + 2]);
                MMA16816(c[mi][nj][0], c[mi][nj][1], c[mi][nj][2], c[mi][nj][3],
                         ah[mi][0], ah[mi][1], ah[mi][2], ah[mi][3],
                         bl[g][od], bl[g][od + 2]);
                MMA16816(c[mi][nj][0], c[mi][nj][1], c[mi][nj][2], c[mi][nj][3],
                         al[mi][0], al[mi][1], al[mi][2], al[mi][3],
                         bh[g][od], bh[g][od + 2]);
            }
        __syncthreads();
        if (s < 4) {
#pragma unroll
            for (int i = 0; i < 4; i++) {
                int idx = tid + i * 256;
                int row = idx >> 2;
                *(uint4*)(sW + (((idx >> 1) & 1) * 256 + row) * 24 + (idx & 1) * 8) = wreg[i];
            }
            *(uint4*)(sX + (xhl * 64 + xrow) * 24 + xpiece * 8) = xreg;
            __syncthreads();
        }
    }

    // ---------------- epilogue ----------------
    int lq = lane >> 2, ln = lane & 3;

    // 1) relu in regs + per-thread column max
    float tmax[4][2];
#pragma unroll
    for (int nj = 0; nj < 4; nj++)
#pragma unroll
        for (int q = 0; q < 2; q++) tmax[nj][q] = 0.f;
#pragma unroll
    for (int mi = 0; mi < 4; mi++)
#pragma unroll
        for (int nj = 0; nj < 4; nj++)
#pragma unroll
            for (int q = 0; q < 4; q++) {
                float y = fmaxf(c[mi][nj][q], 0.f);
                c[mi][nj][q] = y;
                tmax[nj][q & 1] = fmaxf(tmax[nj][q & 1], y);
            }

    // 2) warp max -> pmax ; nbase64
#pragma unroll
    for (int nj = 0; nj < 4; nj++)
#pragma unroll
        for (int q = 0; q < 2; q++) {
            float m = tmax[nj][q];
            m = fmaxf(m, __shfl_xor_sync(0xffffffffu, m, 4));
            m = fmaxf(m, __shfl_xor_sync(0xffffffffu, m, 8));
            m = fmaxf(m, __shfl_xor_sync(0xffffffffu, m, 16));
            if (lq == 0) pmax[wm][wn * 32 + nj * 8 + 2 * ln + q] = m;
        }
    if (tid < 64) {
        int n = nT + tid;
        int b = n / HW_;
        nbase64[tid] = b * (O_ * HW_) + (n - b * HW_);
    }
    __syncthreads();

    // 3) combine ymax, reset counters
    if (tid < 64) {
        ymx[tid] = fmaxf(fmaxf(pmax[0][tid], pmax[1][tid]),
                         fmaxf(pmax[2][tid], pmax[3][tid]));
        cnt[tid] = 0;
    }
    __syncthreads();

    // 4) winner detection (from regs)
#pragma unroll
    for (int mi = 0; mi < 4; mi++)
#pragma unroll
        for (int h = 0; h < 2; h++) {
            int o = wm * 64 + mi * 16 + lq + 8 * h;
#pragma unroll
            for (int nj = 0; nj < 4; nj++)
#pragma unroll
                for (int q = 0; q < 2; q++) {
                    int nn = wn * 32 + nj * 8 + 2 * ln + q;
                    float ym = ymx[nn];
                    if (ym > 0.f && c[mi][nj][h * 2 + q] == ym) {
                        int pos = atomicAdd(&cnt[nn], 1);
                        if (pos < 8) widx[nn][pos] = o;
                    }
                }
        }
    __syncthreads();

    // 5-7) y_out staged in two 128-row halves, coalesced writes
#pragma unroll
    for (int half = 0; half < 2; half++) {
        if ((wm >> 1) == half) {                      // wm 0,1 -> half0 ; 2,3 -> half1
            int obase = (wm & 1) * 64;
#pragma unroll
            for (int mi = 0; mi < 4; mi++)
#pragma unroll
                for (int h = 0; h < 2; h++) {
                    int orow = obase + mi * 16 + lq + 8 * h;
#pragma unroll
                    for (int nj = 0; nj < 4; nj++) {
                        int nn = wn * 32 + nj * 8 + 2 * ln;
                        ybuf[orow * 66 + nn]     = c[mi][nj][h * 2 + 0];
                        ybuf[orow * 66 + nn + 1] = c[mi][nj][h * 2 + 1];
                    }
                }
        }
        __syncthreads();
        // write 128 rows: warp w -> rows w*16 .. w*16+15 ; lane -> 2 floats
#pragma unroll
        for (int rr2 = 0; rr2 < 16; rr2++) {
            int orow = wid * 16 + rr2;
            int o = half * 128 + orow;
            size_t ob = (size_t)o * HW_;
            int n0 = 2 * lane;
            out[ob + nbase64[n0]]     = ybuf[orow * 66 + n0];
            out[ob + nbase64[n0 + 1]] = ybuf[orow * 66 + n0 + 1];
        }
        __syncthreads();
    }

    // 8) r = clip(lfb,-1,1)*y -> rbuf (bf16)
#pragma unroll
    for (int nj = 0; nj < 4; nj++) {
        int nn0 = wn * 32 + nj * 8 + 2 * ln;
        int c0 = min(cnt[nn0], 8), c1 = min(cnt[nn0 + 1], 8);
#pragma unroll
        for (int mi = 0; mi < 4; mi++)
#pragma unroll
            for (int h = 0; h < 2; h++) {
                int o = wm * 64 + mi * 16 + lq + 8 * h;
                float lfb0 = 0.f, lfb1 = 0.f;
                for (int j = 0; j < c0; j++) lfb0 += g_K[widx[nn0][j] * O_ + o];
                for (int j = 0; j < c1; j++) lfb1 += g_K[widx[nn0 + 1][j] * O_ + o];
                lfb0 = fminf(fmaxf(lfb0, -1.f), 1.f);
                lfb1 = fminf(fmaxf(lfb1, -1.f), 1.f);
                __nv_bfloat162 p;
                p.x = __float2bfloat16(lfb0 * c[mi][nj][h * 2 + 0]);
                p.y = __float2bfloat16(lfb1 * c[mi][nj][h * 2 + 1]);
                *(__nv_bfloat162*)(rbuf + o * 66 + nn0) = p;
            }
    }
    __syncthreads();

    // 9) coalesced rT write: warp w -> rows 32w..32w+31 ; lane -> 1 uint (2 n)
#pragma unroll
    for (int rr2 = 0; rr2 < 32; rr2++) {
        int o = wid * 32 + rr2;
        uint32_t v = *(uint32_t*)(rbuf + o * 66 + 2 * lane);
        *(uint32_t*)(g_rTh + (size_t)o * NTOT + nT + 2 * lane) = v;
    }
}

// ------------------------- bf16 tensor-core NT GEMM, split-K ----------------
__device__ __forceinline__ uint32_t sw_off(int row, int kch) {
    return (uint32_t)(row * 128 + ((kch ^ (row & 7)) << 4));
}

template <bool RR>
__global__ void __launch_bounds__(256) k_mma() {
    __shared__ __align__(16) uint8_t As[128 * 128];
    __shared__ __align__(16) uint8_t Bs[128 * 128];

    int mT, nT;
    if (RR) {                                        // 3 lower tiles only
        int ti = blockIdx.x;                         // 0..2
        mT = (ti >= 1) ? 128 : 0;
        nT = (ti == 2) ? 128 : 0;
    } else {
        mT = blockIdx.y * 128;
        nT = 0;
    }

    const __nv_bfloat16* A = g_rTh;
    const __nv_bfloat16* Bm = RR ? g_rTh : g_xunfh;
    float* Cp = RR ? (g_rrP + (size_t)blockIdx.z * (O_ * O_))
                   : (g_rxP + (size_t)blockIdx.z * (O_ * D_));
    const int ldc = RR ? O_ : D_;

    int tid = threadIdx.x;
    int lane = tid & 31, wid = tid >> 5;
    int wm = wid >> 2, wn = wid & 3;                 // warp tile 64(m) x 32(n)
    size_t k0 = (size_t)blockIdx.z * KCHUNK;

    uint32_t sA = (uint32_t)__cvta_generic_to_shared(As);
    uint32_t sB = (uint32_t)__cvta_generic_to_shared(Bs);

    float c[4][4][4];
#pragma unroll
    for (int i = 0; i < 4; i++)
#pragma unroll
        for (int j = 0; j < 4; j++)
#pragma unroll
            for (int q = 0; q < 4; q++) c[i][j][q] = 0.f;

    int lt = lane >> 3, lr = lane & 7;
    int arow = ((lt & 1) << 3) + lr;
    int akch = lt >> 1;

    for (int kk = 0; kk < KCHUNK; kk += 64) {
#pragma unroll
        for (int i = 0; i < 4; i++) {
            int idx = tid + i * 256;
            int row = idx >> 3, ch = idx & 7;
            uint4 v = *(const uint4*)(A + (size_t)(mT + row) * NTOT + k0 + kk + ch * 8);
            *(uint4*)(As + row * 128 + ((ch ^ (row & 7)) << 4)) = v;
        }
#pragma unroll
        for (int i = 0; i < 4; i++) {
            int idx = tid + i * 256;
            int row = idx >> 3, ch = idx & 7;
            int grow = nT + row;
            uint4 v = make_uint4(0u, 0u, 0u, 0u);
            if (RR || grow < D_)
                v = *(const uint4*)(Bm + (size_t)grow * NTOT + k0 + kk + ch * 8);
            *(uint4*)(Bs + row * 128 + ((ch ^ (row & 7)) << 4)) = v;
        }
        __syncthreads();

#pragma unroll
        for (int ks = 0; ks < 4; ks++) {
            int kchb = ks * 2;
            uint32_t af[4][4];
#pragma unroll
            for (int mi = 0; mi < 4; mi++) {
                int row = wm * 64 + mi * 16 + arow;
                LDSM(af[mi][0], af[mi][1], af[mi][2], af[mi][3],
                     sA + sw_off(row, kchb + akch));
            }
            uint32_t bf[2][4];
#pragma unroll
            for (int bj = 0; bj < 2; bj++) {
                int row = wn * 32 + bj * 16 + arow;
                LDSM(bf[bj][0], bf[bj][1], bf[bj][2], bf[bj][3],
                     sB + sw_off(row, kchb + akch));
            }
#pragma unroll
            for (int mi = 0; mi < 4; mi++)
#pragma unroll
                for (int nj = 0; nj < 4; nj++) {
                    int g = nj >> 1, od = nj & 1;
                    MMA16816(c[mi][nj][0], c[mi][nj][1], c[mi][nj][2], c[mi][nj][3],
                             af[mi][0], af[mi][1], af[mi][2], af[mi][3],
                             bf[g][od], bf[g][od + 2]);
                }
        }
        __syncthreads();
    }

#pragma unroll
    for (int mi = 0; mi < 4; mi++) {
        int row0 = mT + wm * 64 + mi * 16 + (lane >> 2);
#pragma unroll
        for (int nj = 0; nj < 4; nj++) {
            int col0 = nT + wn * 32 + nj * 8 + 2 * (lane & 3);
#pragma unroll
            for (int h = 0; h < 2; h++) {
                int r = row0 + h * 8;
                float v0 = c[mi][nj][h * 2 + 0], v1 = c[mi][nj][h * 2 + 1];
                if (RR) {
                    Cp[(size_t)r * ldc + col0] = v0;
                    Cp[(size_t)r * ldc + col0 + 1] = v1;
                } else {
                    if (col0 < D_)     Cp[(size_t)r * ldc + col0] = v0;
                    if (col0 + 1 < D_) Cp[(size_t)r * ldc + col0 + 1] = v1;
                }
            }
        }
    }
}

// ------------------------- deterministic split-K reduce ---------------------
__global__ void k_reduce() {
    int t = blockIdx.x * 256 + threadIdx.x;          // 65536 + 19200 = 84736
    if (t < O_ * O_) {
        float s = 0.f;
        for (int z = 0; z < ZB; z++) s += g_rrP[(size_t)z * (O_ * O_) + t];
        g_rr[t] = s;
    } else if (t < O_ * O_ + O_ * D_) {
        int e = t - O_ * O_;
        float s = 0.f;
        for (int z = 0; z < ZB; z++) s += g_rxP[(size_t)z * (O_ * D_) + e];
        g_rx[e] = s;
    }
}

// ------------------------- weight update ------------------------------------
__global__ void k_update(const float* __restrict__ Wt, float* __restrict__ out) {
    int t = blockIdx.x * 256 + threadIdx.x;
    if (t >= O_ * D_) return;
    int o = t / D_;
    int d = t - o * D_;
    float s = 0.f;
    for (int o2 = 0; o2 <= o; o2++)
        s += g_rr[o * O_ + o2] * Wt[o2 * D_ + d];
    out[YOUT + t] = Wt[t] + 0.01f * ((g_rx[t] - s) * (1.0f / 115200.0f));
}

// ---------------------------------------------------------------------------
extern "C" void kernel_launch(void* const* d_in, const int* in_sizes, int n_in,
                              void* d_out, int out_size) {
    const float* x  = (const float*)d_in[0];
    const float* wt = (const float*)d_in[1];
    float* out = (float*)d_out;

    k_init<<<256, 256>>>(wt);
    k_xunf_dn<<<33750, 256>>>(x);
    k_xunf_nk<<<36000, 256>>>(x);
    k_convfused<<<1800, 256>>>(out);
    k_mma<true ><<<dim3(3, 1, ZB), 256>>>();
    k_mma<false><<<dim3(1, 2, ZB), 256>>>();
    k_reduce<<<332, 256>>>();
    k_update<<<75, 256>>>(wt, out);
}

// round 7
// speedup vs baseline: 3.5282x; 1.1838x over previous
#include <cuda_runtime.h>
#include <cuda_bf16.h>
#include <cstdint>

// ---------------------------------------------------------------------------
// HebbianMap2d: y_out = relu(conv(x,w)); new_w = w + eta*(r^T Xu - tril(r^T r) W)/N
// with r = lfb(winner(relu(s))) * relu(s).
// Shapes: x[32,3,64,64], w[256,3,5,5] -> y_out[32,256,60,60], new_w[256,75]
// ---------------------------------------------------------------------------

#define B_    32
#define C_    3
#define H_    64
#define W_    64
#define HO_   60
#define WO_   60
#define HW_   3600          // 60*60
#define O_    256
#define D_    75            // 3*5*5
#define DP    80            // D padded to multiple of 16
#define NTOT  115200        // 32*3600
#define YOUT  29491200      // 32*256*3600
#define ZB    150           // split-K chunks
#define KCHUNK 768          // NTOT / ZB (multiple of 64)

// ------------------------- scratch (device globals) ------------------------
__device__ __align__(16) float g_K[O_ * O_];                 // SOM lateral kernel
__device__ __align__(16) __nv_bfloat16 g_Whi[O_ * DP];       // W split-bf16 hi
__device__ __align__(16) __nv_bfloat16 g_Wlo[O_ * DP];       // W split-bf16 lo
__device__ __align__(16) __nv_bfloat16 g_xch[(size_t)NTOT * DP]; // im2col [n][80] hi
__device__ __align__(16) __nv_bfloat16 g_xcl[(size_t)NTOT * DP]; // im2col [n][80] lo
__device__ __align__(16) __nv_bfloat16 g_xunfh[(size_t)D_ * NTOT]; // [d][n] bf16 (rx GEMM)
__device__ __align__(16) __nv_bfloat16 g_rTh[(size_t)O_ * NTOT];   // r^T bf16 [o][n]
__device__ __align__(16) float g_rrP[(size_t)ZB * O_ * O_];  // split-K partials
__device__ __align__(16) float g_rxP[(size_t)ZB * O_ * D_];
__device__ __align__(16) float g_rr[O_ * O_];
__device__ __align__(16) float g_rx[O_ * D_];

// ------------------------- K table + W split prep (merged) ------------------
__global__ void k_init(const float* __restrict__ Wt) {
    int t = blockIdx.x * 256 + threadIdx.x;          // 65536 total
    {   // K table
        int w = t >> 8, o = t & 255;
        int wi = w >> 4, wj = w & 15, i = o >> 4, j = o & 15;
        int a = wi - i + 7, b = wj - j + 7;
        float v = 0.f;
        if (a >= 0 && a < 16 && b >= 0 && b < 16) {
            int da = abs(a - 7), db = abs(b - 7);
            int m = da > db ? da : db;
            v = expf(-(float)(m * m) / 98.0f);
        }
        g_K[t] = v;
    }
    if (t < O_ * DP) {                               // W split-bf16
        int o = t / DP, d = t - o * DP;
        float v = (d < D_) ? Wt[o * D_ + d] : 0.f;
        __nv_bfloat16 hi = __float2bfloat16(v);
        g_Whi[t] = hi;
        g_Wlo[t] = __float2bfloat16(v - __bfloat162float(hi));
    }
}

// ------------------------- tiled im2col (all 3 layouts) ---------------------
// block = one (b, i): loads x window [3][5][64] to smem, emits
//   g_xch/g_xcl [n][80] (hi/lo) and g_xunfh [d][n].
__global__ void __launch_bounds__(128) k_im2col(const float* __restrict__ x) {
    __shared__ float xs[3][5][64];
    int b = blockIdx.x >> 6, i = blockIdx.x & 63;    // grid 2048, skip i>=60
    if (i >= HO_) return;
    int tid = threadIdx.x;
    int n0 = b * HW_ + i * WO_;

    for (int idx = tid; idx < 960; idx += 128) {
        int c = idx / 320, rem = idx - c * 320;
        int ki = rem >> 6, col = rem & 63;
        xs[c][ki][col] = x[((b * C_ + c) * H_ + i + ki) * W_ + col];
    }
    __syncthreads();

    // [n][80] hi/lo: unit u = (j, dblk of 8); 600 units
    for (int u = tid; u < 600; u += 128) {
        int j = u / 10, dblk = (u - j * 10) * 8;
        __nv_bfloat16 hibuf[8], lobuf[8];
#pragma unroll
        for (int dd = 0; dd < 8; dd++) {
            int d = dblk + dd;
            float v = 0.f;
            if (d < D_) {
                int c = d / 25, rr = d - c * 25;
                int ki = rr / 5, kj = rr - ki * 5;
                v = xs[c][ki][j + kj];
            }
            __nv_bfloat16 hi = __float2bfloat16(v);
            hibuf[dd] = hi;
            lobuf[dd] = __float2bfloat16(v - __bfloat162float(hi));
        }
        size_t base = (size_t)(n0 + j) * DP + dblk;
        *(uint4*)(g_xch + base) = *(uint4*)hibuf;
        *(uint4*)(g_xcl + base) = *(uint4*)lobuf;
    }

    // [d][n]: unit = (d, jpair); 75*30 = 2250 units
    for (int u = tid; u < 2250; u += 128) {
        int d = u / 30, j = (u - d * 30) * 2;
        int c = d / 25, rr = d - c * 25;
        int ki = rr / 5, kj = rr - ki * 5;
        __nv_bfloat162 p;
        p.x = __float2bfloat16(xs[c][ki][j + kj]);
        p.y = __float2bfloat16(xs[c][ki][j + 1 + kj]);
        *(__nv_bfloat162*)(g_xunfh + (size_t)d * NTOT + n0 + j) = p;
    }
}

// ------------------------- fused conv + winner + lfb + r --------------------
#define LDSM(r0,r1,r2,r3,addr) \
    asm volatile("ldmatrix.sync.aligned.m8n8.x4.shared.b16 {%0,%1,%2,%3}, [%4];" \
                 : "=r"(r0), "=r"(r1), "=r"(r2), "=r"(r3) : "r"(addr))
#define MMA16816(c0,c1,c2,c3,a0,a1,a2,a3,b0,b1) \
    asm volatile("mma.sync.aligned.m16n8k16.row.col.f32.bf16.bf16.f32 " \
                 "{%0,%1,%2,%3}, {%4,%5,%6,%7}, {%8,%9}, {%0,%1,%2,%3};" \
                 : "+f"(c0), "+f"(c1), "+f"(c2), "+f"(c3) \
                 : "r"(a0), "r"(a1), "r"(a2), "r"(a3), "r"(b0), "r"(b1))

// union buffer: mainloop (sW 24KB + sX 6KB) / ybuf 33.8KB / rbuf 33.8KB
#define SMEM_U_BYTES 33792

__global__ void __launch_bounds__(256) k_convfused(float* __restrict__ out) {
    __shared__ __align__(16) uint8_t smem_u[SMEM_U_BYTES];
    __shared__ float pmax[4][64];
    __shared__ float ymx[64];
    __shared__ int   nbase64[64];
    __shared__ int   cnt[64];
    __shared__ int   widx[64][8];

    __nv_bfloat16* sW = (__nv_bfloat16*)smem_u;                 // 512 rows x 24
    __nv_bfloat16* sX = (__nv_bfloat16*)(smem_u + 24576);       // 128 rows x 24
    float*         ybuf = (float*)smem_u;                       // 128 rows x 66
    __nv_bfloat16* rbuf = (__nv_bfloat16*)smem_u;               // 256 rows x 66

    int tid = threadIdx.x, lane = tid & 31, wid = tid >> 5;
    int wm = wid >> 1, wn = wid & 1;
    int nT = blockIdx.x * 64;

    uint32_t sWb = (uint32_t)__cvta_generic_to_shared(sW);
    uint32_t sXb = (uint32_t)__cvta_generic_to_shared(sX);

    int lt = lane >> 3, lr = lane & 7;
    int arow = ((lt & 1) << 3) + lr;
    int akch = lt >> 1;

    float c[4][4][4];
#pragma unroll
    for (int i = 0; i < 4; i++)
#pragma unroll
        for (int j = 0; j < 4; j++)
#pragma unroll
            for (int q = 0; q < 4; q++) c[i][j][q] = 0.f;

    int xpiece = tid & 1, xhl = (tid >> 1) & 1, xrow = tid >> 2;

    uint4 wreg[4];
    uint4 xreg;

    // ---- prologue: load stage 0 ----
#pragma unroll
    for (int i = 0; i < 4; i++) {
        int idx = tid + i * 256;
        int row = idx >> 2;
        const __nv_bfloat16* src = ((idx >> 1) & 1) ? g_Wlo : g_Whi;
        wreg[i] = *(const uint4*)(src + row * DP + (idx & 1) * 8);
    }
    {
        const __nv_bfloat16* src = xhl ? g_xcl : g_xch;
        xreg = *(const uint4*)(src + (size_t)(nT + xrow) * DP + xpiece * 8);
    }
#pragma unroll
    for (int i = 0; i < 4; i++) {
        int idx = tid + i * 256;
        int row = idx >> 2;
        *(uint4*)(sW + (((idx >> 1) & 1) * 256 + row) * 24 + (idx & 1) * 8) = wreg[i];
    }
    *(uint4*)(sX + (xhl * 64 + xrow) * 24 + xpiece * 8) = xreg;
    __syncthreads();

    for (int s = 0; s < 5; s++) {
        if (s < 4) {
#pragma unroll
            for (int i = 0; i < 4; i++) {
                int idx = tid + i * 256;
                int row = idx >> 2;
                const __nv_bfloat16* src = ((idx >> 1) & 1) ? g_Wlo : g_Whi;
                wreg[i] = *(const uint4*)(src + row * DP + (s + 1) * 16 + (idx & 1) * 8);
            }
            const __nv_bfloat16* src = xhl ? g_xcl : g_xch;
            xreg = *(const uint4*)(src + (size_t)(nT + xrow) * DP + (s + 1) * 16 + xpiece * 8);
        }

        uint32_t ah[4][4], al[4][4], bh[2][4], bl[2][4];
#pragma unroll
        for (int mi = 0; mi < 4; mi++) {
            int row = wm * 64 + mi * 16 + arow;
            LDSM(ah[mi][0], ah[mi][1], ah[mi][2], ah[mi][3], sWb + row * 48 + akch * 16);
            LDSM(al[mi][0], al[mi][1], al[mi][2], al[mi][3], sWb + (256 + row) * 48 + akch * 16);
        }
#pragma unroll
        for (int bj = 0; bj < 2; bj++) {
            int row = wn * 32 + bj * 16 + arow;
            LDSM(bh[bj][0], bh[bj][1], bh[bj][2], bh[bj][3], sXb + row * 48 + akch * 16);
            LDSM(bl[bj][0], bl[bj][1], bl[bj][2], bl[bj][3], sXb + (64 + row) * 48 + akch * 16);
        }
#pragma unroll
        for (int mi = 0; mi < 4; mi++)
#pragma unroll
            for (int nj = 0; nj < 4; nj++) {
                int g = nj >> 1, od = nj & 1;
                MMA16816(c[mi][nj][0], c[mi][nj][1], c[mi][nj][2], c[mi][nj][3],
                         ah[mi][0], ah[mi][1], ah[mi][2], ah[mi][3],
                         bh[g][od], bh[g][od + 2]);
                MMA16816(c[mi][nj][0], c[mi][nj][1], c[mi][nj][2], c[mi][nj][3],
                         ah[mi][0], ah[mi][1], ah[mi][2], ah[mi][3],
                         bl[g][od], bl[g][od + 2]);
                MMA16816(c[mi][nj][0], c[mi][nj][1], c[mi][nj][2], c[mi][nj][3],
                         al[mi][0], al[mi][1], al[mi][2], al[mi][3],
                         bh[g][od], bh[g][od + 2]);
            }
        __syncthreads();
        if (s < 4) {
#pragma unroll
            for (int i = 0; i < 4; i++) {
                int idx = tid + i * 256;
                int row = idx >> 2;
                *(uint4*)(sW + (((idx >> 1) & 1) * 256 + row) * 24 + (idx & 1) * 8) = wreg[i];
            }
            *(uint4*)(sX + (xhl * 64 + xrow) * 24 + xpiece * 8) = xreg;
            __syncthreads();
        }
    }

    // ---------------- epilogue ----------------
    int lq = lane >> 2, ln = lane & 3;

    // 1) relu in regs + per-thread column max
    float tmax[4][2];
#pragma unroll
    for (int nj = 0; nj < 4; nj++)
#pragma unroll
        for (int q = 0; q < 2; q++) tmax[nj][q] = 0.f;
#pragma unroll
    for (int mi = 0; mi < 4; mi++)
#pragma unroll
        for (int nj = 0; nj < 4; nj++)
#pragma unroll
            for (int q = 0; q < 4; q++) {
                float y = fmaxf(c[mi][nj][q], 0.f);
                c[mi][nj][q] = y;
                tmax[nj][q & 1] = fmaxf(tmax[nj][q & 1], y);
            }

    // 2) warp max -> pmax ; nbase64
#pragma unroll
    for (int nj = 0; nj < 4; nj++)
#pragma unroll
        for (int q = 0; q < 2; q++) {
            float m = tmax[nj][q];
            m = fmaxf(m, __shfl_xor_sync(0xffffffffu, m, 4));
            m = fmaxf(m, __shfl_xor_sync(0xffffffffu, m, 8));
            m = fmaxf(m, __shfl_xor_sync(0xffffffffu, m, 16));
            if (lq == 0) pmax[wm][wn * 32 + nj * 8 + 2 * ln + q] = m;
        }
    if (tid < 64) {
        int n = nT + tid;
        int b = n / HW_;
        nbase64[tid] = b * (O_ * HW_) + (n - b * HW_);
    }
    __syncthreads();

    // 3) combine ymax, reset counters
    if (tid < 64) {
        ymx[tid] = fmaxf(fmaxf(pmax[0][tid], pmax[1][tid]),
                         fmaxf(pmax[2][tid], pmax[3][tid]));
        cnt[tid] = 0;
    }
    __syncthreads();

    // 4) winner detection (from regs)
#pragma unroll
    for (int mi = 0; mi < 4; mi++)
#pragma unroll
        for (int h = 0; h < 2; h++) {
            int o = wm * 64 + mi * 16 + lq + 8 * h;
#pragma unroll
            for (int nj = 0; nj < 4; nj++)
#pragma unroll
                for (int q = 0; q < 2; q++) {
                    int nn = wn * 32 + nj * 8 + 2 * ln + q;
                    float ym = ymx[nn];
                    if (ym > 0.f && c[mi][nj][h * 2 + q] == ym) {
                        int pos = atomicAdd(&cnt[nn], 1);
                        if (pos < 8) widx[nn][pos] = o;
                    }
                }
        }
    __syncthreads();

    // 5-7) y_out staged in two 128-row halves, coalesced writes
#pragma unroll
    for (int half = 0; half < 2; half++) {
        if ((wm >> 1) == half) {
            int obase = (wm & 1) * 64;
#pragma unroll
            for (int mi = 0; mi < 4; mi++)
#pragma unroll
                for (int h = 0; h < 2; h++) {
                    int orow = obase + mi * 16 + lq + 8 * h;
#pragma unroll
                    for (int nj = 0; nj < 4; nj++) {
                        int nn = wn * 32 + nj * 8 + 2 * ln;
                        ybuf[orow * 66 + nn]     = c[mi][nj][h * 2 + 0];
                        ybuf[orow * 66 + nn + 1] = c[mi][nj][h * 2 + 1];
                    }
                }
        }
        __syncthreads();
#pragma unroll
        for (int rr2 = 0; rr2 < 16; rr2++) {
            int orow = wid * 16 + rr2;
            int o = half * 128 + orow;
            size_t ob = (size_t)o * HW_;
            int n0 = 2 * lane;
            out[ob + nbase64[n0]]     = ybuf[orow * 66 + n0];
            out[ob + nbase64[n0 + 1]] = ybuf[orow * 66 + n0 + 1];
        }
        __syncthreads();
    }

    // 8) stage y as bf16 into rbuf[o][n]
#pragma unroll
    for (int nj = 0; nj < 4; nj++) {
        int nn0 = wn * 32 + nj * 8 + 2 * ln;
#pragma unroll
        for (int mi = 0; mi < 4; mi++)
#pragma unroll
            for (int h = 0; h < 2; h++) {
                int o = wm * 64 + mi * 16 + lq + 8 * h;
                __nv_bfloat162 p;
                p.x = __float2bfloat16(c[mi][nj][h * 2 + 0]);
                p.y = __float2bfloat16(c[mi][nj][h * 2 + 1]);
                *(__nv_bfloat162*)(rbuf + o * 66 + nn0) = p;
            }
    }
    __syncthreads();

    // 8b) per-n lfb row compute (coalesced float4 from g_K) + multiply in place
    {
        int n = tid >> 2, chunk = tid & 3;           // 64 o per thread
        int cN = min(cnt[n], 8);
#pragma unroll
        for (int sub = 0; sub < 4; sub++) {          // 16 o per sub-chunk
            float lfb[16];
#pragma unroll
            for (int i = 0; i < 16; i++) lfb[i] = 0.f;
            for (int j = 0; j < cN; j++) {
                const float4* kp = (const float4*)(g_K + widx[n][j] * O_ + chunk * 64 + sub * 16);
#pragma unroll
                for (int q = 0; q < 4; q++) {
                    float4 kv = kp[q];
                    lfb[q * 4 + 0] += kv.x;
                    lfb[q * 4 + 1] += kv.y;
                    lfb[q * 4 + 2] += kv.z;
                    lfb[q * 4 + 3] += kv.w;
                }
            }
#pragma unroll
            for (int i = 0; i < 16; i++) {
                int o = chunk * 64 + sub * 16 + i;
                float l = fminf(fmaxf(lfb[i], -1.f), 1.f);
                __nv_bfloat16* p = rbuf + o * 66 + n;
                *p = __float2bfloat16(l * __bfloat162float(*p));
            }
        }
    }
    __syncthreads();

    // 9) coalesced rT write: warp w -> rows 32w..32w+31 ; lane -> 1 uint (2 n)
#pragma unroll
    for (int rr2 = 0; rr2 < 32; rr2++) {
        int o = wid * 32 + rr2;
        uint32_t v = *(uint32_t*)(rbuf + o * 66 + 2 * lane);
        *(uint32_t*)(g_rTh + (size_t)o * NTOT + nT + 2 * lane) = v;
    }
}

// ------------------------- bf16 tensor-core NT GEMM, split-K ----------------
__device__ __forceinline__ uint32_t sw_off(int row, int kch) {
    return (uint32_t)(row * 128 + ((kch ^ (row & 7)) << 4));
}

template <bool RR>
__global__ void __launch_bounds__(256) k_mma() {
    __shared__ __align__(16) uint8_t As[128 * 128];
    __shared__ __align__(16) uint8_t Bs[128 * 128];

    int mT, nT;
    if (RR) {                                        // 3 lower tiles only
        int ti = blockIdx.x;                         // 0..2
        mT = (ti >= 1) ? 128 : 0;
        nT = (ti == 2) ? 128 : 0;
    } else {
        mT = blockIdx.y * 128;
        nT = 0;
    }

    const __nv_bfloat16* A = g_rTh;
    const __nv_bfloat16* Bm = RR ? g_rTh : g_xunfh;
    float* Cp = RR ? (g_rrP + (size_t)blockIdx.z * (O_ * O_))
                   : (g_rxP + (size_t)blockIdx.z * (O_ * D_));
    const int ldc = RR ? O_ : D_;

    int tid = threadIdx.x;
    int lane = tid & 31, wid = tid >> 5;
    int wm = wid >> 2, wn = wid & 3;                 // warp tile 64(m) x 32(n)
    size_t k0 = (size_t)blockIdx.z * KCHUNK;

    uint32_t sA = (uint32_t)__cvta_generic_to_shared(As);
    uint32_t sB = (uint32_t)__cvta_generic_to_shared(Bs);

    float c[4][4][4];
#pragma unroll
    for (int i = 0; i < 4; i++)
#pragma unroll
        for (int j = 0; j < 4; j++)
#pragma unroll
            for (int q = 0; q < 4; q++) c[i][j][q] = 0.f;

    int lt = lane >> 3, lr = lane & 7;
    int arow = ((lt & 1) << 3) + lr;
    int akch = lt >> 1;

    for (int kk = 0; kk < KCHUNK; kk += 64) {
#pragma unroll
        for (int i = 0; i < 4; i++) {
            int idx = tid + i * 256;
            int row = idx >> 3, ch = idx & 7;
            uint4 v = *(const uint4*)(A + (size_t)(mT + row) * NTOT + k0 + kk + ch * 8);
            *(uint4*)(As + row * 128 + ((ch ^ (row & 7)) << 4)) = v;
        }
#pragma unroll
        for (int i = 0; i < 4; i++) {
            int idx = tid + i * 256;
            int row = idx >> 3, ch = idx & 7;
            int grow = nT + row;
            uint4 v = make_uint4(0u, 0u, 0u, 0u);
            if (RR || grow < D_)
                v = *(const uint4*)(Bm + (size_t)grow * NTOT + k0 + kk + ch * 8);
            *(uint4*)(Bs + row * 128 + ((ch ^ (row & 7)) << 4)) = v;
        }
        __syncthreads();

#pragma unroll
        for (int ks = 0; ks < 4; ks++) {
            int kchb = ks * 2;
            uint32_t af[4][4];
#pragma unroll
            for (int mi = 0; mi < 4; mi++) {
                int row = wm * 64 + mi * 16 + arow;
                LDSM(af[mi][0], af[mi][1], af[mi][2], af[mi][3],
                     sA + sw_off(row, kchb + akch));
            }
            uint32_t bf[2][4];
#pragma unroll
            for (int bj = 0; bj < 2; bj++) {
                int row = wn * 32 + bj * 16 + arow;
                LDSM(bf[bj][0], bf[bj][1], bf[bj][2], bf[bj][3],
                     sB + sw_off(row, kchb + akch));
            }
#pragma unroll
            for (int mi = 0; mi < 4; mi++)
#pragma unroll
                for (int nj = 0; nj < 4; nj++) {
                    int g = nj >> 1, od = nj & 1;
                    MMA16816(c[mi][nj][0], c[mi][nj][1], c[mi][nj][2], c[mi][nj][3],
                             af[mi][0], af[mi][1], af[mi][2], af[mi][3],
                             bf[g][od], bf[g][od + 2]);
                }
        }
        __syncthreads();
    }

#pragma unroll
    for (int mi = 0; mi < 4; mi++) {
        int row0 = mT + wm * 64 + mi * 16 + (lane >> 2);
#pragma unroll
        for (int nj = 0; nj < 4; nj++) {
            int col0 = nT + wn * 32 + nj * 8 + 2 * (lane & 3);
#pragma unroll
            for (int h = 0; h < 2; h++) {
                int r = row0 + h * 8;
                float v0 = c[mi][nj][h * 2 + 0], v1 = c[mi][nj][h * 2 + 1];
                if (RR) {
                    Cp[(size_t)r * ldc + col0] = v0;
                    Cp[(size_t)r * ldc + col0 + 1] = v1;
                } else {
                    if (col0 < D_)     Cp[(size_t)r * ldc + col0] = v0;
                    if (col0 + 1 < D_) Cp[(size_t)r * ldc + col0 + 1] = v1;
                }
            }
        }
    }
}

// ------------------------- deterministic split-K reduce ---------------------
__global__ void k_reduce() {
    int t = blockIdx.x * 256 + threadIdx.x;          // 65536 + 19200 = 84736
    if (t < O_ * O_) {
        float s = 0.f;
        for (int z = 0; z < ZB; z++) s += g_rrP[(size_t)z * (O_ * O_) + t];
        g_rr[t] = s;
    } else if (t < O_ * O_ + O_ * D_) {
        int e = t - O_ * O_;
        float s = 0.f;
        for (int z = 0; z < ZB; z++) s += g_rxP[(size_t)z * (O_ * D_) + e];
        g_rx[e] = s;
    }
}

// ------------------------- weight update ------------------------------------
__global__ void k_update(const float* __restrict__ Wt, float* __restrict__ out) {
    int t = blockIdx.x * 256 + threadIdx.x;
    if (t >= O_ * D_) return;
    int o = t / D_;
    int d = t - o * D_;
    float s = 0.f;
    for (int o2 = 0; o2 <= o; o2++)
        s += g_rr[o * O_ + o2] * Wt[o2 * D_ + d];
    out[YOUT + t] = Wt[t] + 0.01f * ((g_rx[t] - s) * (1.0f / 115200.0f));
}

// ---------------------------------------------------------------------------
extern "C" void kernel_launch(void* const* d_in, const int* in_sizes, int n_in,
                              void* d_out, int out_size) {
    const float* x  = (const float*)d_in[0];
    const float* wt = (const float*)d_in[1];
    float* out = (float*)d_out;

    k_init<<<256, 256>>>(wt);
    k_im2col<<<2048, 128>>>(x);
    k_convfused<<<1800, 256>>>(out);
    k_mma<true ><<<dim3(3, 1, ZB), 256>>>();
    k_mma<false><<<dim3(1, 2, ZB), 256>>>();
    k_reduce<<<332, 256>>>();
    k_update<<<75, 256>>>(wt, out);
}

// round 8
// speedup vs baseline: 3.8916x; 1.1030x over previous
#include <cuda_runtime.h>
#include <cuda_bf16.h>
#include <cstdint>

// ---------------------------------------------------------------------------
// HebbianMap2d: y_out = relu(conv(x,w)); new_w = w + eta*(r^T Xu - tril(r^T r) W)/N
// with r = lfb(winner(relu(s))) * relu(s).
// Shapes: x[32,3,64,64], w[256,3,5,5] -> y_out[32,256,60,60], new_w[256,75]
// ---------------------------------------------------------------------------

#define B_    32
#define C_    3
#define H_    64
#define W_    64
#define HO_   60
#define WO_   60
#define HW_   3600          // 60*60
#define O_    256
#define D_    75            // 3*5*5
#define DP    80            // D padded to multiple of 16
#define NTOT  115200        // 32*3600
#define YOUT  29491200      // 32*256*3600
#define ZB    90            // split-K chunks
#define KCHUNK 1280         // NTOT / ZB (multiple of 64)

// ------------------------- scratch (device globals) ------------------------
__device__ __align__(16) float g_K[O_ * O_];                 // SOM lateral kernel
__device__ __align__(16) __nv_bfloat16 g_Whi[O_ * DP];       // W split-bf16 hi
__device__ __align__(16) __nv_bfloat16 g_Wlo[O_ * DP];       // W split-bf16 lo
__device__ __align__(16) __nv_bfloat16 g_xch[(size_t)NTOT * DP]; // im2col [n][80] hi
__device__ __align__(16) __nv_bfloat16 g_xcl[(size_t)NTOT * DP]; // im2col [n][80] lo
__device__ __align__(16) __nv_bfloat16 g_xunfh[(size_t)D_ * NTOT]; // [d][n] bf16 (rx GEMM)
__device__ __align__(16) __nv_bfloat16 g_rTh[(size_t)O_ * NTOT];   // r^T bf16 [o][n]
__device__ __align__(16) float g_rrP[(size_t)ZB * O_ * O_];  // split-K partials
__device__ __align__(16) float g_rxP[(size_t)ZB * O_ * D_];
__device__ __align__(16) float g_rr[O_ * O_];
__device__ __align__(16) float g_rx[O_ * D_];

// ------------------------- K table + W split prep (merged) ------------------
__global__ void k_init(const float* __restrict__ Wt) {
    int t = blockIdx.x * 256 + threadIdx.x;          // 65536 total
    {   // K table
        int w = t >> 8, o = t & 255;
        int wi = w >> 4, wj = w & 15, i = o >> 4, j = o & 15;
        int a = wi - i + 7, b = wj - j + 7;
        float v = 0.f;
        if (a >= 0 && a < 16 && b >= 0 && b < 16) {
            int da = abs(a - 7), db = abs(b - 7);
            int m = da > db ? da : db;
            v = expf(-(float)(m * m) / 98.0f);
        }
        g_K[t] = v;
    }
    if (t < O_ * DP) {                               // W split-bf16
        int o = t / DP, d = t - o * DP;
        float v = (d < D_) ? Wt[o * D_ + d] : 0.f;
        __nv_bfloat16 hi = __float2bfloat16(v);
        g_Whi[t] = hi;
        g_Wlo[t] = __float2bfloat16(v - __bfloat162float(hi));
    }
}

// ------------------------- tiled im2col (all 3 layouts) ---------------------
__global__ void __launch_bounds__(128) k_im2col(const float* __restrict__ x) {
    __shared__ float xs[3][5][64];
    int b = blockIdx.x >> 6, i = blockIdx.x & 63;    // grid 2048, skip i>=60
    if (i >= HO_) return;
    int tid = threadIdx.x;
    int n0 = b * HW_ + i * WO_;

    for (int idx = tid; idx < 960; idx += 128) {
        int c = idx / 320, rem = idx - c * 320;
        int ki = rem >> 6, col = rem & 63;
        xs[c][ki][col] = x[((b * C_ + c) * H_ + i + ki) * W_ + col];
    }
    __syncthreads();

    // [n][80] hi/lo: unit u = (j, dblk of 8); 600 units
    for (int u = tid; u < 600; u += 128) {
        int j = u / 10, dblk = (u - j * 10) * 8;
        __nv_bfloat16 hibuf[8], lobuf[8];
#pragma unroll
        for (int dd = 0; dd < 8; dd++) {
            int d = dblk + dd;
            float v = 0.f;
            if (d < D_) {
                int c = d / 25, rr = d - c * 25;
                int ki = rr / 5, kj = rr - ki * 5;
                v = xs[c][ki][j + kj];
            }
            __nv_bfloat16 hi = __float2bfloat16(v);
            hibuf[dd] = hi;
            lobuf[dd] = __float2bfloat16(v - __bfloat162float(hi));
        }
        size_t base = (size_t)(n0 + j) * DP + dblk;
        *(uint4*)(g_xch + base) = *(uint4*)hibuf;
        *(uint4*)(g_xcl + base) = *(uint4*)lobuf;
    }

    // [d][n]: unit = (d, jpair); 75*30 = 2250 units
    for (int u = tid; u < 2250; u += 128) {
        int d = u / 30, j = (u - d * 30) * 2;
        int c = d / 25, rr = d - c * 25;
        int ki = rr / 5, kj = rr - ki * 5;
        __nv_bfloat162 p;
        p.x = __float2bfloat16(xs[c][ki][j + kj]);
        p.y = __float2bfloat16(xs[c][ki][j + 1 + kj]);
        *(__nv_bfloat162*)(g_xunfh + (size_t)d * NTOT + n0 + j) = p;
    }
}

// ------------------------- fused conv + winner + lfb + r --------------------
#define LDSM(r0,r1,r2,r3,addr) \
    asm volatile("ldmatrix.sync.aligned.m8n8.x4.shared.b16 {%0,%1,%2,%3}, [%4];" \
                 : "=r"(r0), "=r"(r1), "=r"(r2), "=r"(r3) : "r"(addr))
#define MMA16816(c0,c1,c2,c3,a0,a1,a2,a3,b0,b1) \
    asm volatile("mma.sync.aligned.m16n8k16.row.col.f32.bf16.bf16.f32 " \
                 "{%0,%1,%2,%3}, {%4,%5,%6,%7}, {%8,%9}, {%0,%1,%2,%3};" \
                 : "+f"(c0), "+f"(c1), "+f"(c2), "+f"(c3) \
                 : "r"(a0), "r"(a1), "r"(a2), "r"(a3), "r"(b0), "r"(b1))

// union buffer: mainloop (sW 24KB + sX 6KB) / ybuf 33.8KB / rbuf 33.8KB
#define SMEM_U_BYTES 33792

__global__ void __launch_bounds__(256) k_convfused(float* __restrict__ out) {
    __shared__ __align__(16) uint8_t smem_u[SMEM_U_BYTES];
    __shared__ float pmax[4][64];
    __shared__ float ymx[64];
    __shared__ int   nbase64[64];
    __shared__ int   cnt[64];
    __shared__ int   widx[64][8];

    __nv_bfloat16* sW = (__nv_bfloat16*)smem_u;                 // 512 rows x 24
    __nv_bfloat16* sX = (__nv_bfloat16*)(smem_u + 24576);       // 128 rows x 24
    float*         ybuf = (float*)smem_u;                       // 128 rows x 66
    __nv_bfloat16* rbuf = (__nv_bfloat16*)smem_u;               // 256 rows x 66

    int tid = threadIdx.x, lane = tid & 31, wid = tid >> 5;
    int wm = wid >> 1, wn = wid & 1;
    int nT = blockIdx.x * 64;

    uint32_t sWb = (uint32_t)__cvta_generic_to_shared(sW);
    uint32_t sXb = (uint32_t)__cvta_generic_to_shared(sX);

    int lt = lane >> 3, lr = lane & 7;
    int arow = ((lt & 1) << 3) + lr;
    int akch = lt >> 1;

    float c[4][4][4];
#pragma unroll
    for (int i = 0; i < 4; i++)
#pragma unroll
        for (int j = 0; j < 4; j++)
#pragma unroll
            for (int q = 0; q < 4; q++) c[i][j][q] = 0.f;

    int xpiece = tid & 1, xhl = (tid >> 1) & 1, xrow = tid >> 2;

    uint4 wreg[4];
    uint4 xreg;

    // ---- prologue: load stage 0 ----
#pragma unroll
    for (int i = 0; i < 4; i++) {
        int idx = tid + i * 256;
        int row = idx >> 2;
        const __nv_bfloat16* src = ((idx >> 1) & 1) ? g_Wlo : g_Whi;
        wreg[i] = *(const uint4*)(src + row * DP + (idx & 1) * 8);
    }
    {
        const __nv_bfloat16* src = xhl ? g_xcl : g_xch;
        xreg = *(const uint4*)(src + (size_t)(nT + xrow) * DP + xpiece * 8);
    }
#pragma unroll
    for (int i = 0; i < 4; i++) {
        int idx = tid + i * 256;
        int row = idx >> 2;
        *(uint4*)(sW + (((idx >> 1) & 1) * 256 + row) * 24 + (idx & 1) * 8) = wreg[i];
    }
    *(uint4*)(sX + (xhl * 64 + xrow) * 24 + xpiece * 8) = xreg;
    __syncthreads();

    for (int s = 0; s < 5; s++) {
        if (s < 4) {
#pragma unroll
            for (int i = 0; i < 4; i++) {
                int idx = tid + i * 256;
                int row = idx >> 2;
                const __nv_bfloat16* src = ((idx >> 1) & 1) ? g_Wlo : g_Whi;
                wreg[i] = *(const uint4*)(src + row * DP + (s + 1) * 16 + (idx & 1) * 8);
            }
            const __nv_bfloat16* src = xhl ? g_xcl : g_xch;
            xreg = *(const uint4*)(src + (size_t)(nT + xrow) * DP + (s + 1) * 16 + xpiece * 8);
        }

        uint32_t ah[4][4], al[4][4], bh[2][4], bl[2][4];
#pragma unroll
        for (int mi = 0; mi < 4; mi++) {
            int row = wm * 64 + mi * 16 + arow;
            LDSM(ah[mi][0], ah[mi][1], ah[mi][2], ah[mi][3], sWb + row * 48 + akch * 16);
            LDSM(al[mi][0], al[mi][1], al[mi][2], al[mi][3], sWb + (256 + row) * 48 + akch * 16);
        }
#pragma unroll
        for (int bj = 0; bj < 2; bj++) {
            int row = wn * 32 + bj * 16 + arow;
            LDSM(bh[bj][0], bh[bj][1], bh[bj][2], bh[bj][3], sXb + row * 48 + akch * 16);
            LDSM(bl[bj][0], bl[bj][1], bl[bj][2], bl[bj][3], sXb + (64 + row) * 48 + akch * 16);
        }
#pragma unroll
        for (int mi = 0; mi < 4; mi++)
#pragma unroll
            for (int nj = 0; nj < 4; nj++) {
                int g = nj >> 1, od = nj & 1;
                MMA16816(c[mi][nj][0], c[mi][nj][1], c[mi][nj][2], c[mi][nj][3],
                         ah[mi][0], ah[mi][1], ah[mi][2], ah[mi][3],
                         bh[g][od], bh[g][od + 2]);
                MMA16816(c[mi][nj][0], c[mi][nj][1], c[mi][nj][2], c[mi][nj][3],
                         ah[mi][0], ah[mi][1], ah[mi][2], ah[mi][3],
                         bl[g][od], bl[g][od + 2]);
                MMA16816(c[mi][nj][0], c[mi][nj][1], c[mi][nj][2], c[mi][nj][3],
                         al[mi][0], al[mi][1], al[mi][2], al[mi][3],
                         bh[g][od], bh[g][od + 2]);
            }
        __syncthreads();
        if (s < 4) {
#pragma unroll
            for (int i = 0; i < 4; i++) {
                int idx = tid + i * 256;
                int row = idx >> 2;
                *(uint4*)(sW + (((idx >> 1) & 1) * 256 + row) * 24 + (idx & 1) * 8) = wreg[i];
            }
            *(uint4*)(sX + (xhl * 64 + xrow) * 24 + xpiece * 8) = xreg;
            __syncthreads();
        }
    }

    // ---------------- epilogue ----------------
    int lq = lane >> 2, ln = lane & 3;

    float tmax[4][2];
#pragma unroll
    for (int nj = 0; nj < 4; nj++)
#pragma unroll
        for (int q = 0; q < 2; q++) tmax[nj][q] = 0.f;
#pragma unroll
    for (int mi = 0; mi < 4; mi++)
#pragma unroll
        for (int nj = 0; nj < 4; nj++)
#pragma unroll
            for (int q = 0; q < 4; q++) {
                float y = fmaxf(c[mi][nj][q], 0.f);
                c[mi][nj][q] = y;
                tmax[nj][q & 1] = fmaxf(tmax[nj][q & 1], y);
            }

#pragma unroll
    for (int nj = 0; nj < 4; nj++)
#pragma unroll
        for (int q = 0; q < 2; q++) {
            float m = tmax[nj][q];
            m = fmaxf(m, __shfl_xor_sync(0xffffffffu, m, 4));
            m = fmaxf(m, __shfl_xor_sync(0xffffffffu, m, 8));
            m = fmaxf(m, __shfl_xor_sync(0xffffffffu, m, 16));
            if (lq == 0) pmax[wm][wn * 32 + nj * 8 + 2 * ln + q] = m;
        }
    if (tid < 64) {
        int n = nT + tid;
        int b = n / HW_;
        nbase64[tid] = b * (O_ * HW_) + (n - b * HW_);
    }
    __syncthreads();

    if (tid < 64) {
        ymx[tid] = fmaxf(fmaxf(pmax[0][tid], pmax[1][tid]),
                         fmaxf(pmax[2][tid], pmax[3][tid]));
        cnt[tid] = 0;
    }
    __syncthreads();

#pragma unroll
    for (int mi = 0; mi < 4; mi++)
#pragma unroll
        for (int h = 0; h < 2; h++) {
            int o = wm * 64 + mi * 16 + lq + 8 * h;
#pragma unroll
            for (int nj = 0; nj < 4; nj++)
#pragma unroll
                for (int q = 0; q < 2; q++) {
                    int nn = wn * 32 + nj * 8 + 2 * ln + q;
                    float ym = ymx[nn];
                    if (ym > 0.f && c[mi][nj][h * 2 + q] == ym) {
                        int pos = atomicAdd(&cnt[nn], 1);
                        if (pos < 8) widx[nn][pos] = o;
                    }
                }
        }
    __syncthreads();

#pragma unroll
    for (int half = 0; half < 2; half++) {
        if ((wm >> 1) == half) {
            int obase = (wm & 1) * 64;
#pragma unroll
            for (int mi = 0; mi < 4; mi++)
#pragma unroll
                for (int h = 0; h < 2; h++) {
                    int orow = obase + mi * 16 + lq + 8 * h;
#pragma unroll
                    for (int nj = 0; nj < 4; nj++) {
                        int nn = wn * 32 + nj * 8 + 2 * ln;
                        ybuf[orow * 66 + nn]     = c[mi][nj][h * 2 + 0];
                        ybuf[orow * 66 + nn + 1] = c[mi][nj][h * 2 + 1];
                    }
                }
        }
        __syncthreads();
#pragma unroll
        for (int rr2 = 0; rr2 < 16; rr2++) {
            int orow = wid * 16 + rr2;
            int o = half * 128 + orow;
            size_t ob = (size_t)o * HW_;
            int n0 = 2 * lane;
            out[ob + nbase64[n0]]     = ybuf[orow * 66 + n0];
            out[ob + nbase64[n0 + 1]] = ybuf[orow * 66 + n0 + 1];
        }
        __syncthreads();
    }

    // stage y as bf16 into rbuf[o][n]
#pragma unroll
    for (int nj = 0; nj < 4; nj++) {
        int nn0 = wn * 32 + nj * 8 + 2 * ln;
#pragma unroll
        for (int mi = 0; mi < 4; mi++)
#pragma unroll
            for (int h = 0; h < 2; h++) {
                int o = wm * 64 + mi * 16 + lq + 8 * h;
                __nv_bfloat162 p;
                p.x = __float2bfloat16(c[mi][nj][h * 2 + 0]);
                p.y = __float2bfloat16(c[mi][nj][h * 2 + 1]);
                *(__nv_bfloat162*)(rbuf + o * 66 + nn0) = p;
            }
    }
    __syncthreads();

    // per-n lfb row compute (coalesced float4 from g_K) + multiply in place
    {
        int n = tid >> 2, chunk = tid & 3;           // 64 o per thread
        int cN = min(cnt[n], 8);
#pragma unroll
        for (int sub = 0; sub < 4; sub++) {          // 16 o per sub-chunk
            float lfb[16];
#pragma unroll
            for (int i = 0; i < 16; i++) lfb[i] = 0.f;
            for (int j = 0; j < cN; j++) {
                const float4* kp = (const float4*)(g_K + widx[n][j] * O_ + chunk * 64 + sub * 16);
#pragma unroll
                for (int q = 0; q < 4; q++) {
                    float4 kv = kp[q];
                    lfb[q * 4 + 0] += kv.x;
                    lfb[q * 4 + 1] += kv.y;
                    lfb[q * 4 + 2] += kv.z;
                    lfb[q * 4 + 3] += kv.w;
                }
            }
#pragma unroll
            for (int i = 0; i < 16; i++) {
                int o = chunk * 64 + sub * 16 + i;
                float l = fminf(fmaxf(lfb[i], -1.f), 1.f);
                __nv_bfloat16* p = rbuf + o * 66 + n;
                *p = __float2bfloat16(l * __bfloat162float(*p));
            }
        }
    }
    __syncthreads();

    // coalesced rT write
#pragma unroll
    for (int rr2 = 0; rr2 < 32; rr2++) {
        int o = wid * 32 + rr2;
        uint32_t v = *(uint32_t*)(rbuf + o * 66 + 2 * lane);
        *(uint32_t*)(g_rTh + (size_t)o * NTOT + nT + 2 * lane) = v;
    }
}

// ------------- merged rr+rx split-K GEMM (z-major, diag dedup) --------------
// Tiles: 0:(rr 0,0 diag) 1:(rr 1,0) 2:(rr 1,1 diag) 3:(rx m=0) 4:(rx m=1)
__device__ __forceinline__ uint32_t sw_off(int row, int kch) {
    return (uint32_t)(row * 128 + ((kch ^ (row & 7)) << 4));
}

__global__ void __launch_bounds__(256) k_mma2() {
    __shared__ __align__(16) uint8_t As[128 * 128];
    __shared__ __align__(16) uint8_t Bs[128 * 128];

    int t = blockIdx.x;                              // 0..4
    int z = blockIdx.y;                              // 0..ZB-1
    int  mT   = (t == 1 || t == 2 || t == 4) ? 128 : 0;
    bool isRx = (t >= 3);
    bool diag = (t == 0 || t == 2);
    int  nT   = (t == 2) ? 128 : 0;                  // rr col-tile offset

    const __nv_bfloat16* A = g_rTh;
    const __nv_bfloat16* Bm = isRx ? g_xunfh : g_rTh;
    float* Cp  = isRx ? (g_rxP + (size_t)z * (O_ * D_))
                      : (g_rrP + (size_t)z * (O_ * O_));
    const int ldc = isRx ? D_ : O_;

    int tid = threadIdx.x;
    int lane = tid & 31, wid = tid >> 5;
    int wm = wid >> 2, wn = wid & 3;                 // warp tile 64(m) x 32(n)
    size_t k0 = (size_t)z * KCHUNK;

    uint32_t sA = (uint32_t)__cvta_generic_to_shared(As);
    uint32_t sB = diag ? sA : (uint32_t)__cvta_generic_to_shared(Bs);

    float c[4][4][4];
#pragma unroll
    for (int i = 0; i < 4; i++)
#pragma unroll
        for (int j = 0; j < 4; j++)
#pragma unroll
            for (int q = 0; q < 4; q++) c[i][j][q] = 0.f;

    int lt = lane >> 3, lr = lane & 7;
    int arow = ((lt & 1) << 3) + lr;
    int akch = lt >> 1;

    for (int kk = 0; kk < KCHUNK; kk += 64) {
#pragma unroll
        for (int i = 0; i < 4; i++) {
            int idx = tid + i * 256;
            int row = idx >> 3, ch = idx & 7;
            uint4 v = *(const uint4*)(A + (size_t)(mT + row) * NTOT + k0 + kk + ch * 8);
            *(uint4*)(As + row * 128 + ((ch ^ (row & 7)) << 4)) = v;
        }
        if (!diag) {
#pragma unroll
            for (int i = 0; i < 4; i++) {
                int idx = tid + i * 256;
                int row = idx >> 3, ch = idx & 7;
                int grow = nT + row;
                uint4 v = make_uint4(0u, 0u, 0u, 0u);
                if (!isRx || row < D_)
                    v = *(const uint4*)(Bm + (size_t)(isRx ? row : grow) * NTOT + k0 + kk + ch * 8);
                *(uint4*)(Bs + row * 128 + ((ch ^ (row & 7)) << 4)) = v;
            }
        }
        __syncthreads();

#pragma unroll
        for (int ks = 0; ks < 4; ks++) {
            int kchb = ks * 2;
            uint32_t af[4][4];
#pragma unroll
            for (int mi = 0; mi < 4; mi++) {
                int row = wm * 64 + mi * 16 + arow;
                LDSM(af[mi][0], af[mi][1], af[mi][2], af[mi][3],
                     sA + sw_off(row, kchb + akch));
            }
            uint32_t bf[2][4];
#pragma unroll
            for (int bj = 0; bj < 2; bj++) {
                int row = wn * 32 + bj * 16 + arow;
                LDSM(bf[bj][0], bf[bj][1], bf[bj][2], bf[bj][3],
                     sB + sw_off(row, kchb + akch));
            }
#pragma unroll
            for (int mi = 0; mi < 4; mi++)
#pragma unroll
                for (int nj = 0; nj < 4; nj++) {
                    int g = nj >> 1, od = nj & 1;
                    MMA16816(c[mi][nj][0], c[mi][nj][1], c[mi][nj][2], c[mi][nj][3],
                             af[mi][0], af[mi][1], af[mi][2], af[mi][3],
                             bf[g][od], bf[g][od + 2]);
                }
        }
        __syncthreads();
    }

#pragma unroll
    for (int mi = 0; mi < 4; mi++) {
        int row0 = mT + wm * 64 + mi * 16 + (lane >> 2);
#pragma unroll
        for (int nj = 0; nj < 4; nj++) {
            int col0 = nT + wn * 32 + nj * 8 + 2 * (lane & 3);
#pragma unroll
            for (int h = 0; h < 2; h++) {
                int r = row0 + h * 8;
                float v0 = c[mi][nj][h * 2 + 0], v1 = c[mi][nj][h * 2 + 1];
                if (!isRx) {
                    Cp[(size_t)r * ldc + col0] = v0;
                    Cp[(size_t)r * ldc + col0 + 1] = v1;
                } else {
                    if (col0 < D_)     Cp[(size_t)r * ldc + col0] = v0;
                    if (col0 + 1 < D_) Cp[(size_t)r * ldc + col0 + 1] = v1;
                }
            }
        }
    }
}

// ------------------------- deterministic split-K reduce ---------------------
__global__ void k_reduce() {
    int t = blockIdx.x * 256 + threadIdx.x;          // 65536 + 19200 = 84736
    if (t < O_ * O_) {
        float s = 0.f;
        for (int z = 0; z < ZB; z++) s += g_rrP[(size_t)z * (O_ * O_) + t];
        g_rr[t] = s;
    } else if (t < O_ * O_ + O_ * D_) {
        int e = t - O_ * O_;
        float s = 0.f;
        for (int z = 0; z < ZB; z++) s += g_rxP[(size_t)z * (O_ * D_) + e];
        g_rx[e] = s;
    }
}

// ------------------------- weight update ------------------------------------
__global__ void k_update(const float* __restrict__ Wt, float* __restrict__ out) {
    int t = blockIdx.x * 256 + threadIdx.x;
    if (t >= O_ * D_) return;
    int o = t / D_;
    int d = t - o * D_;
    float s = 0.f;
    for (int o2 = 0; o2 <= o; o2++)
        s += g_rr[o * O_ + o2] * Wt[o2 * D_ + d];
    out[YOUT + t] = Wt[t] + 0.01f * ((g_rx[t] - s) * (1.0f / 115200.0f));
}

// ---------------------------------------------------------------------------
extern "C" void kernel_launch(void* const* d_in, const int* in_sizes, int n_in,
                              void* d_out, int out_size) {
    const float* x  = (const float*)d_in[0];
    const float* wt = (const float*)d_in[1];
    float* out = (float*)d_out;

    k_init<<<256, 256>>>(wt);
    k_im2col<<<2048, 128>>>(x);
    k_convfused<<<1800, 256>>>(out);
    k_mma2<<<dim3(5, ZB), 256>>>();
    k_reduce<<<332, 256>>>();
    k_update<<<75, 256>>>(wt, out);
}

// round 9
// speedup vs baseline: 4.1940x; 1.0777x over previous
#include <cuda_runtime.h>
#include <cuda_bf16.h>
#include <cstdint>

// ---------------------------------------------------------------------------
// HebbianMap2d: y_out = relu(conv(x,w)); new_w = w + eta*(r^T Xu - tril(r^T r) W)/N
// with r = lfb(winner(relu(s))) * relu(s).
// Shapes: x[32,3,64,64], w[256,3,5,5] -> y_out[32,256,60,60], new_w[256,75]
// ---------------------------------------------------------------------------

#define B_    32
#define C_    3
#define H_    64
#define W_    64
#define HO_   60
#define WO_   60
#define HW_   3600          // 60*60
#define O_    256
#define D_    75            // 3*5*5
#define DP    80            // D padded to multiple of 16
#define NTOT  115200        // 32*3600
#define YOUT  29491200      // 32*256*3600
#define ZB    50            // split-K chunks
#define KCHUNK 2304         // NTOT / ZB (multiple of 64)
#define NK    36            // KCHUNK / 64

// ------------------------- scratch (device globals) ------------------------
__device__ __align__(16) float g_K[O_ * O_];                 // SOM lateral kernel
__device__ __align__(16) __nv_bfloat16 g_Whi[O_ * DP];       // W split-bf16 hi
__device__ __align__(16) __nv_bfloat16 g_Wlo[O_ * DP];       // W split-bf16 lo
__device__ __align__(16) __nv_bfloat16 g_xch[(size_t)NTOT * DP]; // im2col [n][80] hi
__device__ __align__(16) __nv_bfloat16 g_xcl[(size_t)NTOT * DP]; // im2col [n][80] lo
__device__ __align__(16) __nv_bfloat16 g_xunfh[(size_t)D_ * NTOT]; // [d][n] bf16 (rx GEMM)
__device__ __align__(16) __nv_bfloat16 g_rTh[(size_t)O_ * NTOT];   // r^T bf16 [o][n]
__device__ __align__(16) float g_rrP[(size_t)ZB * O_ * O_];  // split-K partials
__device__ __align__(16) float g_rxP[(size_t)ZB * O_ * D_];
__device__ __align__(16) float g_rr[O_ * O_];
__device__ __align__(16) float g_rx[O_ * D_];

// ------------------------- K table + W split prep (merged) ------------------
__global__ void k_init(const float* __restrict__ Wt) {
    int t = blockIdx.x * 256 + threadIdx.x;          // 65536 total
    {   // K table
        int w = t >> 8, o = t & 255;
        int wi = w >> 4, wj = w & 15, i = o >> 4, j = o & 15;
        int a = wi - i + 7, b = wj - j + 7;
        float v = 0.f;
        if (a >= 0 && a < 16 && b >= 0 && b < 16) {
            int da = abs(a - 7), db = abs(b - 7);
            int m = da > db ? da : db;
            v = expf(-(float)(m * m) / 98.0f);
        }
        g_K[t] = v;
    }
    if (t < O_ * DP) {                               // W split-bf16
        int o = t / DP, d = t - o * DP;
        float v = (d < D_) ? Wt[o * D_ + d] : 0.f;
        __nv_bfloat16 hi = __float2bfloat16(v);
        g_Whi[t] = hi;
        g_Wlo[t] = __float2bfloat16(v - __bfloat162float(hi));
    }
}

// ------------------------- tiled im2col (all 3 layouts) ---------------------
__global__ void __launch_bounds__(128) k_im2col(const float* __restrict__ x) {
    __shared__ float xs[3][5][64];
    int b = blockIdx.x >> 6, i = blockIdx.x & 63;    // grid 2048, skip i>=60
    if (i >= HO_) return;
    int tid = threadIdx.x;
    int n0 = b * HW_ + i * WO_;

    for (int idx = tid; idx < 960; idx += 128) {
        int c = idx / 320, rem = idx - c * 320;
        int ki = rem >> 6, col = rem & 63;
        xs[c][ki][col] = x[((b * C_ + c) * H_ + i + ki) * W_ + col];
    }
    __syncthreads();

    for (int u = tid; u < 600; u += 128) {
        int j = u / 10, dblk = (u - j * 10) * 8;
        __nv_bfloat16 hibuf[8], lobuf[8];
#pragma unroll
        for (int dd = 0; dd < 8; dd++) {
            int d = dblk + dd;
            float v = 0.f;
            if (d < D_) {
                int c = d / 25, rr = d - c * 25;
                int ki = rr / 5, kj = rr - ki * 5;
                v = xs[c][ki][j + kj];
            }
            __nv_bfloat16 hi = __float2bfloat16(v);
            hibuf[dd] = hi;
            lobuf[dd] = __float2bfloat16(v - __bfloat162float(hi));
        }
        size_t base = (size_t)(n0 + j) * DP + dblk;
        *(uint4*)(g_xch + base) = *(uint4*)hibuf;
        *(uint4*)(g_xcl + base) = *(uint4*)lobuf;
    }

    for (int u = tid; u < 2250; u += 128) {
        int d = u / 30, j = (u - d * 30) * 2;
        int c = d / 25, rr = d - c * 25;
        int ki = rr / 5, kj = rr - ki * 5;
        __nv_bfloat162 p;
        p.x = __float2bfloat16(xs[c][ki][j + kj]);
        p.y = __float2bfloat16(xs[c][ki][j + 1 + kj]);
        *(__nv_bfloat162*)(g_xunfh + (size_t)d * NTOT + n0 + j) = p;
    }
}

// ------------------------- fused conv + winner + lfb + r --------------------
#define LDSM(r0,r1,r2,r3,addr) \
    asm volatile("ldmatrix.sync.aligned.m8n8.x4.shared.b16 {%0,%1,%2,%3}, [%4];" \
                 : "=r"(r0), "=r"(r1), "=r"(r2), "=r"(r3) : "r"(addr))
#define MMA16816(c0,c1,c2,c3,a0,a1,a2,a3,b0,b1) \
    asm volatile("mma.sync.aligned.m16n8k16.row.col.f32.bf16.bf16.f32 " \
                 "{%0,%1,%2,%3}, {%4,%5,%6,%7}, {%8,%9}, {%0,%1,%2,%3};" \
                 : "+f"(c0), "+f"(c1), "+f"(c2), "+f"(c3) \
                 : "r"(a0), "r"(a1), "r"(a2), "r"(a3), "r"(b0), "r"(b1))

#define SMEM_U_BYTES 33792

__global__ void __launch_bounds__(256) k_convfused(float* __restrict__ out) {
    __shared__ __align__(16) uint8_t smem_u[SMEM_U_BYTES];
    __shared__ float pmax[4][64];
    __shared__ float ymx[64];
    __shared__ int   nbase64[64];
    __shared__ int   cnt[64];
    __shared__ int   widx[64][8];

    __nv_bfloat16* sW = (__nv_bfloat16*)smem_u;                 // 512 rows x 24
    __nv_bfloat16* sX = (__nv_bfloat16*)(smem_u + 24576);       // 128 rows x 24
    float*         ybuf = (float*)smem_u;                       // 128 rows x 66
    __nv_bfloat16* rbuf = (__nv_bfloat16*)smem_u;               // 256 rows x 66

    int tid = threadIdx.x, lane = tid & 31, wid = tid >> 5;
    int wm = wid >> 1, wn = wid & 1;
    int nT = blockIdx.x * 64;

    uint32_t sWb = (uint32_t)__cvta_generic_to_shared(sW);
    uint32_t sXb = (uint32_t)__cvta_generic_to_shared(sX);

    int lt = lane >> 3, lr = lane & 7;
    int arow = ((lt & 1) << 3) + lr;
    int akch = lt >> 1;

    float c[4][4][4];
#pragma unroll
    for (int i = 0; i < 4; i++)
#pragma unroll
        for (int j = 0; j < 4; j++)
#pragma unroll
            for (int q = 0; q < 4; q++) c[i][j][q] = 0.f;

    int xpiece = tid & 1, xhl = (tid >> 1) & 1, xrow = tid >> 2;

    uint4 wreg[4];
    uint4 xreg;

#pragma unroll
    for (int i = 0; i < 4; i++) {
        int idx = tid + i * 256;
        int row = idx >> 2;
        const __nv_bfloat16* src = ((idx >> 1) & 1) ? g_Wlo : g_Whi;
        wreg[i] = *(const uint4*)(src + row * DP + (idx & 1) * 8);
    }
    {
        const __nv_bfloat16* src = xhl ? g_xcl : g_xch;
        xreg = *(const uint4*)(src + (size_t)(nT + xrow) * DP + xpiece * 8);
    }
#pragma unroll
    for (int i = 0; i < 4; i++) {
        int idx = tid + i * 256;
        int row = idx >> 2;
        *(uint4*)(sW + (((idx >> 1) & 1) * 256 + row) * 24 + (idx & 1) * 8) = wreg[i];
    }
    *(uint4*)(sX + (xhl * 64 + xrow) * 24 + xpiece * 8) = xreg;
    __syncthreads();

    for (int s = 0; s < 5; s++) {
        if (s < 4) {
#pragma unroll
            for (int i = 0; i < 4; i++) {
                int idx = tid + i * 256;
                int row = idx >> 2;
                const __nv_bfloat16* src = ((idx >> 1) & 1) ? g_Wlo : g_Whi;
                wreg[i] = *(const uint4*)(src + row * DP + (s + 1) * 16 + (idx & 1) * 8);
            }
            const __nv_bfloat16* src = xhl ? g_xcl : g_xch;
            xreg = *(const uint4*)(src + (size_t)(nT + xrow) * DP + (s + 1) * 16 + xpiece * 8);
        }

        uint32_t ah[4][4], al[4][4], bh[2][4], bl[2][4];
#pragma unroll
        for (int mi = 0; mi < 4; mi++) {
            int row = wm * 64 + mi * 16 + arow;
            LDSM(ah[mi][0], ah[mi][1], ah[mi][2], ah[mi][3], sWb + row * 48 + akch * 16);
            LDSM(al[mi][0], al[mi][1], al[mi][2], al[mi][3], sWb + (256 + row) * 48 + akch * 16);
        }
#pragma unroll
        for (int bj = 0; bj < 2; bj++) {
            int row = wn * 32 + bj * 16 + arow;
            LDSM(bh[bj][0], bh[bj][1], bh[bj][2], bh[bj][3], sXb + row * 48 + akch * 16);
            LDSM(bl[bj][0], bl[bj][1], bl[bj][2], bl[bj][3], sXb + (64 + row) * 48 + akch * 16);
        }
#pragma unroll
        for (int mi = 0; mi < 4; mi++)
#pragma unroll
            for (int nj = 0; nj < 4; nj++) {
                int g = nj >> 1, od = nj & 1;
                MMA16816(c[mi][nj][0], c[mi][nj][1], c[mi][nj][2], c[mi][nj][3],
                         ah[mi][0], ah[mi][1], ah[mi][2], ah[mi][3],
                         bh[g][od], bh[g][od + 2]);
                MMA16816(c[mi][nj][0], c[mi][nj][1], c[mi][nj][2], c[mi][nj][3],
                         ah[mi][0], ah[mi][1], ah[mi][2], ah[mi][3],
                         bl[g][od], bl[g][od + 2]);
                MMA16816(c[mi][nj][0], c[mi][nj][1], c[mi][nj][2], c[mi][nj][3],
                         al[mi][0], al[mi][1], al[mi][2], al[mi][3],
                         bh[g][od], bh[g][od + 2]);
            }
        __syncthreads();
        if (s < 4) {
#pragma unroll
            for (int i = 0; i < 4; i++) {
                int idx = tid + i * 256;
                int row = idx >> 2;
                *(uint4*)(sW + (((idx >> 1) & 1) * 256 + row) * 24 + (idx & 1) * 8) = wreg[i];
            }
            *(uint4*)(sX + (xhl * 64 + xrow) * 24 + xpiece * 8) = xreg;
            __syncthreads();
        }
    }

    // ---------------- epilogue ----------------
    int lq = lane >> 2, ln = lane & 3;

    float tmax[4][2];
#pragma unroll
    for (int nj = 0; nj < 4; nj++)
#pragma unroll
        for (int q = 0; q < 2; q++) tmax[nj][q] = 0.f;
#pragma unroll
    for (int mi = 0; mi < 4; mi++)
#pragma unroll
        for (int nj = 0; nj < 4; nj++)
#pragma unroll
            for (int q = 0; q < 4; q++) {
                float y = fmaxf(c[mi][nj][q], 0.f);
                c[mi][nj][q] = y;
                tmax[nj][q & 1] = fmaxf(tmax[nj][q & 1], y);
            }

#pragma unroll
    for (int nj = 0; nj < 4; nj++)
#pragma unroll
        for (int q = 0; q < 2; q++) {
            float m = tmax[nj][q];
            m = fmaxf(m, __shfl_xor_sync(0xffffffffu, m, 4));
            m = fmaxf(m, __shfl_xor_sync(0xffffffffu, m, 8));
            m = fmaxf(m, __shfl_xor_sync(0xffffffffu, m, 16));
            if (lq == 0) pmax[wm][wn * 32 + nj * 8 + 2 * ln + q] = m;
        }
    if (tid < 64) {
        int n = nT + tid;
        int b = n / HW_;
        nbase64[tid] = b * (O_ * HW_) + (n - b * HW_);
    }
    __syncthreads();

    if (tid < 64) {
        ymx[tid] = fmaxf(fmaxf(pmax[0][tid], pmax[1][tid]),
                         fmaxf(pmax[2][tid], pmax[3][tid]));
        cnt[tid] = 0;
    }
    __syncthreads();

#pragma unroll
    for (int mi = 0; mi < 4; mi++)
#pragma unroll
        for (int h = 0; h < 2; h++) {
            int o = wm * 64 + mi * 16 + lq + 8 * h;
#pragma unroll
            for (int nj = 0; nj < 4; nj++)
#pragma unroll
                for (int q = 0; q < 2; q++) {
                    int nn = wn * 32 + nj * 8 + 2 * ln + q;
                    float ym = ymx[nn];
                    if (ym > 0.f && c[mi][nj][h * 2 + q] == ym) {
                        int pos = atomicAdd(&cnt[nn], 1);
                        if (pos < 8) widx[nn][pos] = o;
                    }
                }
        }
    __syncthreads();

#pragma unroll
    for (int half = 0; half < 2; half++) {
        if ((wm >> 1) == half) {
            int obase = (wm & 1) * 64;
#pragma unroll
            for (int mi = 0; mi < 4; mi++)
#pragma unroll
                for (int h = 0; h < 2; h++) {
                    int orow = obase + mi * 16 + lq + 8 * h;
#pragma unroll
                    for (int nj = 0; nj < 4; nj++) {
                        int nn = wn * 32 + nj * 8 + 2 * ln;
                        ybuf[orow * 66 + nn]     = c[mi][nj][h * 2 + 0];
                        ybuf[orow * 66 + nn + 1] = c[mi][nj][h * 2 + 1];
                    }
                }
        }
        __syncthreads();
#pragma unroll
        for (int rr2 = 0; rr2 < 16; rr2++) {
            int orow = wid * 16 + rr2;
            int o = half * 128 + orow;
            size_t ob = (size_t)o * HW_;
            int n0 = 2 * lane;
            out[ob + nbase64[n0]]     = ybuf[orow * 66 + n0];
            out[ob + nbase64[n0 + 1]] = ybuf[orow * 66 + n0 + 1];
        }
        __syncthreads();
    }

#pragma unroll
    for (int nj = 0; nj < 4; nj++) {
        int nn0 = wn * 32 + nj * 8 + 2 * ln;
#pragma unroll
        for (int mi = 0; mi < 4; mi++)
#pragma unroll
            for (int h = 0; h < 2; h++) {
                int o = wm * 64 + mi * 16 + lq + 8 * h;
                __nv_bfloat162 p;
                p.x = __float2bfloat16(c[mi][nj][h * 2 + 0]);
                p.y = __float2bfloat16(c[mi][nj][h * 2 + 1]);
                *(__nv_bfloat162*)(rbuf + o * 66 + nn0) = p;
            }
    }
    __syncthreads();

    {
        int n = tid >> 2, chunk = tid & 3;           // 64 o per thread
        int cN = min(cnt[n], 8);
#pragma unroll
        for (int sub = 0; sub < 4; sub++) {
            float lfb[16];
#pragma unroll
            for (int i = 0; i < 16; i++) lfb[i] = 0.f;
            for (int j = 0; j < cN; j++) {
                const float4* kp = (const float4*)(g_K + widx[n][j] * O_ + chunk * 64 + sub * 16);
#pragma unroll
                for (int q = 0; q < 4; q++) {
                    float4 kv = kp[q];
                    lfb[q * 4 + 0] += kv.x;
                    lfb[q * 4 + 1] += kv.y;
                    lfb[q * 4 + 2] += kv.z;
                    lfb[q * 4 + 3] += kv.w;
                }
            }
#pragma unroll
            for (int i = 0; i < 16; i++) {
                int o = chunk * 64 + sub * 16 + i;
                float l = fminf(fmaxf(lfb[i], -1.f), 1.f);
                __nv_bfloat16* p = rbuf + o * 66 + n;
                *p = __float2bfloat16(l * __bfloat162float(*p));
            }
        }
    }
    __syncthreads();

#pragma unroll
    for (int rr2 = 0; rr2 < 32; rr2++) {
        int o = wid * 32 + rr2;
        uint32_t v = *(uint32_t*)(rbuf + o * 66 + 2 * lane);
        *(uint32_t*)(g_rTh + (size_t)o * NTOT + nT + 2 * lane) = v;
    }
}

// ------------- merged rr+rx split-K GEMM: 3-stage cp.async pipeline ---------
// Tiles: 0:(rr 0,0 diag) 1:(rr 1,0) 2:(rr 1,1 diag) 3:(rx m=0) 4:(rx m=1)
// dyn smem: 3 stages x (A 16KB + B 16KB) = 96KB
#define CP16(dst, src) \
    asm volatile("cp.async.cg.shared.global [%0], [%1], 16;" :: "r"(dst), "l"(src))
#define CP16Z(dst, src, ss) \
    asm volatile("cp.async.cg.shared.global [%0], [%1], 16, %2;" :: "r"(dst), "l"(src), "r"(ss))
#define CPCOMMIT() asm volatile("cp.async.commit_group;")
#define CPWAIT2()  asm volatile("cp.async.wait_group 2;")

__device__ __forceinline__ uint32_t sw_off(int row, int kch) {
    return (uint32_t)(row * 128 + ((kch ^ (row & 7)) << 4));
}

__global__ void __launch_bounds__(256) k_mma2() {
    extern __shared__ __align__(16) uint8_t dynsm[];

    int t = blockIdx.x;                              // 0..4
    int z = blockIdx.y;                              // 0..ZB-1
    int  mT   = (t == 1 || t == 2 || t == 4) ? 128 : 0;
    bool isRx = (t >= 3);
    bool diag = (t == 0 || t == 2);
    int  nT   = (t == 2) ? 128 : 0;

    const __nv_bfloat16* A = g_rTh;
    const __nv_bfloat16* Bm = isRx ? g_xunfh : g_rTh;
    float* Cp  = isRx ? (g_rxP + (size_t)z * (O_ * D_))
                      : (g_rrP + (size_t)z * (O_ * O_));
    const int ldc = isRx ? D_ : O_;

    int tid = threadIdx.x;
    int lane = tid & 31, wid = tid >> 5;
    int wm = wid >> 2, wn = wid & 3;                 // warp tile 64(m) x 32(n)
    size_t k0 = (size_t)z * KCHUNK;

    uint32_t smB = (uint32_t)__cvta_generic_to_shared(dynsm);

    // per-thread load pattern (fixed)
    int lrow[4], lch[4];
#pragma unroll
    for (int i = 0; i < 4; i++) {
        int idx = tid + i * 256;
        lrow[i] = idx >> 3;
        lch[i]  = idx & 7;
    }

    float c[4][4][4];
#pragma unroll
    for (int i = 0; i < 4; i++)
#pragma unroll
        for (int j = 0; j < 4; j++)
#pragma unroll
            for (int q = 0; q < 4; q++) c[i][j][q] = 0.f;

    int lt = lane >> 3, lr = lane & 7;
    int arow = ((lt & 1) << 3) + lr;
    int akch = lt >> 1;

    // ---- stage issue helper ----
    auto issue = [&](int k) {
        int stg = k % 3;
        size_t kb = k0 + (size_t)k * 64;
        uint32_t abase = smB + stg * 32768;
#pragma unroll
        for (int i = 0; i < 4; i++) {
            const void* src = (const void*)(A + (size_t)(mT + lrow[i]) * NTOT + kb + lch[i] * 8);
            CP16(abase + sw_off(lrow[i], lch[i]) - ((lch[i] ^ (lrow[i] & 7)) << 4)
                 + (((lch[i] ^ (lrow[i] & 7))) << 4), src);
        }
        if (!diag) {
            uint32_t bbase = smB + stg * 32768 + 16384;
#pragma unroll
            for (int i = 0; i < 4; i++) {
                int row = lrow[i];
                int grow = isRx ? row : (nT + row);
                int srcrow = (isRx && row >= D_) ? 0 : grow;
                int ss = (isRx && row >= D_) ? 0 : 16;
                const void* src = (const void*)(Bm + (size_t)srcrow * NTOT + kb + lch[i] * 8);
                CP16Z(bbase + sw_off(row, lch[i]), src, ss);
            }
        }
    };

    // ---- prologue: stages 0,1 ----
    issue(0); CPCOMMIT();
    issue(1); CPCOMMIT();

    for (int k = 0; k < NK; k++) {
        if (k + 2 < NK) issue(k + 2);
        CPCOMMIT();
        CPWAIT2();
        __syncthreads();

        uint32_t sA = smB + (k % 3) * 32768;
        uint32_t sB = diag ? sA : sA + 16384;

#pragma unroll
        for (int ks = 0; ks < 4; ks++) {
            int kchb = ks * 2;
            uint32_t af[4][4];
#pragma unroll
            for (int mi = 0; mi < 4; mi++) {
                int row = wm * 64 + mi * 16 + arow;
                LDSM(af[mi][0], af[mi][1], af[mi][2], af[mi][3],
                     sA + sw_off(row, kchb + akch));
            }
            uint32_t bf[2][4];
#pragma unroll
            for (int bj = 0; bj < 2; bj++) {
                int row = wn * 32 + bj * 16 + arow;
                LDSM(bf[bj][0], bf[bj][1], bf[bj][2], bf[bj][3],
                     sB + sw_off(row, kchb + akch));
            }
#pragma unroll
            for (int mi = 0; mi < 4; mi++)
#pragma unroll
                for (int nj = 0; nj < 4; nj++) {
                    int g = nj >> 1, od = nj & 1;
                    MMA16816(c[mi][nj][0], c[mi][nj][1], c[mi][nj][2], c[mi][nj][3],
                             af[mi][0], af[mi][1], af[mi][2], af[mi][3],
                             bf[g][od], bf[g][od + 2]);
                }
        }
        __syncthreads();
    }

#pragma unroll
    for (int mi = 0; mi < 4; mi++) {
        int row0 = mT + wm * 64 + mi * 16 + (lane >> 2);
#pragma unroll
        for (int nj = 0; nj < 4; nj++) {
            int col0 = nT + wn * 32 + nj * 8 + 2 * (lane & 3);
#pragma unroll
            for (int h = 0; h < 2; h++) {
                int r = row0 + h * 8;
                float v0 = c[mi][nj][h * 2 + 0], v1 = c[mi][nj][h * 2 + 1];
                if (!isRx) {
                    Cp[(size_t)r * ldc + col0] = v0;
                    Cp[(size_t)r * ldc + col0 + 1] = v1;
                } else {
                    if (col0 < D_)     Cp[(size_t)r * ldc + col0] = v0;
                    if (col0 + 1 < D_) Cp[(size_t)r * ldc + col0 + 1] = v1;
                }
            }
        }
    }
}

// ------------------------- deterministic split-K reduce ---------------------
__global__ void k_reduce() {
    int t = blockIdx.x * 256 + threadIdx.x;          // 65536 + 19200 = 84736
    if (t < O_ * O_) {
        float s = 0.f;
        for (int z = 0; z < ZB; z++) s += g_rrP[(size_t)z * (O_ * O_) + t];
        g_rr[t] = s;
    } else if (t < O_ * O_ + O_ * D_) {
        int e = t - O_ * O_;
        float s = 0.f;
        for (int z = 0; z < ZB; z++) s += g_rxP[(size_t)z * (O_ * D_) + e];
        g_rx[e] = s;
    }
}

// ------------------------- weight update ------------------------------------
__global__ void k_update(const float* __restrict__ Wt, float* __restrict__ out) {
    int t = blockIdx.x * 256 + threadIdx.x;
    if (t >= O_ * D_) return;
    int o = t / D_;
    int d = t - o * D_;
    float s = 0.f;
    for (int o2 = 0; o2 <= o; o2++)
        s += g_rr[o * O_ + o2] * Wt[o2 * D_ + d];
    out[YOUT + t] = Wt[t] + 0.01f * ((g_rx[t] - s) * (1.0f / 115200.0f));
}

// ---------------------------------------------------------------------------
extern "C" void kernel_launch(void* const* d_in, const int* in_sizes, int n_in,
                              void* d_out, int out_size) {
    const float* x  = (const float*)d_in[0];
    const float* wt = (const float*)d_in[1];
    float* out = (float*)d_out;

    static int smem_set = 0;
    if (!smem_set) {
        cudaFuncSetAttribute(k_mma2, cudaFuncAttributeMaxDynamicSharedMemorySize, 98304);
        smem_set = 1;
    }

    k_init<<<256, 256>>>(wt);
    k_im2col<<<2048, 128>>>(x);
    k_convfused<<<1800, 256>>>(out);
    k_mma2<<<dim3(5, ZB), 256, 98304>>>();
    k_reduce<<<332, 256>>>();
    k_update<<<75, 256>>>(wt, out);
}

// round 10
// speedup vs baseline: 4.2466x; 1.0126x over previous
#include <cuda_runtime.h>
#include <cuda_bf16.h>
#include <cstdint>

// ---------------------------------------------------------------------------
// HebbianMap2d: y_out = relu(conv(x,w)); new_w = w + eta*(r^T Xu - tril(r^T r) W)/N
// with r = lfb(winner(relu(s))) * relu(s).
// Shapes: x[32,3,64,64], w[256,3,5,5] -> y_out[32,256,60,60], new_w[256,75]
// ---------------------------------------------------------------------------

#define B_    32
#define C_    3
#define H_    64
#define W_    64
#define HO_   60
#define WO_   60
#define HW_   3600          // 60*60
#define O_    256
#define D_    75            // 3*5*5
#define DP    80            // D padded to multiple of 16
#define NTOT  115200        // 32*3600
#define YOUT  29491200      // 32*256*3600
#define ZB    60            // split-K chunks
#define KCHUNK 1920         // NTOT / ZB (multiple of 64)
#define NK    30            // KCHUNK / 64

// ------------------------- scratch (device globals) ------------------------
__device__ __align__(16) float g_K[O_ * O_];                 // SOM lateral kernel
__device__ __align__(16) __nv_bfloat16 g_Whi[O_ * DP];       // W split-bf16 hi
__device__ __align__(16) __nv_bfloat16 g_Wlo[O_ * DP];       // W split-bf16 lo
__device__ __align__(16) __nv_bfloat16 g_xch[(size_t)NTOT * DP]; // im2col [n][80] hi
__device__ __align__(16) __nv_bfloat16 g_xcl[(size_t)NTOT * DP]; // im2col [n][80] lo
__device__ __align__(16) __nv_bfloat16 g_xunfh[(size_t)D_ * NTOT]; // [d][n] bf16 (rx GEMM)
__device__ __align__(16) __nv_bfloat16 g_rTh[(size_t)O_ * NTOT];   // r^T bf16 [o][n]
__device__ __align__(16) float g_rrP[(size_t)ZB * O_ * O_];  // split-K partials
__device__ __align__(16) float g_rxP[(size_t)ZB * O_ * D_];
__device__ __align__(16) float g_rr[O_ * O_];
__device__ __align__(16) float g_rx[O_ * D_];

// ------------------------- K table + W split prep (merged) ------------------
__global__ void k_init(const float* __restrict__ Wt) {
    int t = blockIdx.x * 256 + threadIdx.x;          // 65536 total
    {   // K table
        int w = t >> 8, o = t & 255;
        int wi = w >> 4, wj = w & 15, i = o >> 4, j = o & 15;
        int a = wi - i + 7, b = wj - j + 7;
        float v = 0.f;
        if (a >= 0 && a < 16 && b >= 0 && b < 16) {
            int da = abs(a - 7), db = abs(b - 7);
            int m = da > db ? da : db;
            v = expf(-(float)(m * m) / 98.0f);
        }
        g_K[t] = v;
    }
    if (t < O_ * DP) {                               // W split-bf16
        int o = t / DP, d = t - o * DP;
        float v = (d < D_) ? Wt[o * D_ + d] : 0.f;
        __nv_bfloat16 hi = __float2bfloat16(v);
        g_Whi[t] = hi;
        g_Wlo[t] = __float2bfloat16(v - __bfloat162float(hi));
    }
}

// ------------------------- tiled im2col (all 3 layouts) ---------------------
__global__ void __launch_bounds__(128) k_im2col(const float* __restrict__ x) {
    __shared__ float xs[3][5][64];
    int b = blockIdx.x >> 6, i = blockIdx.x & 63;    // grid 2048, skip i>=60
    if (i >= HO_) return;
    int tid = threadIdx.x;
    int n0 = b * HW_ + i * WO_;

    for (int idx = tid; idx < 960; idx += 128) {
        int c = idx / 320, rem = idx - c * 320;
        int ki = rem >> 6, col = rem & 63;
        xs[c][ki][col] = x[((b * C_ + c) * H_ + i + ki) * W_ + col];
    }
    __syncthreads();

    for (int u = tid; u < 600; u += 128) {
        int j = u / 10, dblk = (u - j * 10) * 8;
        __nv_bfloat16 hibuf[8], lobuf[8];
#pragma unroll
        for (int dd = 0; dd < 8; dd++) {
            int d = dblk + dd;
            float v = 0.f;
            if (d < D_) {
                int c = d / 25, rr = d - c * 25;
                int ki = rr / 5, kj = rr - ki * 5;
                v = xs[c][ki][j + kj];
            }
            __nv_bfloat16 hi = __float2bfloat16(v);
            hibuf[dd] = hi;
            lobuf[dd] = __float2bfloat16(v - __bfloat162float(hi));
        }
        size_t base = (size_t)(n0 + j) * DP + dblk;
        *(uint4*)(g_xch + base) = *(uint4*)hibuf;
        *(uint4*)(g_xcl + base) = *(uint4*)lobuf;
    }

    for (int u = tid; u < 2250; u += 128) {
        int d = u / 30, j = (u - d * 30) * 2;
        int c = d / 25, rr = d - c * 25;
        int ki = rr / 5, kj = rr - ki * 5;
        __nv_bfloat162 p;
        p.x = __float2bfloat16(xs[c][ki][j + kj]);
        p.y = __float2bfloat16(xs[c][ki][j + 1 + kj]);
        *(__nv_bfloat162*)(g_xunfh + (size_t)d * NTOT + n0 + j) = p;
    }
}

// ------------------------- fused conv + winner + lfb + r --------------------
#define LDSM(r0,r1,r2,r3,addr) \
    asm volatile("ldmatrix.sync.aligned.m8n8.x4.shared.b16 {%0,%1,%2,%3}, [%4];" \
                 : "=r"(r0), "=r"(r1), "=r"(r2), "=r"(r3) : "r"(addr))
#define MMA16816(c0,c1,c2,c3,a0,a1,a2,a3,b0,b1) \
    asm volatile("mma.sync.aligned.m16n8k16.row.col.f32.bf16.bf16.f32 " \
                 "{%0,%1,%2,%3}, {%4,%5,%6,%7}, {%8,%9}, {%0,%1,%2,%3};" \
                 : "+f"(c0), "+f"(c1), "+f"(c2), "+f"(c3) \
                 : "r"(a0), "r"(a1), "r"(a2), "r"(a3), "r"(b0), "r"(b1))

// dyn smem layout: [0,24576) sW ; [24576,30720) sX ; [30720,98304) ybuf/rbuf
#define CF_SMEM 98304

__global__ void __launch_bounds__(256) k_convfused(float* __restrict__ out) {
    extern __shared__ __align__(16) uint8_t dyns[];
    __shared__ float pmax[4][64];
    __shared__ float ymx[64];
    __shared__ int   nbase64[64];
    __shared__ int   cnt[64];
    __shared__ int   widx[64][8];

    __nv_bfloat16* sW = (__nv_bfloat16*)dyns;                   // 512 rows x 24
    __nv_bfloat16* sX = (__nv_bfloat16*)(dyns + 24576);         // 128 rows x 24
    float*         ybuf = (float*)(dyns + 30720);               // 256 rows x 66 fp32
    __nv_bfloat16* rbuf = (__nv_bfloat16*)(dyns + 30720);       // 256 rows x 66 bf16

    int tid = threadIdx.x, lane = tid & 31, wid = tid >> 5;
    int wm = wid >> 1, wn = wid & 1;
    int nT = blockIdx.x * 64;

    uint32_t sWb = (uint32_t)__cvta_generic_to_shared(sW);
    uint32_t sXb = (uint32_t)__cvta_generic_to_shared(sX);

    int lt = lane >> 3, lr = lane & 7;
    int arow = ((lt & 1) << 3) + lr;
    int akch = lt >> 1;

    float c[4][4][4];
#pragma unroll
    for (int i = 0; i < 4; i++)
#pragma unroll
        for (int j = 0; j < 4; j++)
#pragma unroll
            for (int q = 0; q < 4; q++) c[i][j][q] = 0.f;

    int xpiece = tid & 1, xhl = (tid >> 1) & 1, xrow = tid >> 2;

    uint4 wreg[4];
    uint4 xreg;

#pragma unroll
    for (int i = 0; i < 4; i++) {
        int idx = tid + i * 256;
        int row = idx >> 2;
        const __nv_bfloat16* src = ((idx >> 1) & 1) ? g_Wlo : g_Whi;
        wreg[i] = *(const uint4*)(src + row * DP + (idx & 1) * 8);
    }
    {
        const __nv_bfloat16* src = xhl ? g_xcl : g_xch;
        xreg = *(const uint4*)(src + (size_t)(nT + xrow) * DP + xpiece * 8);
    }
#pragma unroll
    for (int i = 0; i < 4; i++) {
        int idx = tid + i * 256;
        int row = idx >> 2;
        *(uint4*)(sW + (((idx >> 1) & 1) * 256 + row) * 24 + (idx & 1) * 8) = wreg[i];
    }
    *(uint4*)(sX + (xhl * 64 + xrow) * 24 + xpiece * 8) = xreg;
    __syncthreads();

    for (int s = 0; s < 5; s++) {
        if (s < 4) {
#pragma unroll
            for (int i = 0; i < 4; i++) {
                int idx = tid + i * 256;
                int row = idx >> 2;
                const __nv_bfloat16* src = ((idx >> 1) & 1) ? g_Wlo : g_Whi;
                wreg[i] = *(const uint4*)(src + row * DP + (s + 1) * 16 + (idx & 1) * 8);
            }
            const __nv_bfloat16* src = xhl ? g_xcl : g_xch;
            xreg = *(const uint4*)(src + (size_t)(nT + xrow) * DP + (s + 1) * 16 + xpiece * 8);
        }

        uint32_t ah[4][4], al[4][4], bh[2][4], bl[2][4];
#pragma unroll
        for (int mi = 0; mi < 4; mi++) {
            int row = wm * 64 + mi * 16 + arow;
            LDSM(ah[mi][0], ah[mi][1], ah[mi][2], ah[mi][3], sWb + row * 48 + akch * 16);
            LDSM(al[mi][0], al[mi][1], al[mi][2], al[mi][3], sWb + (256 + row) * 48 + akch * 16);
        }
#pragma unroll
        for (int bj = 0; bj < 2; bj++) {
            int row = wn * 32 + bj * 16 + arow;
            LDSM(bh[bj][0], bh[bj][1], bh[bj][2], bh[bj][3], sXb + row * 48 + akch * 16);
            LDSM(bl[bj][0], bl[bj][1], bl[bj][2], bl[bj][3], sXb + (64 + row) * 48 + akch * 16);
        }
#pragma unroll
        for (int mi = 0; mi < 4; mi++)
#pragma unroll
            for (int nj = 0; nj < 4; nj++) {
                int g = nj >> 1, od = nj & 1;
                MMA16816(c[mi][nj][0], c[mi][nj][1], c[mi][nj][2], c[mi][nj][3],
                         ah[mi][0], ah[mi][1], ah[mi][2], ah[mi][3],
                         bh[g][od], bh[g][od + 2]);
                MMA16816(c[mi][nj][0], c[mi][nj][1], c[mi][nj][2], c[mi][nj][3],
                         ah[mi][0], ah[mi][1], ah[mi][2], ah[mi][3],
                         bl[g][od], bl[g][od + 2]);
                MMA16816(c[mi][nj][0], c[mi][nj][1], c[mi][nj][2], c[mi][nj][3],
                         al[mi][0], al[mi][1], al[mi][2], al[mi][3],
                         bh[g][od], bh[g][od + 2]);
            }
        __syncthreads();
        if (s < 4) {
#pragma unroll
            for (int i = 0; i < 4; i++) {
                int idx = tid + i * 256;
                int row = idx >> 2;
                *(uint4*)(sW + (((idx >> 1) & 1) * 256 + row) * 24 + (idx & 1) * 8) = wreg[i];
            }
            *(uint4*)(sX + (xhl * 64 + xrow) * 24 + xpiece * 8) = xreg;
            __syncthreads();
        }
    }

    // ---------------- epilogue ----------------
    int lq = lane >> 2, ln = lane & 3;

    // 1) relu in regs + per-thread column max
    float tmax[4][2];
#pragma unroll
    for (int nj = 0; nj < 4; nj++)
#pragma unroll
        for (int q = 0; q < 2; q++) tmax[nj][q] = 0.f;
#pragma unroll
    for (int mi = 0; mi < 4; mi++)
#pragma unroll
        for (int nj = 0; nj < 4; nj++)
#pragma unroll
            for (int q = 0; q < 4; q++) {
                float y = fmaxf(c[mi][nj][q], 0.f);
                c[mi][nj][q] = y;
                tmax[nj][q & 1] = fmaxf(tmax[nj][q & 1], y);
            }

#pragma unroll
    for (int nj = 0; nj < 4; nj++)
#pragma unroll
        for (int q = 0; q < 2; q++) {
            float m = tmax[nj][q];
            m = fmaxf(m, __shfl_xor_sync(0xffffffffu, m, 4));
            m = fmaxf(m, __shfl_xor_sync(0xffffffffu, m, 8));
            m = fmaxf(m, __shfl_xor_sync(0xffffffffu, m, 16));
            if (lq == 0) pmax[wm][wn * 32 + nj * 8 + 2 * ln + q] = m;
        }
    if (tid < 64) {
        int n = nT + tid;
        int b = n / HW_;
        nbase64[tid] = b * (O_ * HW_) + (n - b * HW_);
    }
    __syncthreads();

    if (tid < 64) {
        ymx[tid] = fmaxf(fmaxf(pmax[0][tid], pmax[1][tid]),
                         fmaxf(pmax[2][tid], pmax[3][tid]));
        cnt[tid] = 0;
    }
    __syncthreads();

    // 2) winner detection (from regs)
#pragma unroll
    for (int mi = 0; mi < 4; mi++)
#pragma unroll
        for (int h = 0; h < 2; h++) {
            int o = wm * 64 + mi * 16 + lq + 8 * h;
#pragma unroll
            for (int nj = 0; nj < 4; nj++)
#pragma unroll
                for (int q = 0; q < 2; q++) {
                    int nn = wn * 32 + nj * 8 + 2 * ln + q;
                    float ym = ymx[nn];
                    if (ym > 0.f && c[mi][nj][h * 2 + q] == ym) {
                        int pos = atomicAdd(&cnt[nn], 1);
                        if (pos < 8) widx[nn][pos] = o;
                    }
                }
        }

    // 3) stage ALL of y into ybuf (no sync needed before: ybuf disjoint from
    //    winner-detect smem; sync below orders it for the writers)
#pragma unroll
    for (int mi = 0; mi < 4; mi++)
#pragma unroll
        for (int h = 0; h < 2; h++) {
            int orow = wm * 64 + mi * 16 + lq + 8 * h;
#pragma unroll
            for (int nj = 0; nj < 4; nj++) {
                int nn = wn * 32 + nj * 8 + 2 * ln;
                ybuf[orow * 66 + nn]     = c[mi][nj][h * 2 + 0];
                ybuf[orow * 66 + nn + 1] = c[mi][nj][h * 2 + 1];
            }
        }
    __syncthreads();

    // 4) coalesced y_out write: warp wid -> rows wid*32..+31, float2 per lane
    {
        int hw0 = nT % HW_;
        int b0  = nT / HW_;
        if (hw0 + 64 <= HW_) {                        // fast path: contiguous n
            size_t base = ((size_t)b0 * O_) * HW_ + hw0 + 2 * lane;
#pragma unroll
            for (int rr2 = 0; rr2 < 32; rr2++) {
                int o = wid * 32 + rr2;
                float2 v;
                v.x = ybuf[o * 66 + 2 * lane];
                v.y = ybuf[o * 66 + 2 * lane + 1];
                *(float2*)(out + base + (size_t)o * HW_) = v;
            }
        } else {                                      // batch-boundary block
#pragma unroll
            for (int rr2 = 0; rr2 < 32; rr2++) {
                int o = wid * 32 + rr2;
                size_t ob = (size_t)o * HW_;
                int n0 = 2 * lane;
                out[ob + nbase64[n0]]     = ybuf[o * 66 + n0];
                out[ob + nbase64[n0 + 1]] = ybuf[o * 66 + n0 + 1];
            }
        }
    }
    __syncthreads();

    // 5) stage y as bf16 into rbuf (aliases ybuf — y already written out)
#pragma unroll
    for (int nj = 0; nj < 4; nj++) {
        int nn0 = wn * 32 + nj * 8 + 2 * ln;
#pragma unroll
        for (int mi = 0; mi < 4; mi++)
#pragma unroll
            for (int h = 0; h < 2; h++) {
                int o = wm * 64 + mi * 16 + lq + 8 * h;
                __nv_bfloat162 p;
                p.x = __float2bfloat16(c[mi][nj][h * 2 + 0]);
                p.y = __float2bfloat16(c[mi][nj][h * 2 + 1]);
                *(__nv_bfloat162*)(rbuf + o * 66 + nn0) = p;
            }
    }
    __syncthreads();

    // 6) per-n lfb: lanes cover consecutive n (same chunk) -> conflict-light
    {
        int n = tid & 63, chunk = tid >> 6;          // 64 o per thread
        int cN = min(cnt[n], 8);
#pragma unroll
        for (int sub = 0; sub < 4; sub++) {
            float lfb[16];
#pragma unroll
            for (int i = 0; i < 16; i++) lfb[i] = 0.f;
            for (int j = 0; j < cN; j++) {
                const float4* kp = (const float4*)(g_K + widx[n][j] * O_ + chunk * 64 + sub * 16);
#pragma unroll
                for (int q = 0; q < 4; q++) {
                    float4 kv = kp[q];
                    lfb[q * 4 + 0] += kv.x;
                    lfb[q * 4 + 1] += kv.y;
                    lfb[q * 4 + 2] += kv.z;
                    lfb[q * 4 + 3] += kv.w;
                }
            }
#pragma unroll
            for (int i = 0; i < 16; i++) {
                int o = chunk * 64 + sub * 16 + i;
                float l = fminf(fmaxf(lfb[i], -1.f), 1.f);
                __nv_bfloat16* p = rbuf + o * 66 + n;
                *p = __float2bfloat16(l * __bfloat162float(*p));
            }
        }
    }
    __syncthreads();

    // 7) coalesced rT write
#pragma unroll
    for (int rr2 = 0; rr2 < 32; rr2++) {
        int o = wid * 32 + rr2;
        uint32_t v = *(uint32_t*)(rbuf + o * 66 + 2 * lane);
        *(uint32_t*)(g_rTh + (size_t)o * NTOT + nT + 2 * lane) = v;
    }
}

// ------------- merged rr+rx split-K GEMM: 3-stage cp.async, 1 sync/iter -----
// Tiles: 0:(rr 0,0 diag) 1:(rr 1,0) 2:(rr 1,1 diag) 3:(rx m=0) 4:(rx m=1)
#define CP16(dst, src) \
    asm volatile("cp.async.cg.shared.global [%0], [%1], 16;" :: "r"(dst), "l"(src))
#define CP16Z(dst, src, ss) \
    asm volatile("cp.async.cg.shared.global [%0], [%1], 16, %2;" :: "r"(dst), "l"(src), "r"(ss))
#define CPCOMMIT() asm volatile("cp.async.commit_group;")
#define CPWAIT1()  asm volatile("cp.async.wait_group 1;")

__device__ __forceinline__ uint32_t sw_off(int row, int kch) {
    return (uint32_t)(row * 128 + ((kch ^ (row & 7)) << 4));
}

__global__ void __launch_bounds__(256) k_mma2() {
    extern __shared__ __align__(16) uint8_t dynsm[];

    int t = blockIdx.x;                              // 0..4
    int z = blockIdx.y;                              // 0..ZB-1
    int  mT   = (t == 1 || t == 2 || t == 4) ? 128 : 0;
    bool isRx = (t >= 3);
    bool diag = (t == 0 || t == 2);
    int  nT   = (t == 2) ? 128 : 0;

    const __nv_bfloat16* A = g_rTh;
    const __nv_bfloat16* Bm = isRx ? g_xunfh : g_rTh;
    float* Cp  = isRx ? (g_rxP + (size_t)z * (O_ * D_))
                      : (g_rrP + (size_t)z * (O_ * O_));
    const int ldc = isRx ? D_ : O_;

    int tid = threadIdx.x;
    int lane = tid & 31, wid = tid >> 5;
    int wm = wid >> 2, wn = wid & 3;                 // warp tile 64(m) x 32(n)
    size_t k0 = (size_t)z * KCHUNK;

    uint32_t smB = (uint32_t)__cvta_generic_to_shared(dynsm);

    int lrow[4], lch[4];
#pragma unroll
    for (int i = 0; i < 4; i++) {
        int idx = tid + i * 256;
        lrow[i] = idx >> 3;
        lch[i]  = idx & 7;
    }

    float c[4][4][4];
#pragma unroll
    for (int i = 0; i < 4; i++)
#pragma unroll
        for (int j = 0; j < 4; j++)
#pragma unroll
            for (int q = 0; q < 4; q++) c[i][j][q] = 0.f;

    int lt = lane >> 3, lr = lane & 7;
    int arow = ((lt & 1) << 3) + lr;
    int akch = lt >> 1;

    auto issue = [&](int k) {
        int stg = k % 3;
        size_t kb = k0 + (size_t)k * 64;
        uint32_t abase = smB + stg * 32768;
#pragma unroll
        for (int i = 0; i < 4; i++) {
            const void* src = (const void*)(A + (size_t)(mT + lrow[i]) * NTOT + kb + lch[i] * 8);
            CP16(abase + sw_off(lrow[i], lch[i]), src);
        }
        if (!diag) {
            uint32_t bbase = smB + stg * 32768 + 16384;
#pragma unroll
            for (int i = 0; i < 4; i++) {
                int row = lrow[i];
                int grow = isRx ? row : (nT + row);
                int srcrow = (isRx && row >= D_) ? 0 : grow;
                int ss = (isRx && row >= D_) ? 0 : 16;
                const void* src = (const void*)(Bm + (size_t)srcrow * NTOT + kb + lch[i] * 8);
                CP16Z(bbase + sw_off(row, lch[i]), src, ss);
            }
        }
    };

    issue(0); CPCOMMIT();
    issue(1); CPCOMMIT();

    for (int k = 0; k < NK; k++) {
        CPWAIT1();                                   // stage k landed (k+1 may fly)
        __syncthreads();
        if (k + 2 < NK) { issue(k + 2); CPCOMMIT(); }  // writes buf (k-1)%3: safe

        uint32_t sA = smB + (k % 3) * 32768;
        uint32_t sB = diag ? sA : sA + 16384;

#pragma unroll
        for (int ks = 0; ks < 4; ks++) {
            int kchb = ks * 2;
            uint32_t af[4][4];
#pragma unroll
            for (int mi = 0; mi < 4; mi++) {
                int row = wm * 64 + mi * 16 + arow;
                LDSM(af[mi][0], af[mi][1], af[mi][2], af[mi][3],
                     sA + sw_off(row, kchb + akch));
            }
            uint32_t bf[2][4];
#pragma unroll
            for (int bj = 0; bj < 2; bj++) {
                int row = wn * 32 + bj * 16 + arow;
                LDSM(bf[bj][0], bf[bj][1], bf[bj][2], bf[bj][3],
                     sB + sw_off(row, kchb + akch));
            }
#pragma unroll
            for (int mi = 0; mi < 4; mi++)
#pragma unroll
                for (int nj = 0; nj < 4; nj++) {
                    int g = nj >> 1, od = nj & 1;
                    MMA16816(c[mi][nj][0], c[mi][nj][1], c[mi][nj][2], c[mi][nj][3],
                             af[mi][0], af[mi][1], af[mi][2], af[mi][3],
                             bf[g][od], bf[g][od + 2]);
                }
        }
    }

#pragma unroll
    for (int mi = 0; mi < 4; mi++) {
        int row0 = mT + wm * 64 + mi * 16 + (lane >> 2);
#pragma unroll
        for (int nj = 0; nj < 4; nj++) {
            int col0 = nT + wn * 32 + nj * 8 + 2 * (lane & 3);
#pragma unroll
            for (int h = 0; h < 2; h++) {
                int r = row0 + h * 8;
                float v0 = c[mi][nj][h * 2 + 0], v1 = c[mi][nj][h * 2 + 1];
                if (!isRx) {
                    Cp[(size_t)r * ldc + col0] = v0;
                    Cp[(size_t)r * ldc + col0 + 1] = v1;
                } else {
                    if (col0 < D_)     Cp[(size_t)r * ldc + col0] = v0;
                    if (col0 + 1 < D_) Cp[(size_t)r * ldc + col0 + 1] = v1;
                }
            }
        }
    }
}

// ------------------------- deterministic split-K reduce ---------------------
__global__ void k_reduce() {
    int t = blockIdx.x * 256 + threadIdx.x;          // 65536 + 19200 = 84736
    if (t < O_ * O_) {
        float s = 0.f;
        for (int z = 0; z < ZB; z++) s += g_rrP[(size_t)z * (O_ * O_) + t];
        g_rr[t] = s;
    } else if (t < O_ * O_ + O_ * D_) {
        int e = t - O_ * O_;
        float s = 0.f;
        for (int z = 0; z < ZB; z++) s += g_rxP[(size_t)z * (O_ * D_) + e];
        g_rx[e] = s;
    }
}

// ------------------------- weight update ------------------------------------
__global__ void k_update(const float* __restrict__ Wt, float* __restrict__ out) {
    int t = blockIdx.x * 256 + threadIdx.x;
    if (t >= O_ * D_) return;
    int o = t / D_;
    int d = t - o * D_;
    float s = 0.f;
    for (int o2 = 0; o2 <= o; o2++)
        s += g_rr[o * O_ + o2] * Wt[o2 * D_ + d];
    out[YOUT + t] = Wt[t] + 0.01f * ((g_rx[t] - s) * (1.0f / 115200.0f));
}

// ---------------------------------------------------------------------------
extern "C" void kernel_launch(void* const* d_in, const int* in_sizes, int n_in,
                              void* d_out, int out_size) {
    const float* x  = (const float*)d_in[0];
    const float* wt = (const float*)d_in[1];
    float* out = (float*)d_out;

    static int smem_set = 0;
    if (!smem_set) {
        cudaFuncSetAttribute(k_mma2, cudaFuncAttributeMaxDynamicSharedMemorySize, 98304);
        cudaFuncSetAttribute(k_convfused, cudaFuncAttributeMaxDynamicSharedMemorySize, CF_SMEM);
        smem_set = 1;
    }

    k_init<<<256, 256>>>(wt);
    k_im2col<<<2048, 128>>>(x);
    k_convfused<<<1800, 256, CF_SMEM>>>(out);
    k_mma2<<<dim3(5, ZB), 256, 98304>>>();
    k_reduce<<<332, 256>>>();
    k_update<<<75, 256>>>(wt, out);
}

// round 11
// speedup vs baseline: 4.3746x; 1.0301x over previous
#include <cuda_runtime.h>
#include <cuda_bf16.h>
#include <cstdint>

// ---------------------------------------------------------------------------
// HebbianMap2d: y_out = relu(conv(x,w)); new_w = w + eta*(r^T Xu - tril(r^T r) W)/N
// with r = lfb(winner(relu(s))) * relu(s).
// Shapes: x[32,3,64,64], w[256,3,5,5] -> y_out[32,256,60,60], new_w[256,75]
// ---------------------------------------------------------------------------

#define B_    32
#define C_    3
#define H_    64
#define W_    64
#define HO_   60
#define WO_   60
#define HW_   3600          // 60*60
#define O_    256
#define D_    75            // 3*5*5
#define DP    80            // D padded to multiple of 16
#define NTOT  115200        // 32*3600
#define YOUT  29491200      // 32*256*3600
#define ZB    50            // split-K chunks (5*ZB=250 blocks: single wave @2/SM)
#define KCHUNK 2304         // NTOT / ZB (multiple of 64)
#define NK    36            // KCHUNK / 64

// ------------------------- scratch (device globals) ------------------------
__device__ __align__(16) float g_K[O_ * O_];                 // SOM lateral kernel
__device__ __align__(16) __nv_bfloat16 g_Whi[O_ * DP];       // W split-bf16 hi
__device__ __align__(16) __nv_bfloat16 g_Wlo[O_ * DP];       // W split-bf16 lo
__device__ __align__(16) __nv_bfloat16 g_xch[(size_t)NTOT * DP]; // im2col [n][80] hi
__device__ __align__(16) __nv_bfloat16 g_xcl[(size_t)NTOT * DP]; // im2col [n][80] lo
__device__ __align__(16) __nv_bfloat16 g_xunfh[(size_t)D_ * NTOT]; // [d][n] bf16 (rx GEMM)
__device__ __align__(16) __nv_bfloat16 g_rTh[(size_t)O_ * NTOT];   // r^T bf16 [o][n]
__device__ __align__(16) float g_rrP[(size_t)ZB * O_ * O_];  // split-K partials
__device__ __align__(16) float g_rxP[(size_t)ZB * O_ * D_];
__device__ __align__(16) float g_rr[O_ * O_];
__device__ __align__(16) float g_rx[O_ * D_];

// ------------------------- K table + W split prep (merged) ------------------
__global__ void k_init(const float* __restrict__ Wt) {
    int t = blockIdx.x * 256 + threadIdx.x;          // 65536 total
    {   // K table
        int w = t >> 8, o = t & 255;
        int wi = w >> 4, wj = w & 15, i = o >> 4, j = o & 15;
        int a = wi - i + 7, b = wj - j + 7;
        float v = 0.f;
        if (a >= 0 && a < 16 && b >= 0 && b < 16) {
            int da = abs(a - 7), db = abs(b - 7);
            int m = da > db ? da : db;
            v = expf(-(float)(m * m) / 98.0f);
        }
        g_K[t] = v;
    }
    if (t < O_ * DP) {                               // W split-bf16
        int o = t / DP, d = t - o * DP;
        float v = (d < D_) ? Wt[o * D_ + d] : 0.f;
        __nv_bfloat16 hi = __float2bfloat16(v);
        g_Whi[t] = hi;
        g_Wlo[t] = __float2bfloat16(v - __bfloat162float(hi));
    }
}

// ------------------------- tiled im2col (all 3 layouts) ---------------------
__global__ void __launch_bounds__(128) k_im2col(const float* __restrict__ x) {
    __shared__ float xs[3][5][64];
    int b = blockIdx.x >> 6, i = blockIdx.x & 63;    // grid 2048, skip i>=60
    if (i >= HO_) return;
    int tid = threadIdx.x;
    int n0 = b * HW_ + i * WO_;

    for (int idx = tid; idx < 960; idx += 128) {
        int c = idx / 320, rem = idx - c * 320;
        int ki = rem >> 6, col = rem & 63;
        xs[c][ki][col] = x[((b * C_ + c) * H_ + i + ki) * W_ + col];
    }
    __syncthreads();

    for (int u = tid; u < 600; u += 128) {
        int j = u / 10, dblk = (u - j * 10) * 8;
        __nv_bfloat16 hibuf[8], lobuf[8];
#pragma unroll
        for (int dd = 0; dd < 8; dd++) {
            int d = dblk + dd;
            float v = 0.f;
            if (d < D_) {
                int c = d / 25, rr = d - c * 25;
                int ki = rr / 5, kj = rr - ki * 5;
                v = xs[c][ki][j + kj];
            }
            __nv_bfloat16 hi = __float2bfloat16(v);
            hibuf[dd] = hi;
            lobuf[dd] = __float2bfloat16(v - __bfloat162float(hi));
        }
        size_t base = (size_t)(n0 + j) * DP + dblk;
        *(uint4*)(g_xch + base) = *(uint4*)hibuf;
        *(uint4*)(g_xcl + base) = *(uint4*)lobuf;
    }

    for (int u = tid; u < 2250; u += 128) {
        int d = u / 30, j = (u - d * 30) * 2;
        int c = d / 25, rr = d - c * 25;
        int ki = rr / 5, kj = rr - ki * 5;
        __nv_bfloat162 p;
        p.x = __float2bfloat16(xs[c][ki][j + kj]);
        p.y = __float2bfloat16(xs[c][ki][j + 1 + kj]);
        *(__nv_bfloat162*)(g_xunfh + (size_t)d * NTOT + n0 + j) = p;
    }
}

// ------------------------- fused conv + winner + lfb + r --------------------
#define LDSM(r0,r1,r2,r3,addr) \
    asm volatile("ldmatrix.sync.aligned.m8n8.x4.shared.b16 {%0,%1,%2,%3}, [%4];" \
                 : "=r"(r0), "=r"(r1), "=r"(r2), "=r"(r3) : "r"(addr))
#define MMA16816(c0,c1,c2,c3,a0,a1,a2,a3,b0,b1) \
    asm volatile("mma.sync.aligned.m16n8k16.row.col.f32.bf16.bf16.f32 " \
                 "{%0,%1,%2,%3}, {%4,%5,%6,%7}, {%8,%9}, {%0,%1,%2,%3};" \
                 : "+f"(c0), "+f"(c1), "+f"(c2), "+f"(c3) \
                 : "r"(a0), "r"(a1), "r"(a2), "r"(a3), "r"(b0), "r"(b1))

// dyn smem layout: [0,24576) sW ; [24576,30720) sX ; [30720,98304) ybuf/rbuf
#define CF_SMEM 98304

__global__ void __launch_bounds__(256, 2) k_convfused(float* __restrict__ out) {
    extern __shared__ __align__(16) uint8_t dyns[];
    __shared__ float pmax[4][64];
    __shared__ float ymx[64];
    __shared__ int   nbase64[64];
    __shared__ int   cnt[64];
    __shared__ int   widx[64][8];

    __nv_bfloat16* sW = (__nv_bfloat16*)dyns;                   // 512 rows x 24
    __nv_bfloat16* sX = (__nv_bfloat16*)(dyns + 24576);         // 128 rows x 24
    float*         ybuf = (float*)(dyns + 30720);               // 256 rows x 66 fp32
    __nv_bfloat16* rbuf = (__nv_bfloat16*)(dyns + 30720);       // 256 rows x 66 bf16

    int tid = threadIdx.x, lane = tid & 31, wid = tid >> 5;
    int wm = wid >> 1, wn = wid & 1;
    int nT = blockIdx.x * 64;

    uint32_t sWb = (uint32_t)__cvta_generic_to_shared(sW);
    uint32_t sXb = (uint32_t)__cvta_generic_to_shared(sX);

    int lt = lane >> 3, lr = lane & 7;
    int arow = ((lt & 1) << 3) + lr;
    int akch = lt >> 1;

    float c[4][4][4];
#pragma unroll
    for (int i = 0; i < 4; i++)
#pragma unroll
        for (int j = 0; j < 4; j++)
#pragma unroll
            for (int q = 0; q < 4; q++) c[i][j][q] = 0.f;

    int xpiece = tid & 1, xhl = (tid >> 1) & 1, xrow = tid >> 2;

    uint4 wreg[4];
    uint4 xreg;

#pragma unroll
    for (int i = 0; i < 4; i++) {
        int idx = tid + i * 256;
        int row = idx >> 2;
        const __nv_bfloat16* src = ((idx >> 1) & 1) ? g_Wlo : g_Whi;
        wreg[i] = *(const uint4*)(src + row * DP + (idx & 1) * 8);
    }
    {
        const __nv_bfloat16* src = xhl ? g_xcl : g_xch;
        xreg = *(const uint4*)(src + (size_t)(nT + xrow) * DP + xpiece * 8);
    }
#pragma unroll
    for (int i = 0; i < 4; i++) {
        int idx = tid + i * 256;
        int row = idx >> 2;
        *(uint4*)(sW + (((idx >> 1) & 1) * 256 + row) * 24 + (idx & 1) * 8) = wreg[i];
    }
    *(uint4*)(sX + (xhl * 64 + xrow) * 24 + xpiece * 8) = xreg;
    __syncthreads();

    for (int s = 0; s < 5; s++) {
        if (s < 4) {
#pragma unroll
            for (int i = 0; i < 4; i++) {
                int idx = tid + i * 256;
                int row = idx >> 2;
                const __nv_bfloat16* src = ((idx >> 1) & 1) ? g_Wlo : g_Whi;
                wreg[i] = *(const uint4*)(src + row * DP + (s + 1) * 16 + (idx & 1) * 8);
            }
            const __nv_bfloat16* src = xhl ? g_xcl : g_xch;
            xreg = *(const uint4*)(src + (size_t)(nT + xrow) * DP + (s + 1) * 16 + xpiece * 8);
        }

        uint32_t ah[4][4], al[4][4], bh[2][4], bl[2][4];
#pragma unroll
        for (int mi = 0; mi < 4; mi++) {
            int row = wm * 64 + mi * 16 + arow;
            LDSM(ah[mi][0], ah[mi][1], ah[mi][2], ah[mi][3], sWb + row * 48 + akch * 16);
            LDSM(al[mi][0], al[mi][1], al[mi][2], al[mi][3], sWb + (256 + row) * 48 + akch * 16);
        }
#pragma unroll
        for (int bj = 0; bj < 2; bj++) {
            int row = wn * 32 + bj * 16 + arow;
            LDSM(bh[bj][0], bh[bj][1], bh[bj][2], bh[bj][3], sXb + row * 48 + akch * 16);
            LDSM(bl[bj][0], bl[bj][1], bl[bj][2], bl[bj][3], sXb + (64 + row) * 48 + akch * 16);
        }
#pragma unroll
        for (int mi = 0; mi < 4; mi++)
#pragma unroll
            for (int nj = 0; nj < 4; nj++) {
                int g = nj >> 1, od = nj & 1;
                MMA16816(c[mi][nj][0], c[mi][nj][1], c[mi][nj][2], c[mi][nj][3],
                         ah[mi][0], ah[mi][1], ah[mi][2], ah[mi][3],
                         bh[g][od], bh[g][od + 2]);
                MMA16816(c[mi][nj][0], c[mi][nj][1], c[mi][nj][2], c[mi][nj][3],
                         ah[mi][0], ah[mi][1], ah[mi][2], ah[mi][3],
                         bl[g][od], bl[g][od + 2]);
                MMA16816(c[mi][nj][0], c[mi][nj][1], c[mi][nj][2], c[mi][nj][3],
                         al[mi][0], al[mi][1], al[mi][2], al[mi][3],
                         bh[g][od], bh[g][od + 2]);
            }
        __syncthreads();
        if (s < 4) {
#pragma unroll
            for (int i = 0; i < 4; i++) {
                int idx = tid + i * 256;
                int row = idx >> 2;
                *(uint4*)(sW + (((idx >> 1) & 1) * 256 + row) * 24 + (idx & 1) * 8) = wreg[i];
            }
            *(uint4*)(sX + (xhl * 64 + xrow) * 24 + xpiece * 8) = xreg;
            __syncthreads();
        }
    }

    // ---------------- epilogue ----------------
    int lq = lane >> 2, ln = lane & 3;

    // 1) relu in regs + per-thread column max
    float tmax[4][2];
#pragma unroll
    for (int nj = 0; nj < 4; nj++)
#pragma unroll
        for (int q = 0; q < 2; q++) tmax[nj][q] = 0.f;
#pragma unroll
    for (int mi = 0; mi < 4; mi++)
#pragma unroll
        for (int nj = 0; nj < 4; nj++)
#pragma unroll
            for (int q = 0; q < 4; q++) {
                float y = fmaxf(c[mi][nj][q], 0.f);
                c[mi][nj][q] = y;
                tmax[nj][q & 1] = fmaxf(tmax[nj][q & 1], y);
            }

#pragma unroll
    for (int nj = 0; nj < 4; nj++)
#pragma unroll
        for (int q = 0; q < 2; q++) {
            float m = tmax[nj][q];
            m = fmaxf(m, __shfl_xor_sync(0xffffffffu, m, 4));
            m = fmaxf(m, __shfl_xor_sync(0xffffffffu, m, 8));
            m = fmaxf(m, __shfl_xor_sync(0xffffffffu, m, 16));
            if (lq == 0) pmax[wm][wn * 32 + nj * 8 + 2 * ln + q] = m;
        }
    if (tid < 64) {
        int n = nT + tid;
        int b = n / HW_;
        nbase64[tid] = b * (O_ * HW_) + (n - b * HW_);
    }
    __syncthreads();

    if (tid < 64) {
        ymx[tid] = fmaxf(fmaxf(pmax[0][tid], pmax[1][tid]),
                         fmaxf(pmax[2][tid], pmax[3][tid]));
        cnt[tid] = 0;
    }
    __syncthreads();

    // 2) winner detection (from regs)
#pragma unroll
    for (int mi = 0; mi < 4; mi++)
#pragma unroll
        for (int h = 0; h < 2; h++) {
            int o = wm * 64 + mi * 16 + lq + 8 * h;
#pragma unroll
            for (int nj = 0; nj < 4; nj++)
#pragma unroll
                for (int q = 0; q < 2; q++) {
                    int nn = wn * 32 + nj * 8 + 2 * ln + q;
                    float ym = ymx[nn];
                    if (ym > 0.f && c[mi][nj][h * 2 + q] == ym) {
                        int pos = atomicAdd(&cnt[nn], 1);
                        if (pos < 8) widx[nn][pos] = o;
                    }
                }
        }

    // 3) stage ALL of y into ybuf
#pragma unroll
    for (int mi = 0; mi < 4; mi++)
#pragma unroll
        for (int h = 0; h < 2; h++) {
            int orow = wm * 64 + mi * 16 + lq + 8 * h;
#pragma unroll
            for (int nj = 0; nj < 4; nj++) {
                int nn = wn * 32 + nj * 8 + 2 * ln;
                ybuf[orow * 66 + nn]     = c[mi][nj][h * 2 + 0];
                ybuf[orow * 66 + nn + 1] = c[mi][nj][h * 2 + 1];
            }
        }
    __syncthreads();

    // 4) coalesced y_out write: warp wid -> rows wid*32..+31, float2 per lane
    {
        int hw0 = nT % HW_;
        int b0  = nT / HW_;
        if (hw0 + 64 <= HW_) {                        // fast path: contiguous n
            size_t base = ((size_t)b0 * O_) * HW_ + hw0 + 2 * lane;
#pragma unroll
            for (int rr2 = 0; rr2 < 32; rr2++) {
                int o = wid * 32 + rr2;
                float2 v;
                v.x = ybuf[o * 66 + 2 * lane];
                v.y = ybuf[o * 66 + 2 * lane + 1];
                *(float2*)(out + base + (size_t)o * HW_) = v;
            }
        } else {                                      // batch-boundary block
#pragma unroll
            for (int rr2 = 0; rr2 < 32; rr2++) {
                int o = wid * 32 + rr2;
                size_t ob = (size_t)o * HW_;
                int n0 = 2 * lane;
                out[ob + nbase64[n0]]     = ybuf[o * 66 + n0];
                out[ob + nbase64[n0 + 1]] = ybuf[o * 66 + n0 + 1];
            }
        }
    }
    __syncthreads();

    // 5) stage y as bf16 into rbuf (aliases ybuf — y already written out)
#pragma unroll
    for (int nj = 0; nj < 4; nj++) {
        int nn0 = wn * 32 + nj * 8 + 2 * ln;
#pragma unroll
        for (int mi = 0; mi < 4; mi++)
#pragma unroll
            for (int h = 0; h < 2; h++) {
                int o = wm * 64 + mi * 16 + lq + 8 * h;
                __nv_bfloat162 p;
                p.x = __float2bfloat16(c[mi][nj][h * 2 + 0]);
                p.y = __float2bfloat16(c[mi][nj][h * 2 + 1]);
                *(__nv_bfloat162*)(rbuf + o * 66 + nn0) = p;
            }
    }
    __syncthreads();

    // 6) per-n lfb: lanes cover consecutive n
    {
        int n = tid & 63, chunk = tid >> 6;          // 64 o per thread
        int cN = min(cnt[n], 8);
#pragma unroll
        for (int sub = 0; sub < 4; sub++) {
            float lfb[16];
#pragma unroll
            for (int i = 0; i < 16; i++) lfb[i] = 0.f;
            for (int j = 0; j < cN; j++) {
                const float4* kp = (const float4*)(g_K + widx[n][j] * O_ + chunk * 64 + sub * 16);
#pragma unroll
                for (int q = 0; q < 4; q++) {
                    float4 kv = kp[q];
                    lfb[q * 4 + 0] += kv.x;
                    lfb[q * 4 + 1] += kv.y;
                    lfb[q * 4 + 2] += kv.z;
                    lfb[q * 4 + 3] += kv.w;
                }
            }
#pragma unroll
            for (int i = 0; i < 16; i++) {
                int o = chunk * 64 + sub * 16 + i;
                float l = fminf(fmaxf(lfb[i], -1.f), 1.f);
                __nv_bfloat16* p = rbuf + o * 66 + n;
                *p = __float2bfloat16(l * __bfloat162float(*p));
            }
        }
    }
    __syncthreads();

    // 7) coalesced rT write
#pragma unroll
    for (int rr2 = 0; rr2 < 32; rr2++) {
        int o = wid * 32 + rr2;
        uint32_t v = *(uint32_t*)(rbuf + o * 66 + 2 * lane);
        *(uint32_t*)(g_rTh + (size_t)o * NTOT + nT + 2 * lane) = v;
    }
}

// ------------- merged rr+rx split-K GEMM: 3-stage cp.async, 1 sync/iter -----
// Tiles: 0:(rr 0,0 diag) 1:(rr 1,0) 2:(rr 1,1 diag) 3:(rx m=0) 4:(rx m=1)
#define CP16(dst, src) \
    asm volatile("cp.async.cg.shared.global [%0], [%1], 16;" :: "r"(dst), "l"(src))
#define CP16Z(dst, src, ss) \
    asm volatile("cp.async.cg.shared.global [%0], [%1], 16, %2;" :: "r"(dst), "l"(src), "r"(ss))
#define CPCOMMIT() asm volatile("cp.async.commit_group;")
#define CPWAIT1()  asm volatile("cp.async.wait_group 1;")

__device__ __forceinline__ uint32_t sw_off(int row, int kch) {
    return (uint32_t)(row * 128 + ((kch ^ (row & 7)) << 4));
}

__global__ void __launch_bounds__(256) k_mma2() {
    extern __shared__ __align__(16) uint8_t dynsm[];

    int t = blockIdx.x;                              // 0..4
    int z = blockIdx.y;                              // 0..ZB-1
    int  mT   = (t == 1 || t == 2 || t == 4) ? 128 : 0;
    bool isRx = (t >= 3);
    bool diag = (t == 0 || t == 2);
    int  nT   = (t == 2) ? 128 : 0;

    const __nv_bfloat16* A = g_rTh;
    const __nv_bfloat16* Bm = isRx ? g_xunfh : g_rTh;
    float* Cp  = isRx ? (g_rxP + (size_t)z * (O_ * D_))
                      : (g_rrP + (size_t)z * (O_ * O_));
    const int ldc = isRx ? D_ : O_;

    int tid = threadIdx.x;
    int lane = tid & 31, wid = tid >> 5;
    int wm = wid >> 2, wn = wid & 3;                 // warp tile 64(m) x 32(n)
    size_t k0 = (size_t)z * KCHUNK;

    uint32_t smB = (uint32_t)__cvta_generic_to_shared(dynsm);

    int lrow[4], lch[4];
#pragma unroll
    for (int i = 0; i < 4; i++) {
        int idx = tid + i * 256;
        lrow[i] = idx >> 3;
        lch[i]  = idx & 7;
    }

    float c[4][4][4];
#pragma unroll
    for (int i = 0; i < 4; i++)
#pragma unroll
        for (int j = 0; j < 4; j++)
#pragma unroll
            for (int q = 0; q < 4; q++) c[i][j][q] = 0.f;

    int lt = lane >> 3, lr = lane & 7;
    int arow = ((lt & 1) << 3) + lr;
    int akch = lt >> 1;

    auto issue = [&](int k) {
        int stg = k % 3;
        size_t kb = k0 + (size_t)k * 64;
        uint32_t abase = smB + stg * 32768;
#pragma unroll
        for (int i = 0; i < 4; i++) {
            const void* src = (const void*)(A + (size_t)(mT + lrow[i]) * NTOT + kb + lch[i] * 8);
            CP16(abase + sw_off(lrow[i], lch[i]), src);
        }
        if (!diag) {
            uint32_t bbase = smB + stg * 32768 + 16384;
#pragma unroll
            for (int i = 0; i < 4; i++) {
                int row = lrow[i];
                int grow = isRx ? row : (nT + row);
                int srcrow = (isRx && row >= D_) ? 0 : grow;
                int ss = (isRx && row >= D_) ? 0 : 16;
                const void* src = (const void*)(Bm + (size_t)srcrow * NTOT + kb + lch[i] * 8);
                CP16Z(bbase + sw_off(row, lch[i]), src, ss);
            }
        }
    };

    issue(0); CPCOMMIT();
    issue(1); CPCOMMIT();

    for (int k = 0; k < NK; k++) {
        CPWAIT1();                                   // stage k landed (k+1 may fly)
        __syncthreads();
        if (k + 2 < NK) { issue(k + 2); CPCOMMIT(); }  // writes buf (k-1)%3: safe

        uint32_t sA = smB + (k % 3) * 32768;
        uint32_t sB = diag ? sA : sA + 16384;

#pragma unroll
        for (int ks = 0; ks < 4; ks++) {
            int kchb = ks * 2;
            uint32_t af[4][4];
#pragma unroll
            for (int mi = 0; mi < 4; mi++) {
                int row = wm * 64 + mi * 16 + arow;
                LDSM(af[mi][0], af[mi][1], af[mi][2], af[mi][3],
                     sA + sw_off(row, kchb + akch));
            }
            uint32_t bf[2][4];
#pragma unroll
            for (int bj = 0; bj < 2; bj++) {
                int row = wn * 32 + bj * 16 + arow;
                LDSM(bf[bj][0], bf[bj][1], bf[bj][2], bf[bj][3],
                     sB + sw_off(row, kchb + akch));
            }
#pragma unroll
            for (int mi = 0; mi < 4; mi++)
#pragma unroll
                for (int nj = 0; nj < 4; nj++) {
                    int g = nj >> 1, od = nj & 1;
                    MMA16816(c[mi][nj][0], c[mi][nj][1], c[mi][nj][2], c[mi][nj][3],
                             af[mi][0], af[mi][1], af[mi][2], af[mi][3],
                             bf[g][od], bf[g][od + 2]);
                }
        }
    }

#pragma unroll
    for (int mi = 0; mi < 4; mi++) {
        int row0 = mT + wm * 64 + mi * 16 + (lane >> 2);
#pragma unroll
        for (int nj = 0; nj < 4; nj++) {
            int col0 = nT + wn * 32 + nj * 8 + 2 * (lane & 3);
#pragma unroll
            for (int h = 0; h < 2; h++) {
                int r = row0 + h * 8;
                float v0 = c[mi][nj][h * 2 + 0], v1 = c[mi][nj][h * 2 + 1];
                if (!isRx) {
                    Cp[(size_t)r * ldc + col0] = v0;
                    Cp[(size_t)r * ldc + col0 + 1] = v1;
                } else {
                    if (col0 < D_)     Cp[(size_t)r * ldc + col0] = v0;
                    if (col0 + 1 < D_) Cp[(size_t)r * ldc + col0 + 1] = v1;
                }
            }
        }
    }
}

// ------------------------- deterministic split-K reduce ---------------------
__global__ void k_reduce() {
    int t = blockIdx.x * 256 + threadIdx.x;          // 65536 + 19200 = 84736
    if (t < O_ * O_) {
        float s = 0.f;
        for (int z = 0; z < ZB; z++) s += g_rrP[(size_t)z * (O_ * O_) + t];
        g_rr[t] = s;
    } else if (t < O_ * O_ + O_ * D_) {
        int e = t - O_ * O_;
        float s = 0.f;
        for (int z = 0; z < ZB; z++) s += g_rxP[(size_t)z * (O_ * D_) + e];
        g_rx[e] = s;
    }
}

// ------------------------- weight update ------------------------------------
__global__ void k_update(const float* __restrict__ Wt, float* __restrict__ out) {
    int t = blockIdx.x * 256 + threadIdx.x;
    if (t >= O_ * D_) return;
    int o = t / D_;
    int d = t - o * D_;
    float s = 0.f;
    for (int o2 = 0; o2 <= o; o2++)
        s += g_rr[o * O_ + o2] * Wt[o2 * D_ + d];
    out[YOUT + t] = Wt[t] + 0.01f * ((g_rx[t] - s) * (1.0f / 115200.0f));
}

// ---------------------------------------------------------------------------
extern "C" void kernel_launch(void* const* d_in, const int* in_sizes, int n_in,
                              void* d_out, int out_size) {
    const float* x  = (const float*)d_in[0];
    const float* wt = (const float*)d_in[1];
    float* out = (float*)d_out;

    static int smem_set = 0;
    if (!smem_set) {
        cudaFuncSetAttribute(k_mma2, cudaFuncAttributeMaxDynamicSharedMemorySize, 98304);
        cudaFuncSetAttribute(k_convfused, cudaFuncAttributeMaxDynamicSharedMemorySize, CF_SMEM);
        smem_set = 1;
    }

    k_init<<<256, 256>>>(wt);
    k_im2col<<<2048, 128>>>(x);
    k_convfused<<<1800, 256, CF_SMEM>>>(out);
    k_mma2<<<dim3(5, ZB), 256, 98304>>>();
    k_reduce<<<332, 256>>>();
    k_update<<<75, 256>>>(wt, out);
}

// round 13
// speedup vs baseline: 4.5671x; 1.0440x over previous
#include <cuda_runtime.h>
#include <cuda_bf16.h>
#include <cstdint>

// ---------------------------------------------------------------------------
// HebbianMap2d: y_out = relu(conv(x,w)); new_w = w + eta*(r^T Xu - tril(r^T r) W)/N
// with r = lfb(winner(relu(s))) * relu(s).
// Shapes: x[32,3,64,64], w[256,3,5,5] -> y_out[32,256,60,60], new_w[256,75]
// NOTE: toolchain targets sm_100 (no 'a') -> tcgen05 unavailable; mma.sync only.
// ---------------------------------------------------------------------------

#define B_    32
#define C_    3
#define H_    64
#define W_    64
#define HO_   60
#define WO_   60
#define HW_   3600          // 60*60
#define O_    256
#define D_    75            // 3*5*5
#define DP    80            // D padded to multiple of 16
#define NTOT  115200        // 32*3600
#define YOUT  29491200      // 32*256*3600
#define ZB    59            // ragged split-K: 30 z's get 31 iters, 29 get 30 (x64)
                            // grid 5*59 = 295 ~= one full wave @ 2 CTA/SM

// ------------------------- scratch (device globals) ------------------------
__device__ __align__(16) float g_K[O_ * O_];                 // SOM lateral kernel
__device__ __align__(16) __nv_bfloat16 g_Whi[O_ * DP];       // W split-bf16 hi
__device__ __align__(16) __nv_bfloat16 g_Wlo[O_ * DP];       // W split-bf16 lo
__device__ __align__(16) __nv_bfloat16 g_xch[(size_t)NTOT * DP]; // im2col [n][80] hi
__device__ __align__(16) __nv_bfloat16 g_xcl[(size_t)NTOT * DP]; // im2col [n][80] lo
__device__ __align__(16) __nv_bfloat16 g_xunfh[(size_t)D_ * NTOT]; // [d][n] bf16 (rx GEMM)
__device__ __align__(16) __nv_bfloat16 g_rTh[(size_t)O_ * NTOT];   // r^T bf16 [o][n]
__device__ __align__(16) float g_rrP[(size_t)ZB * O_ * O_];  // split-K partials
__device__ __align__(16) float g_rxP[(size_t)ZB * O_ * D_];
__device__ __align__(16) float g_rr[O_ * O_];
__device__ __align__(16) float g_rx[O_ * D_];

// ------------------------- K table + W split prep (merged) ------------------
__global__ void k_init(const float* __restrict__ Wt) {
    int t = blockIdx.x * 256 + threadIdx.x;          // 65536 total
    {   // K table
        int w = t >> 8, o = t & 255;
        int wi = w >> 4, wj = w & 15, i = o >> 4, j = o & 15;
        int a = wi - i + 7, b = wj - j + 7;
        float v = 0.f;
        if (a >= 0 && a < 16 && b >= 0 && b < 16) {
            int da = abs(a - 7), db = abs(b - 7);
            int m = da > db ? da : db;
            v = expf(-(float)(m * m) / 98.0f);
        }
        g_K[t] = v;
    }
    if (t < O_ * DP) {                               // W split-bf16
        int o = t / DP, d = t - o * DP;
        float v = (d < D_) ? Wt[o * D_ + d] : 0.f;
        __nv_bfloat16 hi = __float2bfloat16(v);
        g_Whi[t] = hi;
        g_Wlo[t] = __float2bfloat16(v - __bfloat162float(hi));
    }
}

// ------------------------- tiled im2col (all 3 layouts) ---------------------
__global__ void __launch_bounds__(128) k_im2col(const float* __restrict__ x) {
    __shared__ float xs[3][5][64];
    int b = blockIdx.x >> 6, i = blockIdx.x & 63;    // grid 2048, skip i>=60
    if (i >= HO_) return;
    int tid = threadIdx.x;
    int n0 = b * HW_ + i * WO_;

    for (int idx = tid; idx < 960; idx += 128) {
        int c = idx / 320, rem = idx - c * 320;
        int ki = rem >> 6, col = rem & 63;
        xs[c][ki][col] = x[((b * C_ + c) * H_ + i + ki) * W_ + col];
    }
    __syncthreads();

    for (int u = tid; u < 600; u += 128) {
        int j = u / 10, dblk = (u - j * 10) * 8;
        __nv_bfloat16 hibuf[8], lobuf[8];
#pragma unroll
        for (int dd = 0; dd < 8; dd++) {
            int d = dblk + dd;
            float v = 0.f;
            if (d < D_) {
                int c = d / 25, rr = d - c * 25;
                int ki = rr / 5, kj = rr - ki * 5;
                v = xs[c][ki][j + kj];
            }
            __nv_bfloat16 hi = __float2bfloat16(v);
            hibuf[dd] = hi;
            lobuf[dd] = __float2bfloat16(v - __bfloat162float(hi));
        }
        size_t base = (size_t)(n0 + j) * DP + dblk;
        *(uint4*)(g_xch + base) = *(uint4*)hibuf;
        *(uint4*)(g_xcl + base) = *(uint4*)lobuf;
    }

    for (int u = tid; u < 2250; u += 128) {
        int d = u / 30, j = (u - d * 30) * 2;
        int c = d / 25, rr = d - c * 25;
        int ki = rr / 5, kj = rr - ki * 5;
        __nv_bfloat162 p;
        p.x = __float2bfloat16(xs[c][ki][j + kj]);
        p.y = __float2bfloat16(xs[c][ki][j + 1 + kj]);
        *(__nv_bfloat162*)(g_xunfh + (size_t)d * NTOT + n0 + j) = p;
    }
}

// ------------------------- fused conv + winner + lfb + r --------------------
#define LDSM(r0,r1,r2,r3,addr) \
    asm volatile("ldmatrix.sync.aligned.m8n8.x4.shared.b16 {%0,%1,%2,%3}, [%4];" \
                 : "=r"(r0), "=r"(r1), "=r"(r2), "=r"(r3) : "r"(addr))
#define MMA16816(c0,c1,c2,c3,a0,a1,a2,a3,b0,b1) \
    asm volatile("mma.sync.aligned.m16n8k16.row.col.f32.bf16.bf16.f32 " \
                 "{%0,%1,%2,%3}, {%4,%5,%6,%7}, {%8,%9}, {%0,%1,%2,%3};" \
                 : "+f"(c0), "+f"(c1), "+f"(c2), "+f"(c3) \
                 : "r"(a0), "r"(a1), "r"(a2), "r"(a3), "r"(b0), "r"(b1))

// dyn smem layout: [0,24576) sW ; [24576,30720) sX ; [30720,98304) ybuf/rbuf
#define CF_SMEM 98304

__global__ void __launch_bounds__(256, 2) k_convfused(float* __restrict__ out) {
    extern __shared__ __align__(16) uint8_t dyns[];
    __shared__ float pmax[4][64];
    __shared__ float ymx[64];
    __shared__ int   nbase64[64];
    __shared__ int   cnt[64];
    __shared__ int   widx[64][8];

    __nv_bfloat16* sW = (__nv_bfloat16*)dyns;                   // 512 rows x 24
    __nv_bfloat16* sX = (__nv_bfloat16*)(dyns + 24576);         // 128 rows x 24
    float*         ybuf = (float*)(dyns + 30720);               // 256 rows x 66 fp32
    __nv_bfloat16* rbuf = (__nv_bfloat16*)(dyns + 30720);       // 256 rows x 66 bf16

    int tid = threadIdx.x, lane = tid & 31, wid = tid >> 5;
    int wm = wid >> 1, wn = wid & 1;
    int nT = blockIdx.x * 64;

    uint32_t sWb = (uint32_t)__cvta_generic_to_shared(sW);
    uint32_t sXb = (uint32_t)__cvta_generic_to_shared(sX);

    int lt = lane >> 3, lr = lane & 7;
    int arow = ((lt & 1) << 3) + lr;
    int akch = lt >> 1;

    float c[4][4][4];
#pragma unroll
    for (int i = 0; i < 4; i++)
#pragma unroll
        for (int j = 0; j < 4; j++)
#pragma unroll
            for (int q = 0; q < 4; q++) c[i][j][q] = 0.f;

    int xpiece = tid & 1, xhl = (tid >> 1) & 1, xrow = tid >> 2;

    uint4 wreg[4];
    uint4 xreg;

#pragma unroll
    for (int i = 0; i < 4; i++) {
        int idx = tid + i * 256;
        int row = idx >> 2;
        const __nv_bfloat16* src = ((idx >> 1) & 1) ? g_Wlo : g_Whi;
        wreg[i] = *(const uint4*)(src + row * DP + (idx & 1) * 8);
    }
    {
        const __nv_bfloat16* src = xhl ? g_xcl : g_xch;
        xreg = *(const uint4*)(src + (size_t)(nT + xrow) * DP + xpiece * 8);
    }
#pragma unroll
    for (int i = 0; i < 4; i++) {
        int idx = tid + i * 256;
        int row = idx >> 2;
        *(uint4*)(sW + (((idx >> 1) & 1) * 256 + row) * 24 + (idx & 1) * 8) = wreg[i];
    }
    *(uint4*)(sX + (xhl * 64 + xrow) * 24 + xpiece * 8) = xreg;
    __syncthreads();

    for (int s = 0; s < 5; s++) {
        if (s < 4) {
#pragma unroll
            for (int i = 0; i < 4; i++) {
                int idx = tid + i * 256;
                int row = idx >> 2;
                const __nv_bfloat16* src = ((idx >> 1) & 1) ? g_Wlo : g_Whi;
                wreg[i] = *(const uint4*)(src + row * DP + (s + 1) * 16 + (idx & 1) * 8);
            }
            const __nv_bfloat16* src = xhl ? g_xcl : g_xch;
            xreg = *(const uint4*)(src + (size_t)(nT + xrow) * DP + (s + 1) * 16 + xpiece * 8);
        }

        uint32_t ah[4][4], al[4][4], bh[2][4], bl[2][4];
#pragma unroll
        for (int mi = 0; mi < 4; mi++) {
            int row = wm * 64 + mi * 16 + arow;
            LDSM(ah[mi][0], ah[mi][1], ah[mi][2], ah[mi][3], sWb + row * 48 + akch * 16);
            LDSM(al[mi][0], al[mi][1], al[mi][2], al[mi][3], sWb + (256 + row) * 48 + akch * 16);
        }
#pragma unroll
        for (int bj = 0; bj < 2; bj++) {
            int row = wn * 32 + bj * 16 + arow;
            LDSM(bh[bj][0], bh[bj][1], bh[bj][2], bh[bj][3], sXb + row * 48 + akch * 16);
            LDSM(bl[bj][0], bl[bj][1], bl[bj][2], bl[bj][3], sXb + (64 + row) * 48 + akch * 16);
        }
#pragma unroll
        for (int mi = 0; mi < 4; mi++)
#pragma unroll
            for (int nj = 0; nj < 4; nj++) {
                int g = nj >> 1, od = nj & 1;
                MMA16816(c[mi][nj][0], c[mi][nj][1], c[mi][nj][2], c[mi][nj][3],
                         ah[mi][0], ah[mi][1], ah[mi][2], ah[mi][3],
                         bh[g][od], bh[g][od + 2]);
                MMA16816(c[mi][nj][0], c[mi][nj][1], c[mi][nj][2], c[mi][nj][3],
                         ah[mi][0], ah[mi][1], ah[mi][2], ah[mi][3],
                         bl[g][od], bl[g][od + 2]);
                MMA16816(c[mi][nj][0], c[mi][nj][1], c[mi][nj][2], c[mi][nj][3],
                         al[mi][0], al[mi][1], al[mi][2], al[mi][3],
                         bh[g][od], bh[g][od + 2]);
            }
        __syncthreads();
        if (s < 4) {
#pragma unroll
            for (int i = 0; i < 4; i++) {
                int idx = tid + i * 256;
                int row = idx >> 2;
                *(uint4*)(sW + (((idx >> 1) & 1) * 256 + row) * 24 + (idx & 1) * 8) = wreg[i];
            }
            *(uint4*)(sX + (xhl * 64 + xrow) * 24 + xpiece * 8) = xreg;
            __syncthreads();
        }
    }

    // ---------------- epilogue ----------------
    int lq = lane >> 2, ln = lane & 3;

    float tmax[4][2];
#pragma unroll
    for (int nj = 0; nj < 4; nj++)
#pragma unroll
        for (int q = 0; q < 2; q++) tmax[nj][q] = 0.f;
#pragma unroll
    for (int mi = 0; mi < 4; mi++)
#pragma unroll
        for (int nj = 0; nj < 4; nj++)
#pragma unroll
            for (int q = 0; q < 4; q++) {
                float y = fmaxf(c[mi][nj][q], 0.f);
                c[mi][nj][q] = y;
                tmax[nj][q & 1] = fmaxf(tmax[nj][q & 1], y);
            }

#pragma unroll
    for (int nj = 0; nj < 4; nj++)
#pragma unroll
        for (int q = 0; q < 2; q++) {
            float m = tmax[nj][q];
            m = fmaxf(m, __shfl_xor_sync(0xffffffffu, m, 4));
            m = fmaxf(m, __shfl_xor_sync(0xffffffffu, m, 8));
            m = fmaxf(m, __shfl_xor_sync(0xffffffffu, m, 16));
            if (lq == 0) pmax[wm][wn * 32 + nj * 8 + 2 * ln + q] = m;
        }
    if (tid < 64) {
        int n = nT + tid;
        int b = n / HW_;
        nbase64[tid] = b * (O_ * HW_) + (n - b * HW_);
    }
    __syncthreads();

    if (tid < 64) {
        ymx[tid] = fmaxf(fmaxf(pmax[0][tid], pmax[1][tid]),
                         fmaxf(pmax[2][tid], pmax[3][tid]));
        cnt[tid] = 0;
    }
    __syncthreads();

#pragma unroll
    for (int mi = 0; mi < 4; mi++)
#pragma unroll
        for (int h = 0; h < 2; h++) {
            int o = wm * 64 + mi * 16 + lq + 8 * h;
#pragma unroll
            for (int nj = 0; nj < 4; nj++)
#pragma unroll
                for (int q = 0; q < 2; q++) {
                    int nn = wn * 32 + nj * 8 + 2 * ln + q;
                    float ym = ymx[nn];
                    if (ym > 0.f && c[mi][nj][h * 2 + q] == ym) {
                        int pos = atomicAdd(&cnt[nn], 1);
                        if (pos < 8) widx[nn][pos] = o;
                    }
                }
        }

#pragma unroll
    for (int mi = 0; mi < 4; mi++)
#pragma unroll
        for (int h = 0; h < 2; h++) {
            int orow = wm * 64 + mi * 16 + lq + 8 * h;
#pragma unroll
            for (int nj = 0; nj < 4; nj++) {
                int nn = wn * 32 + nj * 8 + 2 * ln;
                ybuf[orow * 66 + nn]     = c[mi][nj][h * 2 + 0];
                ybuf[orow * 66 + nn + 1] = c[mi][nj][h * 2 + 1];
            }
        }
    __syncthreads();

    {
        int hw0 = nT % HW_;
        int b0  = nT / HW_;
        if (hw0 + 64 <= HW_) {                        // fast path: contiguous n
            size_t base = ((size_t)b0 * O_) * HW_ + hw0 + 2 * lane;
#pragma unroll
            for (int rr2 = 0; rr2 < 32; rr2++) {
                int o = wid * 32 + rr2;
                float2 v;
                v.x = ybuf[o * 66 + 2 * lane];
                v.y = ybuf[o * 66 + 2 * lane + 1];
                *(float2*)(out + base + (size_t)o * HW_) = v;
            }
        } else {                                      // batch-boundary block
#pragma unroll
            for (int rr2 = 0; rr2 < 32; rr2++) {
                int o = wid * 32 + rr2;
                size_t ob = (size_t)o * HW_;
                int n0 = 2 * lane;
                out[ob + nbase64[n0]]     = ybuf[o * 66 + n0];
                out[ob + nbase64[n0 + 1]] = ybuf[o * 66 + n0 + 1];
            }
        }
    }
    __syncthreads();

#pragma unroll
    for (int nj = 0; nj < 4; nj++) {
        int nn0 = wn * 32 + nj * 8 + 2 * ln;
#pragma unroll
        for (int mi = 0; mi < 4; mi++)
#pragma unroll
            for (int h = 0; h < 2; h++) {
                int o = wm * 64 + mi * 16 + lq + 8 * h;
                __nv_bfloat162 p;
                p.x = __float2bfloat16(c[mi][nj][h * 2 + 0]);
                p.y = __float2bfloat16(c[mi][nj][h * 2 + 1]);
                *(__nv_bfloat162*)(rbuf + o * 66 + nn0) = p;
            }
    }
    __syncthreads();

    {
        int n = tid & 63, chunk = tid >> 6;          // 64 o per thread
        int cN = min(cnt[n], 8);
#pragma unroll
        for (int sub = 0; sub < 4; sub++) {
            float lfb[16];
#pragma unroll
            for (int i = 0; i < 16; i++) lfb[i] = 0.f;
            for (int j = 0; j < cN; j++) {
                const float4* kp = (const float4*)(g_K + widx[n][j] * O_ + chunk * 64 + sub * 16);
#pragma unroll
                for (int q = 0; q < 4; q++) {
                    float4 kv = kp[q];
                    lfb[q * 4 + 0] += kv.x;
                    lfb[q * 4 + 1] += kv.y;
                    lfb[q * 4 + 2] += kv.z;
                    lfb[q * 4 + 3] += kv.w;
                }
            }
#pragma unroll
            for (int i = 0; i < 16; i++) {
                int o = chunk * 64 + sub * 16 + i;
                float l = fminf(fmaxf(lfb[i], -1.f), 1.f);
                __nv_bfloat16* p = rbuf + o * 66 + n;
                *p = __float2bfloat16(l * __bfloat162float(*p));
            }
        }
    }
    __syncthreads();

#pragma unroll
    for (int rr2 = 0; rr2 < 32; rr2++) {
        int o = wid * 32 + rr2;
        uint32_t v = *(uint32_t*)(rbuf + o * 66 + 2 * lane);
        *(uint32_t*)(g_rTh + (size_t)o * NTOT + nT + 2 * lane) = v;
    }
}

// ------------- merged rr+rx ragged split-K GEMM: 3-stage cp.async -----------
// Tiles: 0:(rr 0,0 diag) 1:(rr 1,0) 2:(rr 1,1 diag) 3:(rx m=0) 4:(rx m=1)
#define CP16(dst, src) \
    asm volatile("cp.async.cg.shared.global [%0], [%1], 16;" :: "r"(dst), "l"(src))
#define CP16Z(dst, src, ss) \
    asm volatile("cp.async.cg.shared.global [%0], [%1], 16, %2;" :: "r"(dst), "l"(src), "r"(ss))
#define CPCOMMIT() asm volatile("cp.async.commit_group;")
#define CPWAIT1()  asm volatile("cp.async.wait_group 1;")

__device__ __forceinline__ uint32_t sw_off(int row, int kch) {
    return (uint32_t)(row * 128 + ((kch ^ (row & 7)) << 4));
}

__global__ void __launch_bounds__(256) k_mma2() {
    extern __shared__ __align__(16) uint8_t dynsm[];

    int t = blockIdx.x;                              // 0..4
    int z = blockIdx.y;                              // 0..ZB-1
    int  mT   = (t == 1 || t == 2 || t == 4) ? 128 : 0;
    bool isRx = (t >= 3);
    bool diag = (t == 0 || t == 2);
    int  nT   = (t == 2) ? 128 : 0;

    // ragged split-K: first 30 z's take 31 iters of 64, rest take 30
    int nk = (z < 30) ? 31 : 30;
    size_t kstart = (z < 30) ? (size_t)z * 31 : (size_t)930 + (size_t)(z - 30) * 30;
    size_t k0 = kstart * 64;

    const __nv_bfloat16* A = g_rTh;
    const __nv_bfloat16* Bm = isRx ? g_xunfh : g_rTh;
    float* Cp  = isRx ? (g_rxP + (size_t)z * (O_ * D_))
                      : (g_rrP + (size_t)z * (O_ * O_));
    const int ldc = isRx ? D_ : O_;

    int tid = threadIdx.x;
    int lane = tid & 31, wid = tid >> 5;
    int wm = wid >> 2, wn = wid & 3;                 // warp tile 64(m) x 32(n)

    uint32_t smB = (uint32_t)__cvta_generic_to_shared(dynsm);

    int lrow[4], lch[4];
#pragma unroll
    for (int i = 0; i < 4; i++) {
        int idx = tid + i * 256;
        lrow[i] = idx >> 3;
        lch[i]  = idx & 7;
    }

    float c[4][4][4];
#pragma unroll
    for (int i = 0; i < 4; i++)
#pragma unroll
        for (int j = 0; j < 4; j++)
#pragma unroll
            for (int q = 0; q < 4; q++) c[i][j][q] = 0.f;

    int lt = lane >> 3, lr = lane & 7;
    int arow = ((lt & 1) << 3) + lr;
    int akch = lt >> 1;

    auto issue = [&](int k) {
        int stg = k % 3;
        size_t kb = k0 + (size_t)k * 64;
        uint32_t abase = smB + stg * 32768;
#pragma unroll
        for (int i = 0; i < 4; i++) {
            const void* src = (const void*)(A + (size_t)(mT + lrow[i]) * NTOT + kb + lch[i] * 8);
            CP16(abase + sw_off(lrow[i], lch[i]), src);
        }
        if (!diag) {
            uint32_t bbase = smB + stg * 32768 + 16384;
#pragma unroll
            for (int i = 0; i < 4; i++) {
                int row = lrow[i];
                int grow = isRx ? row : (nT + row);
                int srcrow = (isRx && row >= D_) ? 0 : grow;
                int ss = (isRx && row >= D_) ? 0 : 16;
                const void* src = (const void*)(Bm + (size_t)srcrow * NTOT + kb + lch[i] * 8);
                CP16Z(bbase + sw_off(row, lch[i]), src, ss);
            }
        }
    };

    issue(0); CPCOMMIT();
    issue(1); CPCOMMIT();

    for (int k = 0; k < nk; k++) {
        CPWAIT1();                                   // stage k landed (k+1 may fly)
        __syncthreads();
        if (k + 2 < nk) { issue(k + 2); CPCOMMIT(); }  // writes buf (k-1)%3: safe

        uint32_t sA = smB + (k % 3) * 32768;
        uint32_t sB = diag ? sA : sA + 16384;

#pragma unroll
        for (int ks = 0; ks < 4; ks++) {
            int kchb = ks * 2;
            uint32_t af[4][4];
#pragma unroll
            for (int mi = 0; mi < 4; mi++) {
                int row = wm * 64 + mi * 16 + arow;
                LDSM(af[mi][0], af[mi][1], af[mi][2], af[mi][3],
                     sA + sw_off(row, kchb + akch));
            }
            uint32_t bf[2][4];
#pragma unroll
            for (int bj = 0; bj < 2; bj++) {
                int row = wn * 32 + bj * 16 + arow;
                LDSM(bf[bj][0], bf[bj][1], bf[bj][2], bf[bj][3],
                     sB + sw_off(row, kchb + akch));
            }
#pragma unroll
            for (int mi = 0; mi < 4; mi++)
#pragma unroll
                for (int nj = 0; nj < 4; nj++) {
                    int g = nj >> 1, od = nj & 1;
                    MMA16816(c[mi][nj][0], c[mi][nj][1], c[mi][nj][2], c[mi][nj][3],
                             af[mi][0], af[mi][1], af[mi][2], af[mi][3],
                             bf[g][od], bf[g][od + 2]);
                }
        }
    }

#pragma unroll
    for (int mi = 0; mi < 4; mi++) {
        int row0 = mT + wm * 64 + mi * 16 + (lane >> 2);
#pragma unroll
        for (int nj = 0; nj < 4; nj++) {
            int col0 = nT + wn * 32 + nj * 8 + 2 * (lane & 3);
#pragma unroll
            for (int h = 0; h < 2; h++) {
                int r = row0 + h * 8;
                float v0 = c[mi][nj][h * 2 + 0], v1 = c[mi][nj][h * 2 + 1];
                if (!isRx) {
                    Cp[(size_t)r * ldc + col0] = v0;
                    Cp[(size_t)r * ldc + col0 + 1] = v1;
                } else {
                    if (col0 < D_)     Cp[(size_t)r * ldc + col0] = v0;
                    if (col0 + 1 < D_) Cp[(size_t)r * ldc + col0 + 1] = v1;
                }
            }
        }
    }
}

// ------------------------- deterministic split-K reduce ---------------------
__global__ void k_reduce() {
    int t = blockIdx.x * 256 + threadIdx.x;          // 65536 + 19200 = 84736
    if (t < O_ * O_) {
        float s = 0.f;
        for (int z = 0; z < ZB; z++) s += g_rrP[(size_t)z * (O_ * O_) + t];
        g_rr[t] = s;
    } else if (t < O_ * O_ + O_ * D_) {
        int e = t - O_ * O_;
        float s = 0.f;
        for (int z = 0; z < ZB; z++) s += g_rxP[(size_t)z * (O_ * D_) + e];
        g_rx[e] = s;
    }
}

// ------------------------- weight update ------------------------------------
__global__ void k_update(const float* __restrict__ Wt, float* __restrict__ out) {
    int t = blockIdx.x * 256 + threadIdx.x;
    if (t >= O_ * D_) return;
    int o = t / D_;
    int d = t - o * D_;
    float s = 0.f;
    for (int o2 = 0; o2 <= o; o2++)
        s += g_rr[o * O_ + o2] * Wt[o2 * D_ + d];
    out[YOUT + t] = Wt[t] + 0.01f * ((g_rx[t] - s) * (1.0f / 115200.0f));
}

// ---------------------------------------------------------------------------
extern "C" void kernel_launch(void* const* d_in, const int* in_sizes, int n_in,
                              void* d_out, int out_size) {
    const float* x  = (const float*)d_in[0];
    const float* wt = (const float*)d_in[1];
    float* out = (float*)d_out;

    static int smem_set = 0;
    if (!smem_set) {
        cudaFuncSetAttribute(k_mma2, cudaFuncAttributeMaxDynamicSharedMemorySize, 98304);
        cudaFuncSetAttribute(k_convfused, cudaFuncAttributeMaxDynamicSharedMemorySize, CF_SMEM);
        smem_set = 1;
    }

    k_init<<<256, 256>>>(wt);
    k_im2col<<<2048, 128>>>(x);
    k_convfused<<<1800, 256, CF_SMEM>>>(out);
    k_mma2<<<dim3(5, ZB), 256, 98304>>>();
    k_reduce<<<332, 256>>>();
    k_update<<<75, 256>>>(wt, out);
}